// round 1
// baseline (speedup 1.0000x reference)
#include <cuda_runtime.h>
#include <math.h>

#define Bv 4
#define Sv 2048
#define Hv 16
#define Dv 64
#define DM 1024
#define Mv (Bv*Sv)   // 8192

// Scratch (allocation-free rule: __device__ globals)
__device__ float g_q[Mv*DM];
__device__ float g_k[Mv*DM];
__device__ float g_v[Mv*DM];
__device__ float g_y[Mv*DM];
__device__ float g_cos[Sv*32];
__device__ float g_sin[Sv*32];

// ---------------------------------------------------------------------------
// RoPE tables, computed in double for exact match with numpy cos/sin
// ---------------------------------------------------------------------------
__global__ void rope_table_kernel() {
    int idx = blockIdx.x * blockDim.x + threadIdx.x;
    if (idx >= Sv * 32) return;
    int pos = idx >> 5;
    int i   = idx & 31;
    double inv = pow(10000.0, -(double)i / 32.0);
    double ang = (double)pos * inv;
    g_cos[idx] = (float)cos(ang);
    g_sin[idx] = (float)sin(ang);
}

// Apply RoPE in-place on a [Mv, DM] buffer viewed as float2 pairs.
__global__ void rope_apply_kernel(float2* __restrict__ buf) {
    int idx = blockIdx.x * blockDim.x + threadIdx.x;  // over Mv*512
    if (idx >= Mv * 512) return;
    int m = idx >> 9;        // row
    int p = idx & 511;       // pair index within row
    int i = p & 31;          // pair index within head
    int s = m & (Sv - 1);    // sequence position
    float c  = g_cos[(s << 5) + i];
    float sn = g_sin[(s << 5) + i];
    float2 v = buf[idx];
    buf[idx] = make_float2(v.x * c - v.y * sn, v.y * c + v.x * sn);
}

// ---------------------------------------------------------------------------
// SGEMM: C[M,N] = A[M,K] @ B[K,N] + bias[N]
// 128x128 block, K-tile 8, 256 threads, 8x8 per-thread microtile
// ---------------------------------------------------------------------------
__global__ __launch_bounds__(256) void sgemm_bias(
    const float* __restrict__ A, const float* __restrict__ Bw,
    const float* __restrict__ bias, float* __restrict__ C,
    int M, int N, int K)
{
    __shared__ float As[8][128];
    __shared__ float Bs[8][128];

    int tid = threadIdx.x;
    int bm = blockIdx.y << 7;
    int bn = blockIdx.x << 7;
    int tx = tid & 15, ty = tid >> 4;

    float acc[8][8];
#pragma unroll
    for (int i = 0; i < 8; i++)
#pragma unroll
        for (int j = 0; j < 8; j++) acc[i][j] = 0.f;

    int arow = tid >> 1, acol = (tid & 1) << 2;     // A: 128 rows x 8 k
    int brow = tid >> 5, bcol = (tid & 31) << 2;    // B: 8 k x 128 cols

    const float* Aptr = A + (size_t)(bm + arow) * K + acol;
    const float* Bptr = Bw + (size_t)brow * N + bn + bcol;

    for (int k0 = 0; k0 < K; k0 += 8) {
        float4 av = *(const float4*)(Aptr + k0);
        float4 bv = *(const float4*)(Bptr + (size_t)k0 * N);
        __syncthreads();
        As[acol + 0][arow] = av.x;
        As[acol + 1][arow] = av.y;
        As[acol + 2][arow] = av.z;
        As[acol + 3][arow] = av.w;
        *(float4*)&Bs[brow][bcol] = bv;
        __syncthreads();
#pragma unroll
        for (int kk = 0; kk < 8; kk++) {
            float a[8], b[8];
            *(float4*)(a)     = *(const float4*)&As[kk][ty * 8];
            *(float4*)(a + 4) = *(const float4*)&As[kk][ty * 8 + 4];
            *(float4*)(b)     = *(const float4*)&Bs[kk][tx * 8];
            *(float4*)(b + 4) = *(const float4*)&Bs[kk][tx * 8 + 4];
#pragma unroll
            for (int i = 0; i < 8; i++)
#pragma unroll
                for (int j = 0; j < 8; j++)
                    acc[i][j] += a[i] * b[j];
        }
    }

#pragma unroll
    for (int i = 0; i < 8; i++) {
        size_t row = (size_t)(bm + ty * 8 + i) * N + bn + tx * 8;
#pragma unroll
        for (int j4 = 0; j4 < 8; j4 += 4) {
            float4 o;
            o.x = acc[i][j4 + 0] + bias[bn + tx * 8 + j4 + 0];
            o.y = acc[i][j4 + 1] + bias[bn + tx * 8 + j4 + 1];
            o.z = acc[i][j4 + 2] + bias[bn + tx * 8 + j4 + 2];
            o.w = acc[i][j4 + 3] + bias[bn + tx * 8 + j4 + 3];
            *(float4*)&C[row + j4] = o;
        }
    }
}

// ---------------------------------------------------------------------------
// Flash attention (fp32, causal). Q tile 64 rows, KV tile 64 rows, D=64.
// 256 threads: ty=tid/16 owns 4 q-rows, tx=tid%16 owns 4 score-cols / 4 dims.
// Q,K stored d-major (transposed) in smem so score loop is all float4 LDS.
// ---------------------------------------------------------------------------
#define PAD 68
#define FLASH_SMEM (4 * 64 * PAD * sizeof(float))

__global__ __launch_bounds__(256) void flash_kernel(
    const float* __restrict__ q, const float* __restrict__ k,
    const float* __restrict__ v, float* __restrict__ y)
{
    extern __shared__ float sm[];
    float (*Qt)[PAD] = (float(*)[PAD])(sm);                 // [d][r]
    float (*Kt)[PAD] = (float(*)[PAD])(sm + 64 * PAD);      // [d][c]
    float (*Vs)[PAD] = (float(*)[PAD])(sm + 2 * 64 * PAD);  // [c][d]
    float (*Ps)[PAD] = (float(*)[PAD])(sm + 3 * 64 * PAD);  // [r][c]

    int tid = threadIdx.x;
    int qt = blockIdx.x, h = blockIdx.y, b = blockIdx.z;
    int tx = tid & 15, ty = tid >> 4;
    int r0 = ty * 4, c0 = tx * 4;
    const float scale = 0.125f;  // 1/sqrt(64)

    size_t base = ((size_t)b * Sv) * DM + h * Dv;
    int qg0 = qt * 64;

    // Load Q tile transposed
#pragma unroll
    for (int p = 0; p < 4; p++) {
        int e = p * 256 + tid;
        int r = e >> 4;
        int d4 = (e & 15) << 2;
        float4 val = *(const float4*)&q[base + (size_t)(qg0 + r) * DM + d4];
        Qt[d4 + 0][r] = val.x;
        Qt[d4 + 1][r] = val.y;
        Qt[d4 + 2][r] = val.z;
        Qt[d4 + 3][r] = val.w;
    }

    float acc[4][4];
#pragma unroll
    for (int i = 0; i < 4; i++)
#pragma unroll
        for (int j = 0; j < 4; j++) acc[i][j] = 0.f;
    float mrow[4], lrow[4];
#pragma unroll
    for (int i = 0; i < 4; i++) { mrow[i] = -1e30f; lrow[i] = 0.f; }

    for (int ktile = 0; ktile <= qt; ktile++) {
        __syncthreads();  // previous iteration's Ps/Vs reads complete
        // Load K (transposed) and V tiles
#pragma unroll
        for (int p = 0; p < 4; p++) {
            int e = p * 256 + tid;
            int r = e >> 4;
            int d4 = (e & 15) << 2;
            size_t g = base + (size_t)(ktile * 64 + r) * DM + d4;
            float4 kv = *(const float4*)&k[g];
            Kt[d4 + 0][r] = kv.x;
            Kt[d4 + 1][r] = kv.y;
            Kt[d4 + 2][r] = kv.z;
            Kt[d4 + 3][r] = kv.w;
            float4 vv = *(const float4*)&v[g];
            *(float4*)&Vs[r][d4] = vv;
        }
        __syncthreads();

        // Scores: S[r][c] = sum_d Q[r][d] * K[c][d]
        float s_[4][4];
#pragma unroll
        for (int i = 0; i < 4; i++)
#pragma unroll
            for (int j = 0; j < 4; j++) s_[i][j] = 0.f;
#pragma unroll 8
        for (int dd = 0; dd < 64; dd++) {
            float4 a  = *(const float4*)&Qt[dd][r0];
            float4 bb = *(const float4*)&Kt[dd][c0];
            float av[4] = {a.x, a.y, a.z, a.w};
            float bv[4] = {bb.x, bb.y, bb.z, bb.w};
#pragma unroll
            for (int i = 0; i < 4; i++)
#pragma unroll
                for (int j = 0; j < 4; j++)
                    s_[i][j] += av[i] * bv[j];
        }

        bool diag = (ktile == qt);
#pragma unroll
        for (int i = 0; i < 4; i++) {
#pragma unroll
            for (int j = 0; j < 4; j++) {
                s_[i][j] *= scale;
                if (diag && (ktile * 64 + c0 + j) > (qg0 + r0 + i))
                    s_[i][j] = -1e30f;
            }
            // row max across this thread's 4 cols, then across tx (16 lanes)
            float mx = fmaxf(fmaxf(s_[i][0], s_[i][1]), fmaxf(s_[i][2], s_[i][3]));
            mx = fmaxf(mx, __shfl_xor_sync(0xffffffffu, mx, 1, 16));
            mx = fmaxf(mx, __shfl_xor_sync(0xffffffffu, mx, 2, 16));
            mx = fmaxf(mx, __shfl_xor_sync(0xffffffffu, mx, 4, 16));
            mx = fmaxf(mx, __shfl_xor_sync(0xffffffffu, mx, 8, 16));
            float mnew = fmaxf(mrow[i], mx);
            float corr = __expf(mrow[i] - mnew);
            mrow[i] = mnew;
            float rs = 0.f;
#pragma unroll
            for (int j = 0; j < 4; j++) {
                float pj = __expf(s_[i][j] - mnew);
                s_[i][j] = pj;
                rs += pj;
            }
            rs += __shfl_xor_sync(0xffffffffu, rs, 1, 16);
            rs += __shfl_xor_sync(0xffffffffu, rs, 2, 16);
            rs += __shfl_xor_sync(0xffffffffu, rs, 4, 16);
            rs += __shfl_xor_sync(0xffffffffu, rs, 8, 16);
            lrow[i] = lrow[i] * corr + rs;
#pragma unroll
            for (int j = 0; j < 4; j++) acc[i][j] *= corr;
            *(float4*)&Ps[r0 + i][c0] = make_float4(s_[i][0], s_[i][1], s_[i][2], s_[i][3]);
        }
        __syncthreads();

        // O += P @ V  (this thread: rows r0..r0+3, dims c0..c0+3)
#pragma unroll 8
        for (int c = 0; c < 64; c++) {
            float4 vv = *(const float4*)&Vs[c][c0];
            float p0 = Ps[r0 + 0][c];
            float p1 = Ps[r0 + 1][c];
            float p2 = Ps[r0 + 2][c];
            float p3 = Ps[r0 + 3][c];
            acc[0][0] += p0 * vv.x; acc[0][1] += p0 * vv.y; acc[0][2] += p0 * vv.z; acc[0][3] += p0 * vv.w;
            acc[1][0] += p1 * vv.x; acc[1][1] += p1 * vv.y; acc[1][2] += p1 * vv.z; acc[1][3] += p1 * vv.w;
            acc[2][0] += p2 * vv.x; acc[2][1] += p2 * vv.y; acc[2][2] += p2 * vv.z; acc[2][3] += p2 * vv.w;
            acc[3][0] += p3 * vv.x; acc[3][1] += p3 * vv.y; acc[3][2] += p3 * vv.z; acc[3][3] += p3 * vv.w;
        }
    }

    // Normalize and write y
#pragma unroll
    for (int i = 0; i < 4; i++) {
        float inv = 1.f / lrow[i];
        float4 o = make_float4(acc[i][0] * inv, acc[i][1] * inv,
                               acc[i][2] * inv, acc[i][3] * inv);
        *(float4*)&y[base + (size_t)(qg0 + r0 + i) * DM + c0] = o;
    }
}

// ---------------------------------------------------------------------------
// kernel_launch
// ---------------------------------------------------------------------------
extern "C" void kernel_launch(void* const* d_in, const int* in_sizes, int n_in,
                              void* d_out, int out_size)
{
    const float* x  = (const float*)d_in[0];
    const float* Wq = (const float*)d_in[1];
    const float* bq = (const float*)d_in[2];
    const float* Wk = (const float*)d_in[3];
    const float* bk = (const float*)d_in[4];
    const float* Wv = (const float*)d_in[5];
    const float* bv = (const float*)d_in[6];
    const float* Wo = (const float*)d_in[7];
    const float* bo = (const float*)d_in[8];
    float* out = (float*)d_out;

    float *qp, *kp, *vp, *yp;
    cudaGetSymbolAddress((void**)&qp, g_q);
    cudaGetSymbolAddress((void**)&kp, g_k);
    cudaGetSymbolAddress((void**)&vp, g_v);
    cudaGetSymbolAddress((void**)&yp, g_y);

    cudaFuncSetAttribute(flash_kernel,
                         cudaFuncAttributeMaxDynamicSharedMemorySize,
                         (int)FLASH_SMEM);

    // RoPE tables
    rope_table_kernel<<<(Sv * 32 + 255) / 256, 256>>>();

    // QKV projections
    dim3 gemm_grid(DM / 128, Mv / 128);
    sgemm_bias<<<gemm_grid, 256>>>(x, Wq, bq, qp, Mv, DM, DM);
    sgemm_bias<<<gemm_grid, 256>>>(x, Wk, bk, kp, Mv, DM, DM);
    sgemm_bias<<<gemm_grid, 256>>>(x, Wv, bv, vp, Mv, DM, DM);

    // RoPE on Q and K
    int nrope = Mv * 512;
    rope_apply_kernel<<<(nrope + 255) / 256, 256>>>((float2*)qp);
    rope_apply_kernel<<<(nrope + 255) / 256, 256>>>((float2*)kp);

    // Causal attention
    dim3 att_grid(Sv / 64, Hv, Bv);
    flash_kernel<<<att_grid, 256, FLASH_SMEM>>>(qp, kp, vp, yp);

    // Output projection
    sgemm_bias<<<gemm_grid, 256>>>(yp, Wo, bo, out, Mv, DM, DM);
}

// round 3
// speedup vs baseline: 2.1376x; 2.1376x over previous
#include <cuda_runtime.h>
#include <cuda_bf16.h>
#include <stdint.h>
#include <cstdint>
#include <math.h>

#define Bv 4
#define Sv 2048
#define Hv 16
#define Dv 64
#define DM 1024
#define Mv (Bv*Sv)   // 8192

// ---------------------------------------------------------------------------
// Scratch (allocation-free rule: __device__ globals)
// ---------------------------------------------------------------------------
__device__ float g_q[Mv*DM];
__device__ float g_k[Mv*DM];
__device__ float g_v[Mv*DM];
__device__ float g_y[Mv*DM];
__device__ float g_cos[Sv*32];
__device__ float g_sin[Sv*32];

__device__ __nv_bfloat16 g_xhi[Mv*DM];
__device__ __nv_bfloat16 g_xlo[Mv*DM];
__device__ __nv_bfloat16 g_yhi[Mv*DM];
__device__ __nv_bfloat16 g_ylo[Mv*DM];
__device__ __nv_bfloat16 g_whi[4*DM*DM];
__device__ __nv_bfloat16 g_wlo[4*DM*DM];

// ---------------------------------------------------------------------------
// fp32 -> (bf16 hi, bf16 lo) split
// ---------------------------------------------------------------------------
__global__ void split_kernel(const float* __restrict__ s,
                             __nv_bfloat16* __restrict__ hi,
                             __nv_bfloat16* __restrict__ lo, int n)
{
    int i = blockIdx.x * blockDim.x + threadIdx.x;
    if (i >= n) return;
    float x = s[i];
    __nv_bfloat16 h = __float2bfloat16(x);
    hi[i] = h;
    lo[i] = __float2bfloat16(x - __bfloat162float(h));
}

// ---------------------------------------------------------------------------
// RoPE tables (double precision for exact match)
// ---------------------------------------------------------------------------
__global__ void rope_table_kernel() {
    int idx = blockIdx.x * blockDim.x + threadIdx.x;
    if (idx >= Sv * 32) return;
    int pos = idx >> 5;
    int i   = idx & 31;
    double inv = pow(10000.0, -(double)i / 32.0);
    double ang = (double)pos * inv;
    g_cos[idx] = (float)cos(ang);
    g_sin[idx] = (float)sin(ang);
}

__global__ void rope_apply_kernel(float2* __restrict__ buf) {
    int idx = blockIdx.x * blockDim.x + threadIdx.x;  // over Mv*512
    if (idx >= Mv * 512) return;
    int m = idx >> 9;
    int p = idx & 511;
    int i = p & 31;
    int s = m & (Sv - 1);
    float c  = g_cos[(s << 5) + i];
    float sn = g_sin[(s << 5) + i];
    float2 v = buf[idx];
    buf[idx] = make_float2(v.x * c - v.y * sn, v.y * c + v.x * sn);
}

// ---------------------------------------------------------------------------
// Tensor-core GEMM with bf16x3 split: C = A @ B + bias  (fp32-accurate)
// BM=128 BN=64 BK=32, 128 threads (4 warps, 2x2), warp tile 64x32.
// ---------------------------------------------------------------------------
__device__ __forceinline__ void ldmx4(unsigned& r0, unsigned& r1,
                                      unsigned& r2, unsigned& r3, unsigned a) {
    asm volatile("ldmatrix.sync.aligned.m8n8.x4.shared.b16 {%0,%1,%2,%3}, [%4];"
        : "=r"(r0), "=r"(r1), "=r"(r2), "=r"(r3) : "r"(a));
}
__device__ __forceinline__ void ldmx4t(unsigned& r0, unsigned& r1,
                                       unsigned& r2, unsigned& r3, unsigned a) {
    asm volatile("ldmatrix.sync.aligned.m8n8.x4.trans.shared.b16 {%0,%1,%2,%3}, [%4];"
        : "=r"(r0), "=r"(r1), "=r"(r2), "=r"(r3) : "r"(a));
}
__device__ __forceinline__ void mma16816(float* c, const unsigned* a, const unsigned* b) {
    asm volatile(
        "mma.sync.aligned.m16n8k16.row.col.f32.bf16.bf16.f32 "
        "{%0,%1,%2,%3}, {%4,%5,%6,%7}, {%8,%9}, {%0,%1,%2,%3};"
        : "+f"(c[0]), "+f"(c[1]), "+f"(c[2]), "+f"(c[3])
        : "r"(a[0]), "r"(a[1]), "r"(a[2]), "r"(a[3]), "r"(b[0]), "r"(b[1]));
}

#define APAD 40   // A smem row stride (bf16): conflict-free ldmatrix
#define BPAD 72   // B smem row stride (bf16)

__global__ __launch_bounds__(128) void gemm_bf16x3(
    const __nv_bfloat16* __restrict__ Ahi, const __nv_bfloat16* __restrict__ Alo,
    const __nv_bfloat16* __restrict__ Bhi, const __nv_bfloat16* __restrict__ Blo,
    const float* __restrict__ bias, float* __restrict__ C,
    int M, int N, int K)
{
    __shared__ __nv_bfloat16 As[2][128][APAD];
    __shared__ __nv_bfloat16 Bs[2][32][BPAD];

    int tid  = threadIdx.x;
    int lane = tid & 31;
    int warp = tid >> 5;
    int wm = warp >> 1, wn = warp & 1;
    int bm = blockIdx.y << 7;
    int bn = blockIdx.x << 6;

    float acc[4][4][4];
#pragma unroll
    for (int i = 0; i < 4; i++)
#pragma unroll
        for (int j = 0; j < 4; j++)
#pragma unroll
            for (int e = 0; e < 4; e++) acc[i][j][e] = 0.f;

    // B global: 32k x 64n per buffer, uint4 = 8 n; 256 uint4 / 128 thr
    int u0k = tid >> 3, u0n = (tid & 7) << 3;
    int u1k = (tid + 128) >> 3, u1n = ((tid + 128) & 7) << 3;

    for (int k0 = 0; k0 < K; k0 += 32) {
        // ---- global loads into registers ----
        uint4 ah[4], al[4], bh[2], bl[2];
        const __nv_bfloat16* Ahp = Ahi + (size_t)(bm + tid) * K + k0;
        const __nv_bfloat16* Alp = Alo + (size_t)(bm + tid) * K + k0;
#pragma unroll
        for (int i = 0; i < 4; i++) {
            ah[i] = *(const uint4*)(Ahp + i * 8);
            al[i] = *(const uint4*)(Alp + i * 8);
        }
        bh[0] = *(const uint4*)(Bhi + (size_t)(k0 + u0k) * N + bn + u0n);
        bh[1] = *(const uint4*)(Bhi + (size_t)(k0 + u1k) * N + bn + u1n);
        bl[0] = *(const uint4*)(Blo + (size_t)(k0 + u0k) * N + bn + u0n);
        bl[1] = *(const uint4*)(Blo + (size_t)(k0 + u1k) * N + bn + u1n);

        __syncthreads();
#pragma unroll
        for (int i = 0; i < 4; i++) {
            *(uint4*)&As[0][tid][i * 8] = ah[i];
            *(uint4*)&As[1][tid][i * 8] = al[i];
        }
        *(uint4*)&Bs[0][u0k][u0n] = bh[0];
        *(uint4*)&Bs[0][u1k][u1n] = bh[1];
        *(uint4*)&Bs[1][u0k][u0n] = bl[0];
        *(uint4*)&Bs[1][u1k][u1n] = bl[1];
        __syncthreads();

#pragma unroll
        for (int ks = 0; ks < 2; ks++) {
            int k16 = ks << 4;
            // A fragments: [buf][mtile][4 regs]
            unsigned Af[2][4][4];
            int ar = (lane & 15);
            int ac = k16 + ((lane >> 4) << 3);
#pragma unroll
            for (int mt = 0; mt < 4; mt++) {
                int m0 = wm * 64 + mt * 16;
                unsigned a0 = (unsigned)__cvta_generic_to_shared(&As[0][m0 + ar][ac]);
                ldmx4(Af[0][mt][0], Af[0][mt][1], Af[0][mt][2], Af[0][mt][3], a0);
                unsigned a1 = (unsigned)__cvta_generic_to_shared(&As[1][m0 + ar][ac]);
                ldmx4(Af[1][mt][0], Af[1][mt][1], Af[1][mt][2], Af[1][mt][3], a1);
            }
            // B fragments: [buf][ntile][2 regs] via trans ldmatrix (2 ntiles/instr)
            unsigned Bf[2][4][2];
            int bkr = k16 + (lane & 7) + (lane & 8);
#pragma unroll
            for (int p = 0; p < 2; p++) {
                int n0 = wn * 32 + p * 16 + (((lane >> 4) & 1) << 3);
                unsigned r0, r1, r2, r3;
                unsigned ad = (unsigned)__cvta_generic_to_shared(&Bs[0][bkr][n0]);
                ldmx4t(r0, r1, r2, r3, ad);
                Bf[0][p * 2][0] = r0; Bf[0][p * 2][1] = r1;
                Bf[0][p * 2 + 1][0] = r2; Bf[0][p * 2 + 1][1] = r3;
                ad = (unsigned)__cvta_generic_to_shared(&Bs[1][bkr][n0]);
                ldmx4t(r0, r1, r2, r3, ad);
                Bf[1][p * 2][0] = r0; Bf[1][p * 2][1] = r1;
                Bf[1][p * 2 + 1][0] = r2; Bf[1][p * 2 + 1][1] = r3;
            }
            // 3-term split MMA
#pragma unroll
            for (int mt = 0; mt < 4; mt++)
#pragma unroll
                for (int nt = 0; nt < 4; nt++) {
                    mma16816(acc[mt][nt], Af[0][mt], Bf[0][nt]);  // hi*hi
                    mma16816(acc[mt][nt], Af[0][mt], Bf[1][nt]);  // hi*lo
                    mma16816(acc[mt][nt], Af[1][mt], Bf[0][nt]);  // lo*hi
                }
        }
    }

    // ---- epilogue ----
    int gid = lane >> 2, tq = lane & 3;
#pragma unroll
    for (int mt = 0; mt < 4; mt++) {
        int row = bm + wm * 64 + mt * 16 + gid;
#pragma unroll
        for (int nt = 0; nt < 4; nt++) {
            int col = bn + wn * 32 + nt * 8 + tq * 2;
            float b0 = bias[col], b1 = bias[col + 1];
            *(float2*)&C[(size_t)row * N + col] =
                make_float2(acc[mt][nt][0] + b0, acc[mt][nt][1] + b1);
            *(float2*)&C[(size_t)(row + 8) * N + col] =
                make_float2(acc[mt][nt][2] + b0, acc[mt][nt][3] + b1);
        }
    }
}

// ---------------------------------------------------------------------------
// Flash attention (fp32, causal) — unchanged from round 1
// ---------------------------------------------------------------------------
#define FPAD 68
#define FLASH_SMEM (4 * 64 * FPAD * sizeof(float))

__global__ __launch_bounds__(256) void flash_kernel(
    const float* __restrict__ q, const float* __restrict__ k,
    const float* __restrict__ v, float* __restrict__ y)
{
    extern __shared__ float smbuf[];
    float (*Qt)[FPAD] = (float(*)[FPAD])(smbuf);
    float (*Kt)[FPAD] = (float(*)[FPAD])(smbuf + 64 * FPAD);
    float (*Vs)[FPAD] = (float(*)[FPAD])(smbuf + 2 * 64 * FPAD);
    float (*Ps)[FPAD] = (float(*)[FPAD])(smbuf + 3 * 64 * FPAD);

    int tid = threadIdx.x;
    int qt = blockIdx.x, h = blockIdx.y, b = blockIdx.z;
    int tx = tid & 15, ty = tid >> 4;
    int r0 = ty * 4, c0 = tx * 4;
    const float scale = 0.125f;

    size_t base = ((size_t)b * Sv) * DM + h * Dv;
    int qg0 = qt * 64;

#pragma unroll
    for (int p = 0; p < 4; p++) {
        int e = p * 256 + tid;
        int r = e >> 4;
        int d4 = (e & 15) << 2;
        float4 val = *(const float4*)&q[base + (size_t)(qg0 + r) * DM + d4];
        Qt[d4 + 0][r] = val.x;
        Qt[d4 + 1][r] = val.y;
        Qt[d4 + 2][r] = val.z;
        Qt[d4 + 3][r] = val.w;
    }

    float acc[4][4];
#pragma unroll
    for (int i = 0; i < 4; i++)
#pragma unroll
        for (int j = 0; j < 4; j++) acc[i][j] = 0.f;
    float mrow[4], lrow[4];
#pragma unroll
    for (int i = 0; i < 4; i++) { mrow[i] = -1e30f; lrow[i] = 0.f; }

    for (int ktile = 0; ktile <= qt; ktile++) {
        __syncthreads();
#pragma unroll
        for (int p = 0; p < 4; p++) {
            int e = p * 256 + tid;
            int r = e >> 4;
            int d4 = (e & 15) << 2;
            size_t g = base + (size_t)(ktile * 64 + r) * DM + d4;
            float4 kv = *(const float4*)&k[g];
            Kt[d4 + 0][r] = kv.x;
            Kt[d4 + 1][r] = kv.y;
            Kt[d4 + 2][r] = kv.z;
            Kt[d4 + 3][r] = kv.w;
            float4 vv = *(const float4*)&v[g];
            *(float4*)&Vs[r][d4] = vv;
        }
        __syncthreads();

        float s_[4][4];
#pragma unroll
        for (int i = 0; i < 4; i++)
#pragma unroll
            for (int j = 0; j < 4; j++) s_[i][j] = 0.f;
#pragma unroll 8
        for (int dd = 0; dd < 64; dd++) {
            float4 a  = *(const float4*)&Qt[dd][r0];
            float4 bb = *(const float4*)&Kt[dd][c0];
            float av[4] = {a.x, a.y, a.z, a.w};
            float bv2[4] = {bb.x, bb.y, bb.z, bb.w};
#pragma unroll
            for (int i = 0; i < 4; i++)
#pragma unroll
                for (int j = 0; j < 4; j++)
                    s_[i][j] += av[i] * bv2[j];
        }

        bool diag = (ktile == qt);
#pragma unroll
        for (int i = 0; i < 4; i++) {
#pragma unroll
            for (int j = 0; j < 4; j++) {
                s_[i][j] *= scale;
                if (diag && (ktile * 64 + c0 + j) > (qg0 + r0 + i))
                    s_[i][j] = -1e30f;
            }
            float mx = fmaxf(fmaxf(s_[i][0], s_[i][1]), fmaxf(s_[i][2], s_[i][3]));
            mx = fmaxf(mx, __shfl_xor_sync(0xffffffffu, mx, 1, 16));
            mx = fmaxf(mx, __shfl_xor_sync(0xffffffffu, mx, 2, 16));
            mx = fmaxf(mx, __shfl_xor_sync(0xffffffffu, mx, 4, 16));
            mx = fmaxf(mx, __shfl_xor_sync(0xffffffffu, mx, 8, 16));
            float mnew = fmaxf(mrow[i], mx);
            float corr = __expf(mrow[i] - mnew);
            mrow[i] = mnew;
            float rs = 0.f;
#pragma unroll
            for (int j = 0; j < 4; j++) {
                float pj = __expf(s_[i][j] - mnew);
                s_[i][j] = pj;
                rs += pj;
            }
            rs += __shfl_xor_sync(0xffffffffu, rs, 1, 16);
            rs += __shfl_xor_sync(0xffffffffu, rs, 2, 16);
            rs += __shfl_xor_sync(0xffffffffu, rs, 4, 16);
            rs += __shfl_xor_sync(0xffffffffu, rs, 8, 16);
            lrow[i] = lrow[i] * corr + rs;
#pragma unroll
            for (int j = 0; j < 4; j++) acc[i][j] *= corr;
            *(float4*)&Ps[r0 + i][c0] = make_float4(s_[i][0], s_[i][1], s_[i][2], s_[i][3]);
        }
        __syncthreads();

#pragma unroll 8
        for (int c = 0; c < 64; c++) {
            float4 vv = *(const float4*)&Vs[c][c0];
            float p0 = Ps[r0 + 0][c];
            float p1 = Ps[r0 + 1][c];
            float p2 = Ps[r0 + 2][c];
            float p3 = Ps[r0 + 3][c];
            acc[0][0] += p0 * vv.x; acc[0][1] += p0 * vv.y; acc[0][2] += p0 * vv.z; acc[0][3] += p0 * vv.w;
            acc[1][0] += p1 * vv.x; acc[1][1] += p1 * vv.y; acc[1][2] += p1 * vv.z; acc[1][3] += p1 * vv.w;
            acc[2][0] += p2 * vv.x; acc[2][1] += p2 * vv.y; acc[2][2] += p2 * vv.z; acc[2][3] += p2 * vv.w;
            acc[3][0] += p3 * vv.x; acc[3][1] += p3 * vv.y; acc[3][2] += p3 * vv.z; acc[3][3] += p3 * vv.w;
        }
    }

#pragma unroll
    for (int i = 0; i < 4; i++) {
        float inv = 1.f / lrow[i];
        float4 o = make_float4(acc[i][0] * inv, acc[i][1] * inv,
                               acc[i][2] * inv, acc[i][3] * inv);
        *(float4*)&y[base + (size_t)(qg0 + r0 + i) * DM + c0] = o;
    }
}

// ---------------------------------------------------------------------------
// kernel_launch
// ---------------------------------------------------------------------------
extern "C" void kernel_launch(void* const* d_in, const int* in_sizes, int n_in,
                              void* d_out, int out_size)
{
    const float* x  = (const float*)d_in[0];
    const float* Wq = (const float*)d_in[1];
    const float* bq = (const float*)d_in[2];
    const float* Wk = (const float*)d_in[3];
    const float* bk = (const float*)d_in[4];
    const float* Wv = (const float*)d_in[5];
    const float* bv = (const float*)d_in[6];
    const float* Wo = (const float*)d_in[7];
    const float* bo = (const float*)d_in[8];
    float* out = (float*)d_out;

    float *qp, *kp, *vp, *yp;
    cudaGetSymbolAddress((void**)&qp, g_q);
    cudaGetSymbolAddress((void**)&kp, g_k);
    cudaGetSymbolAddress((void**)&vp, g_v);
    cudaGetSymbolAddress((void**)&yp, g_y);
    __nv_bfloat16 *xhi, *xlo, *yhi, *ylo, *whi, *wlo;
    cudaGetSymbolAddress((void**)&xhi, g_xhi);
    cudaGetSymbolAddress((void**)&xlo, g_xlo);
    cudaGetSymbolAddress((void**)&yhi, g_yhi);
    cudaGetSymbolAddress((void**)&ylo, g_ylo);
    cudaGetSymbolAddress((void**)&whi, g_whi);
    cudaGetSymbolAddress((void**)&wlo, g_wlo);

    cudaFuncSetAttribute(flash_kernel,
                         cudaFuncAttributeMaxDynamicSharedMemorySize,
                         (int)FLASH_SMEM);

    const int NX = Mv * DM;       // 8.4M
    const int NW = DM * DM;       // 1M

    rope_table_kernel<<<(Sv * 32 + 255) / 256, 256>>>();

    // splits
    split_kernel<<<(NX + 255) / 256, 256>>>(x, xhi, xlo, NX);
    split_kernel<<<(NW + 255) / 256, 256>>>(Wq, whi + 0 * NW, wlo + 0 * NW, NW);
    split_kernel<<<(NW + 255) / 256, 256>>>(Wk, whi + 1 * NW, wlo + 1 * NW, NW);
    split_kernel<<<(NW + 255) / 256, 256>>>(Wv, whi + 2 * NW, wlo + 2 * NW, NW);
    split_kernel<<<(NW + 255) / 256, 256>>>(Wo, whi + 3 * NW, wlo + 3 * NW, NW);

    // QKV projections (tensor cores)
    dim3 gg(DM / 64, Mv / 128);
    gemm_bf16x3<<<gg, 128>>>(xhi, xlo, whi + 0 * NW, wlo + 0 * NW, bq, qp, Mv, DM, DM);
    gemm_bf16x3<<<gg, 128>>>(xhi, xlo, whi + 1 * NW, wlo + 1 * NW, bk, kp, Mv, DM, DM);
    gemm_bf16x3<<<gg, 128>>>(xhi, xlo, whi + 2 * NW, wlo + 2 * NW, bv, vp, Mv, DM, DM);

    // RoPE
    int nrope = Mv * 512;
    rope_apply_kernel<<<(nrope + 255) / 256, 256>>>((float2*)qp);
    rope_apply_kernel<<<(nrope + 255) / 256, 256>>>((float2*)kp);

    // attention
    dim3 att_grid(Sv / 64, Hv, Bv);
    flash_kernel<<<att_grid, 256, FLASH_SMEM>>>(qp, kp, vp, yp);

    // output projection
    split_kernel<<<(NX + 255) / 256, 256>>>(yp, yhi, ylo, NX);
    gemm_bf16x3<<<gg, 128>>>(yhi, ylo, whi + 3 * NW, wlo + 3 * NW, bo, out, Mv, DM, DM);
}

// round 4
// speedup vs baseline: 3.2970x; 1.5424x over previous
#include <cuda_runtime.h>
#include <cuda_bf16.h>
#include <stdint.h>
#include <cstdint>
#include <math.h>

#define Bv 4
#define Sv 2048
#define Hv 16
#define Dv 64
#define DM 1024
#define Mv (Bv*Sv)   // 8192

// ---------------------------------------------------------------------------
// Scratch (allocation-free rule: __device__ globals)
// ---------------------------------------------------------------------------
__device__ float g_q[Mv*DM];
__device__ float g_k[Mv*DM];
__device__ float g_v[Mv*DM];
__device__ float g_cos[Sv*32];
__device__ float g_sin[Sv*32];

__device__ __nv_bfloat16 g_xhi[Mv*DM];
__device__ __nv_bfloat16 g_xlo[Mv*DM];
__device__ __nv_bfloat16 g_yhi[Mv*DM];
__device__ __nv_bfloat16 g_ylo[Mv*DM];
__device__ __nv_bfloat16 g_whi[4*DM*DM];
__device__ __nv_bfloat16 g_wlo[4*DM*DM];
__device__ __nv_bfloat16 g_qhi[Mv*DM];
__device__ __nv_bfloat16 g_qlo[Mv*DM];
__device__ __nv_bfloat16 g_khi[Mv*DM];
__device__ __nv_bfloat16 g_klo[Mv*DM];
__device__ __nv_bfloat16 g_vhi[Mv*DM];
__device__ __nv_bfloat16 g_vlo[Mv*DM];

// ---------------------------------------------------------------------------
// helpers
// ---------------------------------------------------------------------------
__global__ void split_kernel(const float* __restrict__ s,
                             __nv_bfloat16* __restrict__ hi,
                             __nv_bfloat16* __restrict__ lo, int n)
{
    int i = blockIdx.x * blockDim.x + threadIdx.x;
    if (i >= n) return;
    float x = s[i];
    __nv_bfloat16 h = __float2bfloat16(x);
    hi[i] = h;
    lo[i] = __float2bfloat16(x - __bfloat162float(h));
}

__global__ void rope_table_kernel() {
    int idx = blockIdx.x * blockDim.x + threadIdx.x;
    if (idx >= Sv * 32) return;
    int pos = idx >> 5;
    int i   = idx & 31;
    double inv = pow(10000.0, -(double)i / 32.0);
    double ang = (double)pos * inv;
    g_cos[idx] = (float)cos(ang);
    g_sin[idx] = (float)sin(ang);
}

// fused rope + bf16 hi/lo split (fp32 [M,DM] -> two bf16 [M,DM])
__global__ void rope_split_kernel(const float2* __restrict__ src,
                                  __nv_bfloat162* __restrict__ hi,
                                  __nv_bfloat162* __restrict__ lo)
{
    int idx = blockIdx.x * blockDim.x + threadIdx.x;  // over Mv*512 pairs
    if (idx >= Mv * 512) return;
    int p = idx & 511;
    int i = p & 31;
    int s = (idx >> 9) & (Sv - 1);
    float c  = g_cos[(s << 5) + i];
    float sn = g_sin[(s << 5) + i];
    float2 v = src[idx];
    float2 r = make_float2(v.x * c - v.y * sn, v.y * c + v.x * sn);
    __nv_bfloat162 h2 = __float22bfloat162_rn(r);
    float2 back = __bfloat1622float2(h2);
    hi[idx] = h2;
    lo[idx] = __float22bfloat162_rn(make_float2(r.x - back.x, r.y - back.y));
}

// ---------------------------------------------------------------------------
// MMA primitives
// ---------------------------------------------------------------------------
__device__ __forceinline__ void ldmx4(unsigned& r0, unsigned& r1,
                                      unsigned& r2, unsigned& r3, unsigned a) {
    asm volatile("ldmatrix.sync.aligned.m8n8.x4.shared.b16 {%0,%1,%2,%3}, [%4];"
        : "=r"(r0), "=r"(r1), "=r"(r2), "=r"(r3) : "r"(a));
}
__device__ __forceinline__ void ldmx4t(unsigned& r0, unsigned& r1,
                                       unsigned& r2, unsigned& r3, unsigned a) {
    asm volatile("ldmatrix.sync.aligned.m8n8.x4.trans.shared.b16 {%0,%1,%2,%3}, [%4];"
        : "=r"(r0), "=r"(r1), "=r"(r2), "=r"(r3) : "r"(a));
}
__device__ __forceinline__ void mma16816(float* c, const unsigned* a, const unsigned* b) {
    asm volatile(
        "mma.sync.aligned.m16n8k16.row.col.f32.bf16.bf16.f32 "
        "{%0,%1,%2,%3}, {%4,%5,%6,%7}, {%8,%9}, {%0,%1,%2,%3};"
        : "+f"(c[0]), "+f"(c[1]), "+f"(c[2]), "+f"(c[3])
        : "r"(a[0]), "r"(a[1]), "r"(a[2]), "r"(a[3]), "r"(b[0]), "r"(b[1]));
}

// ---------------------------------------------------------------------------
// Tensor-core GEMM with bf16x3 split (unchanged from R3)
// ---------------------------------------------------------------------------
#define APAD 40
#define BPAD 72

__global__ __launch_bounds__(128) void gemm_bf16x3(
    const __nv_bfloat16* __restrict__ Ahi, const __nv_bfloat16* __restrict__ Alo,
    const __nv_bfloat16* __restrict__ Bhi, const __nv_bfloat16* __restrict__ Blo,
    const float* __restrict__ bias, float* __restrict__ C,
    int M, int N, int K)
{
    __shared__ __nv_bfloat16 As[2][128][APAD];
    __shared__ __nv_bfloat16 Bs[2][32][BPAD];

    int tid  = threadIdx.x;
    int lane = tid & 31;
    int warp = tid >> 5;
    int wm = warp >> 1, wn = warp & 1;
    int bm = blockIdx.y << 7;
    int bn = blockIdx.x << 6;

    float acc[4][4][4];
#pragma unroll
    for (int i = 0; i < 4; i++)
#pragma unroll
        for (int j = 0; j < 4; j++)
#pragma unroll
            for (int e = 0; e < 4; e++) acc[i][j][e] = 0.f;

    int u0k = tid >> 3, u0n = (tid & 7) << 3;
    int u1k = (tid + 128) >> 3, u1n = ((tid + 128) & 7) << 3;

    for (int k0 = 0; k0 < K; k0 += 32) {
        uint4 ah[4], al[4], bh[2], bl[2];
        const __nv_bfloat16* Ahp = Ahi + (size_t)(bm + tid) * K + k0;
        const __nv_bfloat16* Alp = Alo + (size_t)(bm + tid) * K + k0;
#pragma unroll
        for (int i = 0; i < 4; i++) {
            ah[i] = *(const uint4*)(Ahp + i * 8);
            al[i] = *(const uint4*)(Alp + i * 8);
        }
        bh[0] = *(const uint4*)(Bhi + (size_t)(k0 + u0k) * N + bn + u0n);
        bh[1] = *(const uint4*)(Bhi + (size_t)(k0 + u1k) * N + bn + u1n);
        bl[0] = *(const uint4*)(Blo + (size_t)(k0 + u0k) * N + bn + u0n);
        bl[1] = *(const uint4*)(Blo + (size_t)(k0 + u1k) * N + bn + u1n);

        __syncthreads();
#pragma unroll
        for (int i = 0; i < 4; i++) {
            *(uint4*)&As[0][tid][i * 8] = ah[i];
            *(uint4*)&As[1][tid][i * 8] = al[i];
        }
        *(uint4*)&Bs[0][u0k][u0n] = bh[0];
        *(uint4*)&Bs[0][u1k][u1n] = bh[1];
        *(uint4*)&Bs[1][u0k][u0n] = bl[0];
        *(uint4*)&Bs[1][u1k][u1n] = bl[1];
        __syncthreads();

#pragma unroll
        for (int ks = 0; ks < 2; ks++) {
            int k16 = ks << 4;
            unsigned Af[2][4][4];
            int ar = (lane & 15);
            int ac = k16 + ((lane >> 4) << 3);
#pragma unroll
            for (int mt = 0; mt < 4; mt++) {
                int m0 = wm * 64 + mt * 16;
                unsigned a0 = (unsigned)__cvta_generic_to_shared(&As[0][m0 + ar][ac]);
                ldmx4(Af[0][mt][0], Af[0][mt][1], Af[0][mt][2], Af[0][mt][3], a0);
                unsigned a1 = (unsigned)__cvta_generic_to_shared(&As[1][m0 + ar][ac]);
                ldmx4(Af[1][mt][0], Af[1][mt][1], Af[1][mt][2], Af[1][mt][3], a1);
            }
            unsigned Bf[2][4][2];
            int bkr = k16 + (lane & 7) + (lane & 8);
#pragma unroll
            for (int p = 0; p < 2; p++) {
                int n0 = wn * 32 + p * 16 + (((lane >> 4) & 1) << 3);
                unsigned r0, r1, r2, r3;
                unsigned ad = (unsigned)__cvta_generic_to_shared(&Bs[0][bkr][n0]);
                ldmx4t(r0, r1, r2, r3, ad);
                Bf[0][p * 2][0] = r0; Bf[0][p * 2][1] = r1;
                Bf[0][p * 2 + 1][0] = r2; Bf[0][p * 2 + 1][1] = r3;
                ad = (unsigned)__cvta_generic_to_shared(&Bs[1][bkr][n0]);
                ldmx4t(r0, r1, r2, r3, ad);
                Bf[1][p * 2][0] = r0; Bf[1][p * 2][1] = r1;
                Bf[1][p * 2 + 1][0] = r2; Bf[1][p * 2 + 1][1] = r3;
            }
#pragma unroll
            for (int mt = 0; mt < 4; mt++)
#pragma unroll
                for (int nt = 0; nt < 4; nt++) {
                    mma16816(acc[mt][nt], Af[0][mt], Bf[0][nt]);
                    mma16816(acc[mt][nt], Af[0][mt], Bf[1][nt]);
                    mma16816(acc[mt][nt], Af[1][mt], Bf[0][nt]);
                }
        }
    }

    int gid = lane >> 2, tq = lane & 3;
#pragma unroll
    for (int mt = 0; mt < 4; mt++) {
        int row = bm + wm * 64 + mt * 16 + gid;
#pragma unroll
        for (int nt = 0; nt < 4; nt++) {
            int col = bn + wn * 32 + nt * 8 + tq * 2;
            float b0 = bias[col], b1 = bias[col + 1];
            *(float2*)&C[(size_t)row * N + col] =
                make_float2(acc[mt][nt][0] + b0, acc[mt][nt][1] + b1);
            *(float2*)&C[(size_t)(row + 8) * N + col] =
                make_float2(acc[mt][nt][2] + b0, acc[mt][nt][3] + b1);
        }
    }
}

// ---------------------------------------------------------------------------
// Tensor-core flash attention, causal, bf16x3 split (fp32-accurate).
// CTA: 128 threads (4 warps). Q tile 64 rows (16/warp), KV tile 64, D=64.
// Outputs y pre-split into bf16 hi/lo for the out-projection GEMM.
// ---------------------------------------------------------------------------
#define KPAD 72

__global__ __launch_bounds__(128) void flash_mma(
    const __nv_bfloat16* __restrict__ qhi, const __nv_bfloat16* __restrict__ qlo,
    const __nv_bfloat16* __restrict__ khi, const __nv_bfloat16* __restrict__ klo,
    const __nv_bfloat16* __restrict__ vhi, const __nv_bfloat16* __restrict__ vlo,
    __nv_bfloat16* __restrict__ yhi, __nv_bfloat16* __restrict__ ylo)
{
    __shared__ __nv_bfloat16 Kh[64][KPAD];
    __shared__ __nv_bfloat16 Kl[64][KPAD];
    __shared__ __nv_bfloat16 Vh[64][KPAD];
    __shared__ __nv_bfloat16 Vl[64][KPAD];

    int tid = threadIdx.x, lane = tid & 31, warp = tid >> 5;
    int qt = blockIdx.x, h = blockIdx.y, b = blockIdx.z;
    int qg0 = qt * 64;
    size_t base = ((size_t)b * Sv) * DM + h * Dv;
    int gid = lane >> 2, tig = lane & 3;

    // ---- stage Q tile (hi->Kh, lo->Kl), ldmatrix into register fragments ----
#pragma unroll
    for (int p = 0; p < 4; p++) {
        int e = p * 128 + tid;          // 0..511
        int r = e >> 3, c8 = (e & 7) << 3;
        size_t g = base + (size_t)(qg0 + r) * DM + c8;
        *(uint4*)&Kh[r][c8] = *(const uint4*)&qhi[g];
        *(uint4*)&Kl[r][c8] = *(const uint4*)&qlo[g];
    }
    __syncthreads();
    unsigned Qf[2][4][4];
    {
        int r = warp * 16 + (lane & 15);
        int c = (lane >> 4) << 3;
#pragma unroll
        for (int kt = 0; kt < 4; kt++) {
            unsigned a = (unsigned)__cvta_generic_to_shared(&Kh[r][kt * 16 + c]);
            ldmx4(Qf[0][kt][0], Qf[0][kt][1], Qf[0][kt][2], Qf[0][kt][3], a);
            a = (unsigned)__cvta_generic_to_shared(&Kl[r][kt * 16 + c]);
            ldmx4(Qf[1][kt][0], Qf[1][kt][1], Qf[1][kt][2], Qf[1][kt][3], a);
        }
    }

    // ldmatrix lane address components (constant across tiles)
    int krow = (lane & 7) + ((lane >> 4) << 3);        // K frag: n-row
    int kcol = ((lane >> 3) & 1) << 3;                 // K frag: k offset
    int vrow = (lane & 7) + (((lane >> 3) & 1) << 3);  // V frag: kv-row
    int vcol = (lane >> 4) << 3;                       // V frag: d offset

    float acc_o[8][4];
#pragma unroll
    for (int i = 0; i < 8; i++)
#pragma unroll
        for (int e = 0; e < 4; e++) acc_o[i][e] = 0.f;
    float mrow0 = -1e30f, mrow1 = -1e30f, lrow0 = 0.f, lrow1 = 0.f;

    for (int ktile = 0; ktile <= qt; ktile++) {
        __syncthreads();
        // ---- load K/V hi+lo tiles ----
#pragma unroll
        for (int p = 0; p < 4; p++) {
            int e = p * 128 + tid;
            int r = e >> 3, c8 = (e & 7) << 3;
            size_t g = base + (size_t)(ktile * 64 + r) * DM + c8;
            *(uint4*)&Kh[r][c8] = *(const uint4*)&khi[g];
            *(uint4*)&Kl[r][c8] = *(const uint4*)&klo[g];
            *(uint4*)&Vh[r][c8] = *(const uint4*)&vhi[g];
            *(uint4*)&Vl[r][c8] = *(const uint4*)&vlo[g];
        }
        __syncthreads();

        // ---- S = Q K^T (3-term split) ----
        float s[8][4];
#pragma unroll
        for (int i = 0; i < 8; i++)
#pragma unroll
            for (int e = 0; e < 4; e++) s[i][e] = 0.f;

#pragma unroll
        for (int kt = 0; kt < 4; kt++) {
            unsigned Kf[2][8][2];
#pragma unroll
            for (int ng = 0; ng < 4; ng++) {
                unsigned r0, r1, r2, r3;
                unsigned a = (unsigned)__cvta_generic_to_shared(
                    &Kh[ng * 16 + krow][kt * 16 + kcol]);
                ldmx4(r0, r1, r2, r3, a);
                Kf[0][ng * 2][0] = r0; Kf[0][ng * 2][1] = r1;
                Kf[0][ng * 2 + 1][0] = r2; Kf[0][ng * 2 + 1][1] = r3;
                a = (unsigned)__cvta_generic_to_shared(
                    &Kl[ng * 16 + krow][kt * 16 + kcol]);
                ldmx4(r0, r1, r2, r3, a);
                Kf[1][ng * 2][0] = r0; Kf[1][ng * 2][1] = r1;
                Kf[1][ng * 2 + 1][0] = r2; Kf[1][ng * 2 + 1][1] = r3;
            }
#pragma unroll
            for (int nt = 0; nt < 8; nt++) {
                mma16816(s[nt], Qf[0][kt], Kf[0][nt]);
                mma16816(s[nt], Qf[0][kt], Kf[1][nt]);
                mma16816(s[nt], Qf[1][kt], Kf[0][nt]);
            }
        }

        // ---- scale + causal mask ----
        bool diag = (ktile == qt);
#pragma unroll
        for (int nt = 0; nt < 8; nt++)
#pragma unroll
            for (int e = 0; e < 4; e++) {
                float v = s[nt][e] * 0.125f;
                if (diag) {
                    int col = nt * 8 + 2 * tig + (e & 1);
                    int row = warp * 16 + gid + ((e >> 1) << 3);
                    if (col > row) v = -1e30f;
                }
                s[nt][e] = v;
            }

        // ---- online softmax (rows gid and gid+8; quad reduce) ----
        float mx0 = -1e30f, mx1 = -1e30f;
#pragma unroll
        for (int nt = 0; nt < 8; nt++) {
            mx0 = fmaxf(mx0, fmaxf(s[nt][0], s[nt][1]));
            mx1 = fmaxf(mx1, fmaxf(s[nt][2], s[nt][3]));
        }
        mx0 = fmaxf(mx0, __shfl_xor_sync(0xffffffffu, mx0, 1));
        mx0 = fmaxf(mx0, __shfl_xor_sync(0xffffffffu, mx0, 2));
        mx1 = fmaxf(mx1, __shfl_xor_sync(0xffffffffu, mx1, 1));
        mx1 = fmaxf(mx1, __shfl_xor_sync(0xffffffffu, mx1, 2));
        float mn0 = fmaxf(mrow0, mx0), mn1 = fmaxf(mrow1, mx1);
        float corr0 = __expf(mrow0 - mn0), corr1 = __expf(mrow1 - mn1);
        mrow0 = mn0; mrow1 = mn1;
        float rs0 = 0.f, rs1 = 0.f;
#pragma unroll
        for (int nt = 0; nt < 8; nt++) {
            s[nt][0] = __expf(s[nt][0] - mn0);
            s[nt][1] = __expf(s[nt][1] - mn0);
            s[nt][2] = __expf(s[nt][2] - mn1);
            s[nt][3] = __expf(s[nt][3] - mn1);
            rs0 += s[nt][0] + s[nt][1];
            rs1 += s[nt][2] + s[nt][3];
        }
        rs0 += __shfl_xor_sync(0xffffffffu, rs0, 1);
        rs0 += __shfl_xor_sync(0xffffffffu, rs0, 2);
        rs1 += __shfl_xor_sync(0xffffffffu, rs1, 1);
        rs1 += __shfl_xor_sync(0xffffffffu, rs1, 2);
        lrow0 = lrow0 * corr0 + rs0;
        lrow1 = lrow1 * corr1 + rs1;
#pragma unroll
        for (int i = 0; i < 8; i++) {
            acc_o[i][0] *= corr0; acc_o[i][1] *= corr0;
            acc_o[i][2] *= corr1; acc_o[i][3] *= corr1;
        }

        // ---- O += P V (3-term split; P split in-register) ----
#pragma unroll
        for (int kt = 0; kt < 4; kt++) {
            unsigned Ph[4], Pl[4];
#pragma unroll
            for (int half = 0; half < 2; half++) {
                int nt = 2 * kt + half;
                float2 p0 = make_float2(s[nt][0], s[nt][1]);
                float2 p1 = make_float2(s[nt][2], s[nt][3]);
                __nv_bfloat162 h0 = __float22bfloat162_rn(p0);
                __nv_bfloat162 h1 = __float22bfloat162_rn(p1);
                float2 b0 = __bfloat1622float2(h0);
                float2 b1 = __bfloat1622float2(h1);
                __nv_bfloat162 l0 = __float22bfloat162_rn(
                    make_float2(p0.x - b0.x, p0.y - b0.y));
                __nv_bfloat162 l1 = __float22bfloat162_rn(
                    make_float2(p1.x - b1.x, p1.y - b1.y));
                Ph[half * 2]     = *(unsigned*)&h0;
                Ph[half * 2 + 1] = *(unsigned*)&h1;
                Pl[half * 2]     = *(unsigned*)&l0;
                Pl[half * 2 + 1] = *(unsigned*)&l1;
            }
            unsigned Vf[2][8][2];
#pragma unroll
            for (int dg = 0; dg < 4; dg++) {
                unsigned r0, r1, r2, r3;
                unsigned a = (unsigned)__cvta_generic_to_shared(
                    &Vh[kt * 16 + vrow][dg * 16 + vcol]);
                ldmx4t(r0, r1, r2, r3, a);
                Vf[0][dg * 2][0] = r0; Vf[0][dg * 2][1] = r1;
                Vf[0][dg * 2 + 1][0] = r2; Vf[0][dg * 2 + 1][1] = r3;
                a = (unsigned)__cvta_generic_to_shared(
                    &Vl[kt * 16 + vrow][dg * 16 + vcol]);
                ldmx4t(r0, r1, r2, r3, a);
                Vf[1][dg * 2][0] = r0; Vf[1][dg * 2][1] = r1;
                Vf[1][dg * 2 + 1][0] = r2; Vf[1][dg * 2 + 1][1] = r3;
            }
#pragma unroll
            for (int dnt = 0; dnt < 8; dnt++) {
                mma16816(acc_o[dnt], Ph, Vf[0][dnt]);
                mma16816(acc_o[dnt], Pl, Vf[0][dnt]);
                mma16816(acc_o[dnt], Ph, Vf[1][dnt]);
            }
        }
    }

    // ---- epilogue: normalize, split to bf16 hi/lo, store ----
    float inv0 = 1.f / lrow0, inv1 = 1.f / lrow1;
    int row0 = qg0 + warp * 16 + gid;
    size_t o0 = ((size_t)b * Sv + row0) * DM + h * Dv;
    size_t o1 = o0 + (size_t)8 * DM;
#pragma unroll
    for (int dnt = 0; dnt < 8; dnt++) {
        int col = dnt * 8 + 2 * tig;
        float2 v0 = make_float2(acc_o[dnt][0] * inv0, acc_o[dnt][1] * inv0);
        float2 v1 = make_float2(acc_o[dnt][2] * inv1, acc_o[dnt][3] * inv1);
        __nv_bfloat162 h0 = __float22bfloat162_rn(v0);
        __nv_bfloat162 h1 = __float22bfloat162_rn(v1);
        float2 b0 = __bfloat1622float2(h0);
        float2 b1 = __bfloat1622float2(h1);
        __nv_bfloat162 l0 = __float22bfloat162_rn(make_float2(v0.x - b0.x, v0.y - b0.y));
        __nv_bfloat162 l1 = __float22bfloat162_rn(make_float2(v1.x - b1.x, v1.y - b1.y));
        *(__nv_bfloat162*)&yhi[o0 + col] = h0;
        *(__nv_bfloat162*)&ylo[o0 + col] = l0;
        *(__nv_bfloat162*)&yhi[o1 + col] = h1;
        *(__nv_bfloat162*)&ylo[o1 + col] = l1;
    }
}

// ---------------------------------------------------------------------------
// kernel_launch
// ---------------------------------------------------------------------------
extern "C" void kernel_launch(void* const* d_in, const int* in_sizes, int n_in,
                              void* d_out, int out_size)
{
    const float* x  = (const float*)d_in[0];
    const float* Wq = (const float*)d_in[1];
    const float* bq = (const float*)d_in[2];
    const float* Wk = (const float*)d_in[3];
    const float* bk = (const float*)d_in[4];
    const float* Wv = (const float*)d_in[5];
    const float* bv = (const float*)d_in[6];
    const float* Wo = (const float*)d_in[7];
    const float* bo = (const float*)d_in[8];
    float* out = (float*)d_out;

    float *qp, *kp, *vp;
    cudaGetSymbolAddress((void**)&qp, g_q);
    cudaGetSymbolAddress((void**)&kp, g_k);
    cudaGetSymbolAddress((void**)&vp, g_v);
    __nv_bfloat16 *xhi, *xlo, *yhi, *ylo, *whi, *wlo;
    __nv_bfloat16 *qhi, *qlo, *khi, *klo, *vhi, *vlo;
    cudaGetSymbolAddress((void**)&xhi, g_xhi);
    cudaGetSymbolAddress((void**)&xlo, g_xlo);
    cudaGetSymbolAddress((void**)&yhi, g_yhi);
    cudaGetSymbolAddress((void**)&ylo, g_ylo);
    cudaGetSymbolAddress((void**)&whi, g_whi);
    cudaGetSymbolAddress((void**)&wlo, g_wlo);
    cudaGetSymbolAddress((void**)&qhi, g_qhi);
    cudaGetSymbolAddress((void**)&qlo, g_qlo);
    cudaGetSymbolAddress((void**)&khi, g_khi);
    cudaGetSymbolAddress((void**)&klo, g_klo);
    cudaGetSymbolAddress((void**)&vhi, g_vhi);
    cudaGetSymbolAddress((void**)&vlo, g_vlo);

    const int NX = Mv * DM;
    const int NW = DM * DM;

    rope_table_kernel<<<(Sv * 32 + 255) / 256, 256>>>();

    split_kernel<<<(NX + 255) / 256, 256>>>(x, xhi, xlo, NX);
    split_kernel<<<(NW + 255) / 256, 256>>>(Wq, whi + 0 * NW, wlo + 0 * NW, NW);
    split_kernel<<<(NW + 255) / 256, 256>>>(Wk, whi + 1 * NW, wlo + 1 * NW, NW);
    split_kernel<<<(NW + 255) / 256, 256>>>(Wv, whi + 2 * NW, wlo + 2 * NW, NW);
    split_kernel<<<(NW + 255) / 256, 256>>>(Wo, whi + 3 * NW, wlo + 3 * NW, NW);

    dim3 gg(DM / 64, Mv / 128);
    gemm_bf16x3<<<gg, 128>>>(xhi, xlo, whi + 0 * NW, wlo + 0 * NW, bq, qp, Mv, DM, DM);
    gemm_bf16x3<<<gg, 128>>>(xhi, xlo, whi + 1 * NW, wlo + 1 * NW, bk, kp, Mv, DM, DM);
    gemm_bf16x3<<<gg, 128>>>(xhi, xlo, whi + 2 * NW, wlo + 2 * NW, bv, vp, Mv, DM, DM);

    // rope + split q/k; split v
    int nrope = Mv * 512;
    rope_split_kernel<<<(nrope + 255) / 256, 256>>>(
        (const float2*)qp, (__nv_bfloat162*)qhi, (__nv_bfloat162*)qlo);
    rope_split_kernel<<<(nrope + 255) / 256, 256>>>(
        (const float2*)kp, (__nv_bfloat162*)khi, (__nv_bfloat162*)klo);
    split_kernel<<<(NX + 255) / 256, 256>>>(vp, vhi, vlo, NX);

    // tensor-core flash attention -> yhi/ylo
    dim3 att_grid(Sv / 64, Hv, Bv);
    flash_mma<<<att_grid, 128>>>(qhi, qlo, khi, klo, vhi, vlo, yhi, ylo);

    // output projection
    gemm_bf16x3<<<gg, 128>>>(yhi, ylo, whi + 3 * NW, wlo + 3 * NW, bo, out, Mv, DM, DM);
}

// round 5
// speedup vs baseline: 3.4199x; 1.0373x over previous
#include <cuda_runtime.h>
#include <cuda_bf16.h>
#include <stdint.h>
#include <cstdint>
#include <math.h>

#define Bv 4
#define Sv 2048
#define Hv 16
#define Dv 64
#define DM 1024
#define Mv (Bv*Sv)   // 8192

// ---------------------------------------------------------------------------
// Scratch (allocation-free rule: __device__ globals)
// ---------------------------------------------------------------------------
__device__ float g_q[Mv*DM];
__device__ float g_k[Mv*DM];
__device__ float g_v[Mv*DM];
__device__ float g_cos[Sv*32];
__device__ float g_sin[Sv*32];

__device__ __nv_bfloat16 g_xhi[Mv*DM];
__device__ __nv_bfloat16 g_xlo[Mv*DM];
__device__ __nv_bfloat16 g_yhi[Mv*DM];
__device__ __nv_bfloat16 g_ylo[Mv*DM];
__device__ __nv_bfloat16 g_whi[4*DM*DM];
__device__ __nv_bfloat16 g_wlo[4*DM*DM];
__device__ __nv_bfloat16 g_qhi[Mv*DM];
__device__ __nv_bfloat16 g_qlo[Mv*DM];
__device__ __nv_bfloat16 g_khi[Mv*DM];
__device__ __nv_bfloat16 g_klo[Mv*DM];
__device__ __nv_bfloat16 g_vhi[Mv*DM];
__device__ __nv_bfloat16 g_vlo[Mv*DM];

// ---------------------------------------------------------------------------
// helpers
// ---------------------------------------------------------------------------
__global__ void split_kernel(const float* __restrict__ s,
                             __nv_bfloat16* __restrict__ hi,
                             __nv_bfloat16* __restrict__ lo, int n)
{
    int i = blockIdx.x * blockDim.x + threadIdx.x;
    if (i >= n) return;
    float x = s[i];
    __nv_bfloat16 h = __float2bfloat16(x);
    hi[i] = h;
    lo[i] = __float2bfloat16(x - __bfloat162float(h));
}

__global__ void rope_table_kernel() {
    int idx = blockIdx.x * blockDim.x + threadIdx.x;
    if (idx >= Sv * 32) return;
    int pos = idx >> 5;
    int i   = idx & 31;
    double inv = pow(10000.0, -(double)i / 32.0);
    double ang = (double)pos * inv;
    g_cos[idx] = (float)cos(ang);
    g_sin[idx] = (float)sin(ang);
}

__global__ void rope_split_kernel(const float2* __restrict__ src,
                                  __nv_bfloat162* __restrict__ hi,
                                  __nv_bfloat162* __restrict__ lo)
{
    int idx = blockIdx.x * blockDim.x + threadIdx.x;
    if (idx >= Mv * 512) return;
    int p = idx & 511;
    int i = p & 31;
    int s = (idx >> 9) & (Sv - 1);
    float c  = g_cos[(s << 5) + i];
    float sn = g_sin[(s << 5) + i];
    float2 v = src[idx];
    float2 r = make_float2(v.x * c - v.y * sn, v.y * c + v.x * sn);
    __nv_bfloat162 h2 = __float22bfloat162_rn(r);
    float2 back = __bfloat1622float2(h2);
    hi[idx] = h2;
    lo[idx] = __float22bfloat162_rn(make_float2(r.x - back.x, r.y - back.y));
}

// ---------------------------------------------------------------------------
// MMA / async-copy primitives
// ---------------------------------------------------------------------------
__device__ __forceinline__ void ldmx4(unsigned& r0, unsigned& r1,
                                      unsigned& r2, unsigned& r3, unsigned a) {
    asm volatile("ldmatrix.sync.aligned.m8n8.x4.shared.b16 {%0,%1,%2,%3}, [%4];"
        : "=r"(r0), "=r"(r1), "=r"(r2), "=r"(r3) : "r"(a));
}
__device__ __forceinline__ void ldmx4t(unsigned& r0, unsigned& r1,
                                       unsigned& r2, unsigned& r3, unsigned a) {
    asm volatile("ldmatrix.sync.aligned.m8n8.x4.trans.shared.b16 {%0,%1,%2,%3}, [%4];"
        : "=r"(r0), "=r"(r1), "=r"(r2), "=r"(r3) : "r"(a));
}
__device__ __forceinline__ void mma16816(float* c, const unsigned* a, const unsigned* b) {
    asm volatile(
        "mma.sync.aligned.m16n8k16.row.col.f32.bf16.bf16.f32 "
        "{%0,%1,%2,%3}, {%4,%5,%6,%7}, {%8,%9}, {%0,%1,%2,%3};"
        : "+f"(c[0]), "+f"(c[1]), "+f"(c[2]), "+f"(c[3])
        : "r"(a[0]), "r"(a[1]), "r"(a[2]), "r"(a[3]), "r"(b[0]), "r"(b[1]));
}
__device__ __forceinline__ void cpa16(void* smem, const void* g) {
    unsigned s = (unsigned)__cvta_generic_to_shared(smem);
    asm volatile("cp.async.cg.shared.global [%0], [%1], 16;" :: "r"(s), "l"(g));
}
__device__ __forceinline__ void cp_commit() {
    asm volatile("cp.async.commit_group;");
}
template<int N> __device__ __forceinline__ void cp_wait() {
    asm volatile("cp.async.wait_group %0;" :: "n"(N));
}

// ---------------------------------------------------------------------------
// Tensor-core GEMM with bf16x3 split (unchanged from R3/R4)
// ---------------------------------------------------------------------------
#define APAD 40
#define BPAD 72

__global__ __launch_bounds__(128) void gemm_bf16x3(
    const __nv_bfloat16* __restrict__ Ahi, const __nv_bfloat16* __restrict__ Alo,
    const __nv_bfloat16* __restrict__ Bhi, const __nv_bfloat16* __restrict__ Blo,
    const float* __restrict__ bias, float* __restrict__ C,
    int M, int N, int K)
{
    __shared__ __nv_bfloat16 As[2][128][APAD];
    __shared__ __nv_bfloat16 Bs[2][32][BPAD];

    int tid  = threadIdx.x;
    int lane = tid & 31;
    int warp = tid >> 5;
    int wm = warp >> 1, wn = warp & 1;
    int bm = blockIdx.y << 7;
    int bn = blockIdx.x << 6;

    float acc[4][4][4];
#pragma unroll
    for (int i = 0; i < 4; i++)
#pragma unroll
        for (int j = 0; j < 4; j++)
#pragma unroll
            for (int e = 0; e < 4; e++) acc[i][j][e] = 0.f;

    int u0k = tid >> 3, u0n = (tid & 7) << 3;
    int u1k = (tid + 128) >> 3, u1n = ((tid + 128) & 7) << 3;

    for (int k0 = 0; k0 < K; k0 += 32) {
        uint4 ah[4], al[4], bh[2], bl[2];
        const __nv_bfloat16* Ahp = Ahi + (size_t)(bm + tid) * K + k0;
        const __nv_bfloat16* Alp = Alo + (size_t)(bm + tid) * K + k0;
#pragma unroll
        for (int i = 0; i < 4; i++) {
            ah[i] = *(const uint4*)(Ahp + i * 8);
            al[i] = *(const uint4*)(Alp + i * 8);
        }
        bh[0] = *(const uint4*)(Bhi + (size_t)(k0 + u0k) * N + bn + u0n);
        bh[1] = *(const uint4*)(Bhi + (size_t)(k0 + u1k) * N + bn + u1n);
        bl[0] = *(const uint4*)(Blo + (size_t)(k0 + u0k) * N + bn + u0n);
        bl[1] = *(const uint4*)(Blo + (size_t)(k0 + u1k) * N + bn + u1n);

        __syncthreads();
#pragma unroll
        for (int i = 0; i < 4; i++) {
            *(uint4*)&As[0][tid][i * 8] = ah[i];
            *(uint4*)&As[1][tid][i * 8] = al[i];
        }
        *(uint4*)&Bs[0][u0k][u0n] = bh[0];
        *(uint4*)&Bs[0][u1k][u1n] = bh[1];
        *(uint4*)&Bs[1][u0k][u0n] = bl[0];
        *(uint4*)&Bs[1][u1k][u1n] = bl[1];
        __syncthreads();

#pragma unroll
        for (int ks = 0; ks < 2; ks++) {
            int k16 = ks << 4;
            unsigned Af[2][4][4];
            int ar = (lane & 15);
            int ac = k16 + ((lane >> 4) << 3);
#pragma unroll
            for (int mt = 0; mt < 4; mt++) {
                int m0 = wm * 64 + mt * 16;
                unsigned a0 = (unsigned)__cvta_generic_to_shared(&As[0][m0 + ar][ac]);
                ldmx4(Af[0][mt][0], Af[0][mt][1], Af[0][mt][2], Af[0][mt][3], a0);
                unsigned a1 = (unsigned)__cvta_generic_to_shared(&As[1][m0 + ar][ac]);
                ldmx4(Af[1][mt][0], Af[1][mt][1], Af[1][mt][2], Af[1][mt][3], a1);
            }
            unsigned Bf[2][4][2];
            int bkr = k16 + (lane & 7) + (lane & 8);
#pragma unroll
            for (int p = 0; p < 2; p++) {
                int n0 = wn * 32 + p * 16 + (((lane >> 4) & 1) << 3);
                unsigned r0, r1, r2, r3;
                unsigned ad = (unsigned)__cvta_generic_to_shared(&Bs[0][bkr][n0]);
                ldmx4t(r0, r1, r2, r3, ad);
                Bf[0][p * 2][0] = r0; Bf[0][p * 2][1] = r1;
                Bf[0][p * 2 + 1][0] = r2; Bf[0][p * 2 + 1][1] = r3;
                ad = (unsigned)__cvta_generic_to_shared(&Bs[1][bkr][n0]);
                ldmx4t(r0, r1, r2, r3, ad);
                Bf[1][p * 2][0] = r0; Bf[1][p * 2][1] = r1;
                Bf[1][p * 2 + 1][0] = r2; Bf[1][p * 2 + 1][1] = r3;
            }
#pragma unroll
            for (int mt = 0; mt < 4; mt++)
#pragma unroll
                for (int nt = 0; nt < 4; nt++) {
                    mma16816(acc[mt][nt], Af[0][mt], Bf[0][nt]);
                    mma16816(acc[mt][nt], Af[0][mt], Bf[1][nt]);
                    mma16816(acc[mt][nt], Af[1][mt], Bf[0][nt]);
                }
        }
    }

    int gid = lane >> 2, tq = lane & 3;
#pragma unroll
    for (int mt = 0; mt < 4; mt++) {
        int row = bm + wm * 64 + mt * 16 + gid;
#pragma unroll
        for (int nt = 0; nt < 4; nt++) {
            int col = bn + wn * 32 + nt * 8 + tq * 2;
            float b0 = bias[col], b1 = bias[col + 1];
            *(float2*)&C[(size_t)row * N + col] =
                make_float2(acc[mt][nt][0] + b0, acc[mt][nt][1] + b1);
            *(float2*)&C[(size_t)(row + 8) * N + col] =
                make_float2(acc[mt][nt][2] + b0, acc[mt][nt][3] + b1);
        }
    }
}

// ---------------------------------------------------------------------------
// Tensor-core flash attention, causal, bf16x3, cp.async double-buffered K/V.
// 128 threads (4 warps). Q tile 64 rows (16/warp), KV tile 64, D=64.
// smem: 2 stages x {Kh,Kl,Vh,Vl}, each buffer 64x72 bf16 (9216 B).
// ---------------------------------------------------------------------------
#define KPAD 72
#define BUF_ELEMS (64*KPAD)      // 4608
#define STG_ELEMS (4*BUF_ELEMS)  // 18432
#define FLASH_SMEM (2*STG_ELEMS*sizeof(__nv_bfloat16))  // 73728

__global__ __launch_bounds__(128) void flash_mma(
    const __nv_bfloat16* __restrict__ qhi, const __nv_bfloat16* __restrict__ qlo,
    const __nv_bfloat16* __restrict__ khi, const __nv_bfloat16* __restrict__ klo,
    const __nv_bfloat16* __restrict__ vhi, const __nv_bfloat16* __restrict__ vlo,
    __nv_bfloat16* __restrict__ yhi, __nv_bfloat16* __restrict__ ylo)
{
    extern __shared__ __nv_bfloat16 smx[];

    int tid = threadIdx.x, lane = tid & 31, warp = tid >> 5;
    int qt = blockIdx.x, h = blockIdx.y, b = blockIdx.z;
    int qg0 = qt * 64;
    size_t base = ((size_t)b * Sv) * DM + h * Dv;
    int gid = lane >> 2, tig = lane & 3;

    const __nv_bfloat16* srcs[4] = {khi, klo, vhi, vlo};

    // ---- prefetch Q tile into stage 1 (hi @ +0, lo @ +BUF_ELEMS) ----
    {
        const __nv_bfloat16* qs[2] = {qhi, qlo};
#pragma unroll
        for (int p = 0; p < 8; p++) {
            int e = p * 128 + tid;            // 0..1023
            int bq = e >> 9;                  // 0:hi 1:lo
            int idx = e & 511;
            int row = idx >> 3, c = idx & 7;
            cpa16(&smx[STG_ELEMS + bq * BUF_ELEMS + row * KPAD + c * 8],
                  qs[bq] + base + (size_t)(qg0 + row) * DM + c * 8);
        }
        cp_commit();
    }
    // ---- prefetch KV tile 0 into stage 0 ----
#pragma unroll
    for (int p = 0; p < 16; p++) {
        int buf = p >> 2;
        int idx = ((p & 3) << 7) + tid;
        int row = idx >> 3, c = idx & 7;
        cpa16(&smx[buf * BUF_ELEMS + row * KPAD + c * 8],
              srcs[buf] + base + (size_t)row * DM + c * 8);
    }
    cp_commit();

    // Q arrived (tile0 may still be in flight)
    cp_wait<1>();
    __syncthreads();

    unsigned Qf[2][4][4];
    {
        int r = warp * 16 + (lane & 15);
        int c = (lane >> 4) << 3;
#pragma unroll
        for (int kt = 0; kt < 4; kt++) {
            unsigned a = (unsigned)__cvta_generic_to_shared(
                &smx[STG_ELEMS + r * KPAD + kt * 16 + c]);
            ldmx4(Qf[0][kt][0], Qf[0][kt][1], Qf[0][kt][2], Qf[0][kt][3], a);
            a = (unsigned)__cvta_generic_to_shared(
                &smx[STG_ELEMS + BUF_ELEMS + r * KPAD + kt * 16 + c]);
            ldmx4(Qf[1][kt][0], Qf[1][kt][1], Qf[1][kt][2], Qf[1][kt][3], a);
        }
    }
    __syncthreads();   // stage1 reads done before tile-1 prefetch overwrites it

    int krow = (lane & 7) + ((lane >> 4) << 3);
    int kcol = ((lane >> 3) & 1) << 3;
    int vrow = (lane & 7) + (((lane >> 3) & 1) << 3);
    int vcol = (lane >> 4) << 3;

    float acc_o[8][4];
#pragma unroll
    for (int i = 0; i < 8; i++)
#pragma unroll
        for (int e = 0; e < 4; e++) acc_o[i][e] = 0.f;
    float mrow0 = -1e30f, mrow1 = -1e30f, lrow0 = 0.f, lrow1 = 0.f;

    int n = qt + 1;
    for (int j = 0; j < n; j++) {
        int s = j & 1;
        if (j + 1 < n) {
            // prefetch tile j+1 into the other stage
            int sb = (1 - s) * STG_ELEMS;
            size_t grow = base + (size_t)(j + 1) * 64 * DM;
#pragma unroll
            for (int p = 0; p < 16; p++) {
                int buf = p >> 2;
                int idx = ((p & 3) << 7) + tid;
                int row = idx >> 3, c = idx & 7;
                cpa16(&smx[sb + buf * BUF_ELEMS + row * KPAD + c * 8],
                      srcs[buf] + grow + (size_t)row * DM + c * 8);
            }
            cp_commit();
            cp_wait<1>();
        } else {
            cp_wait<0>();
        }
        __syncthreads();

        __nv_bfloat16* Kh_ = smx + s * STG_ELEMS;
        __nv_bfloat16* Kl_ = Kh_ + BUF_ELEMS;
        __nv_bfloat16* Vh_ = Kh_ + 2 * BUF_ELEMS;
        __nv_bfloat16* Vl_ = Kh_ + 3 * BUF_ELEMS;

        // ---- S = Q K^T (3-term split) ----
        float sc[8][4];
#pragma unroll
        for (int i = 0; i < 8; i++)
#pragma unroll
            for (int e = 0; e < 4; e++) sc[i][e] = 0.f;

#pragma unroll
        for (int kt = 0; kt < 4; kt++) {
            unsigned Kf[2][8][2];
#pragma unroll
            for (int ng = 0; ng < 4; ng++) {
                unsigned r0, r1, r2, r3;
                unsigned a = (unsigned)__cvta_generic_to_shared(
                    &Kh_[(ng * 16 + krow) * KPAD + kt * 16 + kcol]);
                ldmx4(r0, r1, r2, r3, a);
                Kf[0][ng * 2][0] = r0; Kf[0][ng * 2][1] = r1;
                Kf[0][ng * 2 + 1][0] = r2; Kf[0][ng * 2 + 1][1] = r3;
                a = (unsigned)__cvta_generic_to_shared(
                    &Kl_[(ng * 16 + krow) * KPAD + kt * 16 + kcol]);
                ldmx4(r0, r1, r2, r3, a);
                Kf[1][ng * 2][0] = r0; Kf[1][ng * 2][1] = r1;
                Kf[1][ng * 2 + 1][0] = r2; Kf[1][ng * 2 + 1][1] = r3;
            }
#pragma unroll
            for (int nt = 0; nt < 8; nt++) {
                mma16816(sc[nt], Qf[0][kt], Kf[0][nt]);
                mma16816(sc[nt], Qf[0][kt], Kf[1][nt]);
                mma16816(sc[nt], Qf[1][kt], Kf[0][nt]);
            }
        }

        // ---- scale + causal mask ----
        bool diag = (j == qt);
#pragma unroll
        for (int nt = 0; nt < 8; nt++)
#pragma unroll
            for (int e = 0; e < 4; e++) {
                float v = sc[nt][e] * 0.125f;
                if (diag) {
                    int col = nt * 8 + 2 * tig + (e & 1);
                    int row = warp * 16 + gid + ((e >> 1) << 3);
                    if (col > row) v = -1e30f;
                }
                sc[nt][e] = v;
            }

        // ---- online softmax ----
        float mx0 = -1e30f, mx1 = -1e30f;
#pragma unroll
        for (int nt = 0; nt < 8; nt++) {
            mx0 = fmaxf(mx0, fmaxf(sc[nt][0], sc[nt][1]));
            mx1 = fmaxf(mx1, fmaxf(sc[nt][2], sc[nt][3]));
        }
        mx0 = fmaxf(mx0, __shfl_xor_sync(0xffffffffu, mx0, 1));
        mx0 = fmaxf(mx0, __shfl_xor_sync(0xffffffffu, mx0, 2));
        mx1 = fmaxf(mx1, __shfl_xor_sync(0xffffffffu, mx1, 1));
        mx1 = fmaxf(mx1, __shfl_xor_sync(0xffffffffu, mx1, 2));
        float mn0 = fmaxf(mrow0, mx0), mn1 = fmaxf(mrow1, mx1);
        float corr0 = __expf(mrow0 - mn0), corr1 = __expf(mrow1 - mn1);
        mrow0 = mn0; mrow1 = mn1;
        float rs0 = 0.f, rs1 = 0.f;
#pragma unroll
        for (int nt = 0; nt < 8; nt++) {
            sc[nt][0] = __expf(sc[nt][0] - mn0);
            sc[nt][1] = __expf(sc[nt][1] - mn0);
            sc[nt][2] = __expf(sc[nt][2] - mn1);
            sc[nt][3] = __expf(sc[nt][3] - mn1);
            rs0 += sc[nt][0] + sc[nt][1];
            rs1 += sc[nt][2] + sc[nt][3];
        }
        rs0 += __shfl_xor_sync(0xffffffffu, rs0, 1);
        rs0 += __shfl_xor_sync(0xffffffffu, rs0, 2);
        rs1 += __shfl_xor_sync(0xffffffffu, rs1, 1);
        rs1 += __shfl_xor_sync(0xffffffffu, rs1, 2);
        lrow0 = lrow0 * corr0 + rs0;
        lrow1 = lrow1 * corr1 + rs1;
#pragma unroll
        for (int i = 0; i < 8; i++) {
            acc_o[i][0] *= corr0; acc_o[i][1] *= corr0;
            acc_o[i][2] *= corr1; acc_o[i][3] *= corr1;
        }

        // ---- O += P V (3-term split; P split in-register) ----
#pragma unroll
        for (int kt = 0; kt < 4; kt++) {
            unsigned Ph[4], Pl[4];
#pragma unroll
            for (int half = 0; half < 2; half++) {
                int nt = 2 * kt + half;
                float2 p0 = make_float2(sc[nt][0], sc[nt][1]);
                float2 p1 = make_float2(sc[nt][2], sc[nt][3]);
                __nv_bfloat162 h0 = __float22bfloat162_rn(p0);
                __nv_bfloat162 h1 = __float22bfloat162_rn(p1);
                float2 b0 = __bfloat1622float2(h0);
                float2 b1 = __bfloat1622float2(h1);
                __nv_bfloat162 l0 = __float22bfloat162_rn(
                    make_float2(p0.x - b0.x, p0.y - b0.y));
                __nv_bfloat162 l1 = __float22bfloat162_rn(
                    make_float2(p1.x - b1.x, p1.y - b1.y));
                Ph[half * 2]     = *(unsigned*)&h0;
                Ph[half * 2 + 1] = *(unsigned*)&h1;
                Pl[half * 2]     = *(unsigned*)&l0;
                Pl[half * 2 + 1] = *(unsigned*)&l1;
            }
            unsigned Vf[2][8][2];
#pragma unroll
            for (int dg = 0; dg < 4; dg++) {
                unsigned r0, r1, r2, r3;
                unsigned a = (unsigned)__cvta_generic_to_shared(
                    &Vh_[(kt * 16 + vrow) * KPAD + dg * 16 + vcol]);
                ldmx4t(r0, r1, r2, r3, a);
                Vf[0][dg * 2][0] = r0; Vf[0][dg * 2][1] = r1;
                Vf[0][dg * 2 + 1][0] = r2; Vf[0][dg * 2 + 1][1] = r3;
                a = (unsigned)__cvta_generic_to_shared(
                    &Vl_[(kt * 16 + vrow) * KPAD + dg * 16 + vcol]);
                ldmx4t(r0, r1, r2, r3, a);
                Vf[1][dg * 2][0] = r0; Vf[1][dg * 2][1] = r1;
                Vf[1][dg * 2 + 1][0] = r2; Vf[1][dg * 2 + 1][1] = r3;
            }
#pragma unroll
            for (int dnt = 0; dnt < 8; dnt++) {
                mma16816(acc_o[dnt], Ph, Vf[0][dnt]);
                mma16816(acc_o[dnt], Pl, Vf[0][dnt]);
                mma16816(acc_o[dnt], Ph, Vf[1][dnt]);
            }
        }
        __syncthreads();  // reads of stage s done before it is overwritten
    }

    // ---- epilogue ----
    float inv0 = 1.f / lrow0, inv1 = 1.f / lrow1;
    int row0 = qg0 + warp * 16 + gid;
    size_t o0 = ((size_t)b * Sv + row0) * DM + h * Dv;
    size_t o1 = o0 + (size_t)8 * DM;
#pragma unroll
    for (int dnt = 0; dnt < 8; dnt++) {
        int col = dnt * 8 + 2 * tig;
        float2 v0 = make_float2(acc_o[dnt][0] * inv0, acc_o[dnt][1] * inv0);
        float2 v1 = make_float2(acc_o[dnt][2] * inv1, acc_o[dnt][3] * inv1);
        __nv_bfloat162 h0 = __float22bfloat162_rn(v0);
        __nv_bfloat162 h1 = __float22bfloat162_rn(v1);
        float2 b0 = __bfloat1622float2(h0);
        float2 b1 = __bfloat1622float2(h1);
        __nv_bfloat162 l0 = __float22bfloat162_rn(make_float2(v0.x - b0.x, v0.y - b0.y));
        __nv_bfloat162 l1 = __float22bfloat162_rn(make_float2(v1.x - b1.x, v1.y - b1.y));
        *(__nv_bfloat162*)&yhi[o0 + col] = h0;
        *(__nv_bfloat162*)&ylo[o0 + col] = l0;
        *(__nv_bfloat162*)&yhi[o1 + col] = h1;
        *(__nv_bfloat162*)&ylo[o1 + col] = l1;
    }
}

// ---------------------------------------------------------------------------
// kernel_launch
// ---------------------------------------------------------------------------
extern "C" void kernel_launch(void* const* d_in, const int* in_sizes, int n_in,
                              void* d_out, int out_size)
{
    const float* x  = (const float*)d_in[0];
    const float* Wq = (const float*)d_in[1];
    const float* bq = (const float*)d_in[2];
    const float* Wk = (const float*)d_in[3];
    const float* bk = (const float*)d_in[4];
    const float* Wv = (const float*)d_in[5];
    const float* bv = (const float*)d_in[6];
    const float* Wo = (const float*)d_in[7];
    const float* bo = (const float*)d_in[8];
    float* out = (float*)d_out;

    float *qp, *kp, *vp;
    cudaGetSymbolAddress((void**)&qp, g_q);
    cudaGetSymbolAddress((void**)&kp, g_k);
    cudaGetSymbolAddress((void**)&vp, g_v);
    __nv_bfloat16 *xhi, *xlo, *yhi, *ylo, *whi, *wlo;
    __nv_bfloat16 *qhi, *qlo, *khi, *klo, *vhi, *vlo;
    cudaGetSymbolAddress((void**)&xhi, g_xhi);
    cudaGetSymbolAddress((void**)&xlo, g_xlo);
    cudaGetSymbolAddress((void**)&yhi, g_yhi);
    cudaGetSymbolAddress((void**)&ylo, g_ylo);
    cudaGetSymbolAddress((void**)&whi, g_whi);
    cudaGetSymbolAddress((void**)&wlo, g_wlo);
    cudaGetSymbolAddress((void**)&qhi, g_qhi);
    cudaGetSymbolAddress((void**)&qlo, g_qlo);
    cudaGetSymbolAddress((void**)&khi, g_khi);
    cudaGetSymbolAddress((void**)&klo, g_klo);
    cudaGetSymbolAddress((void**)&vhi, g_vhi);
    cudaGetSymbolAddress((void**)&vlo, g_vlo);

    cudaFuncSetAttribute(flash_mma,
                         cudaFuncAttributeMaxDynamicSharedMemorySize,
                         (int)FLASH_SMEM);

    const int NX = Mv * DM;
    const int NW = DM * DM;

    rope_table_kernel<<<(Sv * 32 + 255) / 256, 256>>>();

    split_kernel<<<(NX + 255) / 256, 256>>>(x, xhi, xlo, NX);
    split_kernel<<<(NW + 255) / 256, 256>>>(Wq, whi + 0 * NW, wlo + 0 * NW, NW);
    split_kernel<<<(NW + 255) / 256, 256>>>(Wk, whi + 1 * NW, wlo + 1 * NW, NW);
    split_kernel<<<(NW + 255) / 256, 256>>>(Wv, whi + 2 * NW, wlo + 2 * NW, NW);
    split_kernel<<<(NW + 255) / 256, 256>>>(Wo, whi + 3 * NW, wlo + 3 * NW, NW);

    dim3 gg(DM / 64, Mv / 128);
    gemm_bf16x3<<<gg, 128>>>(xhi, xlo, whi + 0 * NW, wlo + 0 * NW, bq, qp, Mv, DM, DM);
    gemm_bf16x3<<<gg, 128>>>(xhi, xlo, whi + 1 * NW, wlo + 1 * NW, bk, kp, Mv, DM, DM);
    gemm_bf16x3<<<gg, 128>>>(xhi, xlo, whi + 2 * NW, wlo + 2 * NW, bv, vp, Mv, DM, DM);

    int nrope = Mv * 512;
    rope_split_kernel<<<(nrope + 255) / 256, 256>>>(
        (const float2*)qp, (__nv_bfloat162*)qhi, (__nv_bfloat162*)qlo);
    rope_split_kernel<<<(nrope + 255) / 256, 256>>>(
        (const float2*)kp, (__nv_bfloat162*)khi, (__nv_bfloat162*)klo);
    split_kernel<<<(NX + 255) / 256, 256>>>(vp, vhi, vlo, NX);

    dim3 att_grid(Sv / 64, Hv, Bv);
    flash_mma<<<att_grid, 128, FLASH_SMEM>>>(qhi, qlo, khi, klo, vhi, vlo, yhi, ylo);

    gemm_bf16x3<<<gg, 128>>>(yhi, ylo, whi + 3 * NW, wlo + 3 * NW, bo, out, Mv, DM, DM);
}

// round 7
// speedup vs baseline: 3.4565x; 1.0107x over previous
#include <cuda_runtime.h>
#include <cuda_bf16.h>
#include <stdint.h>
#include <cstdint>
#include <math.h>

#define Bv 4
#define Sv 2048
#define Hv 16
#define Dv 64
#define DM 1024
#define Mv (Bv*Sv)   // 8192

// ---------------------------------------------------------------------------
// Scratch (allocation-free rule: __device__ globals)
// ---------------------------------------------------------------------------
__device__ float g_q[Mv*DM];
__device__ float g_k[Mv*DM];
__device__ float g_v[Mv*DM];
__device__ float g_cos[Sv*32];
__device__ float g_sin[Sv*32];

__device__ __nv_bfloat16 g_xhi[Mv*DM];
__device__ __nv_bfloat16 g_xlo[Mv*DM];
__device__ __nv_bfloat16 g_yhi[Mv*DM];
__device__ __nv_bfloat16 g_ylo[Mv*DM];
__device__ __nv_bfloat16 g_whi[4*DM*DM];
__device__ __nv_bfloat16 g_wlo[4*DM*DM];
__device__ __nv_bfloat16 g_qhi[Mv*DM];
__device__ __nv_bfloat16 g_qlo[Mv*DM];
__device__ __nv_bfloat16 g_khi[Mv*DM];
__device__ __nv_bfloat16 g_klo[Mv*DM];
__device__ __nv_bfloat16 g_vhi[Mv*DM];
__device__ __nv_bfloat16 g_vlo[Mv*DM];

// ---------------------------------------------------------------------------
// helpers
// ---------------------------------------------------------------------------
__global__ void split_kernel(const float* __restrict__ s,
                             __nv_bfloat16* __restrict__ hi,
                             __nv_bfloat16* __restrict__ lo, int n)
{
    int i = blockIdx.x * blockDim.x + threadIdx.x;
    if (i >= n) return;
    float x = s[i];
    __nv_bfloat16 h = __float2bfloat16(x);
    hi[i] = h;
    lo[i] = __float2bfloat16(x - __bfloat162float(h));
}

__global__ void rope_table_kernel() {
    int idx = blockIdx.x * blockDim.x + threadIdx.x;
    if (idx >= Sv * 32) return;
    int pos = idx >> 5;
    int i   = idx & 31;
    double inv = pow(10000.0, -(double)i / 32.0);
    double ang = (double)pos * inv;
    g_cos[idx] = (float)cos(ang);
    g_sin[idx] = (float)sin(ang);
}

// rope + scale + bf16 hi/lo split
__global__ void rope_split_kernel(const float2* __restrict__ src,
                                  __nv_bfloat162* __restrict__ hi,
                                  __nv_bfloat162* __restrict__ lo, float scl)
{
    int idx = blockIdx.x * blockDim.x + threadIdx.x;
    if (idx >= Mv * 512) return;
    int p = idx & 511;
    int i = p & 31;
    int s = (idx >> 9) & (Sv - 1);
    float c  = g_cos[(s << 5) + i];
    float sn = g_sin[(s << 5) + i];
    float2 v = src[idx];
    float2 r = make_float2((v.x * c - v.y * sn) * scl, (v.y * c + v.x * sn) * scl);
    __nv_bfloat162 h2 = __float22bfloat162_rn(r);
    float2 back = __bfloat1622float2(h2);
    hi[idx] = h2;
    lo[idx] = __float22bfloat162_rn(make_float2(r.x - back.x, r.y - back.y));
}

// ---------------------------------------------------------------------------
// MMA / async-copy primitives
// ---------------------------------------------------------------------------
__device__ __forceinline__ void ldmx4(unsigned& r0, unsigned& r1,
                                      unsigned& r2, unsigned& r3, unsigned a) {
    asm volatile("ldmatrix.sync.aligned.m8n8.x4.shared.b16 {%0,%1,%2,%3}, [%4];"
        : "=r"(r0), "=r"(r1), "=r"(r2), "=r"(r3) : "r"(a));
}
__device__ __forceinline__ void ldmx4t(unsigned& r0, unsigned& r1,
                                       unsigned& r2, unsigned& r3, unsigned a) {
    asm volatile("ldmatrix.sync.aligned.m8n8.x4.trans.shared.b16 {%0,%1,%2,%3}, [%4];"
        : "=r"(r0), "=r"(r1), "=r"(r2), "=r"(r3) : "r"(a));
}
__device__ __forceinline__ void mma16816(float* c, const unsigned* a, const unsigned* b) {
    asm volatile(
        "mma.sync.aligned.m16n8k16.row.col.f32.bf16.bf16.f32 "
        "{%0,%1,%2,%3}, {%4,%5,%6,%7}, {%8,%9}, {%0,%1,%2,%3};"
        : "+f"(c[0]), "+f"(c[1]), "+f"(c[2]), "+f"(c[3])
        : "r"(a[0]), "r"(a[1]), "r"(a[2]), "r"(a[3]), "r"(b[0]), "r"(b[1]));
}
__device__ __forceinline__ void cpa16(void* smem, const void* g) {
    unsigned s = (unsigned)__cvta_generic_to_shared(smem);
    asm volatile("cp.async.cg.shared.global [%0], [%1], 16;" :: "r"(s), "l"(g));
}
__device__ __forceinline__ void cp_commit() { asm volatile("cp.async.commit_group;"); }
template<int N> __device__ __forceinline__ void cp_wait() {
    asm volatile("cp.async.wait_group %0;" :: "n"(N));
}
__device__ __forceinline__ float ex2f(float x) {
    float y;
    asm("ex2.approx.ftz.f32 %0, %1;" : "=f"(y) : "f"(x));
    return y;
}

// ---------------------------------------------------------------------------
// Tensor-core GEMM with bf16x3 split (unchanged — known-good)
// ---------------------------------------------------------------------------
#define APAD 40
#define BPAD 72

__global__ __launch_bounds__(128) void gemm_bf16x3(
    const __nv_bfloat16* __restrict__ Ahi, const __nv_bfloat16* __restrict__ Alo,
    const __nv_bfloat16* __restrict__ Bhi, const __nv_bfloat16* __restrict__ Blo,
    const float* __restrict__ bias, float* __restrict__ C,
    int M, int N, int K)
{
    __shared__ __nv_bfloat16 As[2][128][APAD];
    __shared__ __nv_bfloat16 Bs[2][32][BPAD];

    int tid  = threadIdx.x;
    int lane = tid & 31;
    int warp = tid >> 5;
    int wm = warp >> 1, wn = warp & 1;
    int bm = blockIdx.y << 7;
    int bn = blockIdx.x << 6;

    float acc[4][4][4];
#pragma unroll
    for (int i = 0; i < 4; i++)
#pragma unroll
        for (int j = 0; j < 4; j++)
#pragma unroll
            for (int e = 0; e < 4; e++) acc[i][j][e] = 0.f;

    int u0k = tid >> 3, u0n = (tid & 7) << 3;
    int u1k = (tid + 128) >> 3, u1n = ((tid + 128) & 7) << 3;

    for (int k0 = 0; k0 < K; k0 += 32) {
        uint4 ah[4], al[4], bh[2], bl[2];
        const __nv_bfloat16* Ahp = Ahi + (size_t)(bm + tid) * K + k0;
        const __nv_bfloat16* Alp = Alo + (size_t)(bm + tid) * K + k0;
#pragma unroll
        for (int i = 0; i < 4; i++) {
            ah[i] = *(const uint4*)(Ahp + i * 8);
            al[i] = *(const uint4*)(Alp + i * 8);
        }
        bh[0] = *(const uint4*)(Bhi + (size_t)(k0 + u0k) * N + bn + u0n);
        bh[1] = *(const uint4*)(Bhi + (size_t)(k0 + u1k) * N + bn + u1n);
        bl[0] = *(const uint4*)(Blo + (size_t)(k0 + u0k) * N + bn + u0n);
        bl[1] = *(const uint4*)(Blo + (size_t)(k0 + u1k) * N + bn + u1n);

        __syncthreads();
#pragma unroll
        for (int i = 0; i < 4; i++) {
            *(uint4*)&As[0][tid][i * 8] = ah[i];
            *(uint4*)&As[1][tid][i * 8] = al[i];
        }
        *(uint4*)&Bs[0][u0k][u0n] = bh[0];
        *(uint4*)&Bs[0][u1k][u1n] = bh[1];
        *(uint4*)&Bs[1][u0k][u0n] = bl[0];
        *(uint4*)&Bs[1][u1k][u1n] = bl[1];
        __syncthreads();

#pragma unroll
        for (int ks = 0; ks < 2; ks++) {
            int k16 = ks << 4;
            unsigned Af[2][4][4];
            int ar = (lane & 15);
            int ac = k16 + ((lane >> 4) << 3);
#pragma unroll
            for (int mt = 0; mt < 4; mt++) {
                int m0 = wm * 64 + mt * 16;
                unsigned a0 = (unsigned)__cvta_generic_to_shared(&As[0][m0 + ar][ac]);
                ldmx4(Af[0][mt][0], Af[0][mt][1], Af[0][mt][2], Af[0][mt][3], a0);
                unsigned a1 = (unsigned)__cvta_generic_to_shared(&As[1][m0 + ar][ac]);
                ldmx4(Af[1][mt][0], Af[1][mt][1], Af[1][mt][2], Af[1][mt][3], a1);
            }
            unsigned Bf[2][4][2];
            int bkr = k16 + (lane & 7) + (lane & 8);
#pragma unroll
            for (int p = 0; p < 2; p++) {
                int n0 = wn * 32 + p * 16 + (((lane >> 4) & 1) << 3);
                unsigned r0, r1, r2, r3;
                unsigned ad = (unsigned)__cvta_generic_to_shared(&Bs[0][bkr][n0]);
                ldmx4t(r0, r1, r2, r3, ad);
                Bf[0][p * 2][0] = r0; Bf[0][p * 2][1] = r1;
                Bf[0][p * 2 + 1][0] = r2; Bf[0][p * 2 + 1][1] = r3;
                ad = (unsigned)__cvta_generic_to_shared(&Bs[1][bkr][n0]);
                ldmx4t(r0, r1, r2, r3, ad);
                Bf[1][p * 2][0] = r0; Bf[1][p * 2][1] = r1;
                Bf[1][p * 2 + 1][0] = r2; Bf[1][p * 2 + 1][1] = r3;
            }
#pragma unroll
            for (int mt = 0; mt < 4; mt++)
#pragma unroll
                for (int nt = 0; nt < 4; nt++) {
                    mma16816(acc[mt][nt], Af[0][mt], Bf[0][nt]);
                    mma16816(acc[mt][nt], Af[0][mt], Bf[1][nt]);
                    mma16816(acc[mt][nt], Af[1][mt], Bf[0][nt]);
                }
        }
    }

    int gid = lane >> 2, tq = lane & 3;
#pragma unroll
    for (int mt = 0; mt < 4; mt++) {
        int row = bm + wm * 64 + mt * 16 + gid;
#pragma unroll
        for (int nt = 0; nt < 4; nt++) {
            int col = bn + wn * 32 + nt * 8 + tq * 2;
            float b0 = bias[col], b1 = bias[col + 1];
            *(float2*)&C[(size_t)row * N + col] =
                make_float2(acc[mt][nt][0] + b0, acc[mt][nt][1] + b1);
            *(float2*)&C[(size_t)(row + 8) * N + col] =
                make_float2(acc[mt][nt][2] + b0, acc[mt][nt][3] + b1);
        }
    }
}

// ---------------------------------------------------------------------------
// Tensor-core flash attention, causal, bf16x3, cp.async double-buffered K/V,
// NO-RESCALE softmax: Q pre-scaled by 0.125*log2(e); P = exp2(S) directly;
// row sum accumulated thread-locally, reduced once in the epilogue.
// 128 threads (4 warps). Q tile 64 rows (16/warp), KV tile 64, D=64.
// qt reversed (heavy CTAs first) for better tail scheduling.
// ---------------------------------------------------------------------------
#define KPAD 72
#define BUF_ELEMS (64*KPAD)      // 4608
#define STG_ELEMS (4*BUF_ELEMS)  // 18432
#define FLASH_SMEM (2*STG_ELEMS*sizeof(__nv_bfloat16))  // 73728

__global__ __launch_bounds__(128) void flash_mma(
    const __nv_bfloat16* __restrict__ qhi, const __nv_bfloat16* __restrict__ qlo,
    const __nv_bfloat16* __restrict__ khi, const __nv_bfloat16* __restrict__ klo,
    const __nv_bfloat16* __restrict__ vhi, const __nv_bfloat16* __restrict__ vlo,
    __nv_bfloat16* __restrict__ yhi, __nv_bfloat16* __restrict__ ylo)
{
    extern __shared__ __nv_bfloat16 smx[];

    int tid = threadIdx.x, lane = tid & 31, warp = tid >> 5;
    int qt = (int)gridDim.x - 1 - (int)blockIdx.x;   // heavy tiles first
    int h = blockIdx.y, b = blockIdx.z;
    int qg0 = qt * 64;
    size_t base = ((size_t)b * Sv) * DM + h * Dv;
    int gid = lane >> 2, tig = lane & 3;

    const __nv_bfloat16* srcs[4] = {khi, klo, vhi, vlo};

    // ---- prefetch Q tile into stage 1 ----
    {
        const __nv_bfloat16* qs[2] = {qhi, qlo};
#pragma unroll
        for (int p = 0; p < 8; p++) {
            int e = p * 128 + tid;
            int bq = e >> 9;
            int idx = e & 511;
            int row = idx >> 3, c = idx & 7;
            cpa16(&smx[STG_ELEMS + bq * BUF_ELEMS + row * KPAD + c * 8],
                  qs[bq] + base + (size_t)(qg0 + row) * DM + c * 8);
        }
        cp_commit();
    }
    // ---- prefetch KV tile 0 into stage 0 ----
#pragma unroll
    for (int p = 0; p < 16; p++) {
        int buf = p >> 2;
        int idx = ((p & 3) << 7) + tid;
        int row = idx >> 3, c = idx & 7;
        cpa16(&smx[buf * BUF_ELEMS + row * KPAD + c * 8],
              srcs[buf] + base + (size_t)row * DM + c * 8);
    }
    cp_commit();

    cp_wait<1>();
    __syncthreads();

    unsigned Qf[2][4][4];
    {
        int r = warp * 16 + (lane & 15);
        int c = (lane >> 4) << 3;
#pragma unroll
        for (int kt = 0; kt < 4; kt++) {
            unsigned a = (unsigned)__cvta_generic_to_shared(
                &smx[STG_ELEMS + r * KPAD + kt * 16 + c]);
            ldmx4(Qf[0][kt][0], Qf[0][kt][1], Qf[0][kt][2], Qf[0][kt][3], a);
            a = (unsigned)__cvta_generic_to_shared(
                &smx[STG_ELEMS + BUF_ELEMS + r * KPAD + kt * 16 + c]);
            ldmx4(Qf[1][kt][0], Qf[1][kt][1], Qf[1][kt][2], Qf[1][kt][3], a);
        }
    }
    __syncthreads();

    int krow = (lane & 7) + ((lane >> 4) << 3);
    int kcol = ((lane >> 3) & 1) << 3;
    int vrow = (lane & 7) + (((lane >> 3) & 1) << 3);
    int vcol = (lane >> 4) << 3;

    float acc_o[8][4];
#pragma unroll
    for (int i = 0; i < 8; i++)
#pragma unroll
        for (int e = 0; e < 4; e++) acc_o[i][e] = 0.f;
    float lsum0 = 0.f, lsum1 = 0.f;
    int row0g = qg0 + warp * 16 + gid;        // this thread's q rows (and +8)

    int n = qt + 1;
    for (int j = 0; j < n; j++) {
        int s = j & 1;
        if (j + 1 < n) {
            int sb = (1 - s) * STG_ELEMS;
            size_t grow = base + (size_t)(j + 1) * 64 * DM;
#pragma unroll
            for (int p = 0; p < 16; p++) {
                int buf = p >> 2;
                int idx = ((p & 3) << 7) + tid;
                int row = idx >> 3, c = idx & 7;
                cpa16(&smx[sb + buf * BUF_ELEMS + row * KPAD + c * 8],
                      srcs[buf] + grow + (size_t)row * DM + c * 8);
            }
            cp_commit();
            cp_wait<1>();
        } else {
            cp_wait<0>();
        }
        __syncthreads();

        __nv_bfloat16* Kh_ = smx + s * STG_ELEMS;
        __nv_bfloat16* Kl_ = Kh_ + BUF_ELEMS;
        __nv_bfloat16* Vh_ = Kh_ + 2 * BUF_ELEMS;
        __nv_bfloat16* Vl_ = Kh_ + 3 * BUF_ELEMS;

        // ---- S = Q K^T (3-term split; Q carries 0.125*log2e) ----
        float sc[8][4];
#pragma unroll
        for (int i = 0; i < 8; i++)
#pragma unroll
            for (int e = 0; e < 4; e++) sc[i][e] = 0.f;

#pragma unroll
        for (int kt = 0; kt < 4; kt++) {
            unsigned Kf[2][8][2];
#pragma unroll
            for (int ng = 0; ng < 4; ng++) {
                unsigned r0, r1, r2, r3;
                unsigned a = (unsigned)__cvta_generic_to_shared(
                    &Kh_[(ng * 16 + krow) * KPAD + kt * 16 + kcol]);
                ldmx4(r0, r1, r2, r3, a);
                Kf[0][ng * 2][0] = r0; Kf[0][ng * 2][1] = r1;
                Kf[0][ng * 2 + 1][0] = r2; Kf[0][ng * 2 + 1][1] = r3;
                a = (unsigned)__cvta_generic_to_shared(
                    &Kl_[(ng * 16 + krow) * KPAD + kt * 16 + kcol]);
                ldmx4(r0, r1, r2, r3, a);
                Kf[1][ng * 2][0] = r0; Kf[1][ng * 2][1] = r1;
                Kf[1][ng * 2 + 1][0] = r2; Kf[1][ng * 2 + 1][1] = r3;
            }
#pragma unroll
            for (int nt = 0; nt < 8; nt++) {
                mma16816(sc[nt], Qf[0][kt], Kf[0][nt]);
                mma16816(sc[nt], Qf[0][kt], Kf[1][nt]);
                mma16816(sc[nt], Qf[1][kt], Kf[0][nt]);
            }
        }

        // ---- P = exp2(S) with causal zeroing; accumulate row sums ----
        if (j == qt) {
#pragma unroll
            for (int nt = 0; nt < 8; nt++) {
#pragma unroll
                for (int e = 0; e < 4; e++) {
                    int col = qg0 + nt * 8 + 2 * tig + (e & 1);
                    int row = row0g + ((e >> 1) << 3);
                    sc[nt][e] = (col > row) ? 0.f : ex2f(sc[nt][e]);
                }
                lsum0 += sc[nt][0] + sc[nt][1];
                lsum1 += sc[nt][2] + sc[nt][3];
            }
        } else {
#pragma unroll
            for (int nt = 0; nt < 8; nt++) {
                sc[nt][0] = ex2f(sc[nt][0]);
                sc[nt][1] = ex2f(sc[nt][1]);
                sc[nt][2] = ex2f(sc[nt][2]);
                sc[nt][3] = ex2f(sc[nt][3]);
                lsum0 += sc[nt][0] + sc[nt][1];
                lsum1 += sc[nt][2] + sc[nt][3];
            }
        }

        // ---- O += P V (3-term split; P split in-register) ----
#pragma unroll
        for (int kt = 0; kt < 4; kt++) {
            unsigned Ph[4], Pl[4];
#pragma unroll
            for (int half = 0; half < 2; half++) {
                int nt = 2 * kt + half;
                float2 p0 = make_float2(sc[nt][0], sc[nt][1]);
                float2 p1 = make_float2(sc[nt][2], sc[nt][3]);
                __nv_bfloat162 h0 = __float22bfloat162_rn(p0);
                __nv_bfloat162 h1 = __float22bfloat162_rn(p1);
                float2 b0 = __bfloat1622float2(h0);
                float2 b1 = __bfloat1622float2(h1);
                __nv_bfloat162 l0 = __float22bfloat162_rn(
                    make_float2(p0.x - b0.x, p0.y - b0.y));
                __nv_bfloat162 l1 = __float22bfloat162_rn(
                    make_float2(p1.x - b1.x, p1.y - b1.y));
                Ph[half * 2]     = *(unsigned*)&h0;
                Ph[half * 2 + 1] = *(unsigned*)&h1;
                Pl[half * 2]     = *(unsigned*)&l0;
                Pl[half * 2 + 1] = *(unsigned*)&l1;
            }
            unsigned Vf[2][8][2];
#pragma unroll
            for (int dg = 0; dg < 4; dg++) {
                unsigned r0, r1, r2, r3;
                unsigned a = (unsigned)__cvta_generic_to_shared(
                    &Vh_[(kt * 16 + vrow) * KPAD + dg * 16 + vcol]);
                ldmx4t(r0, r1, r2, r3, a);
                Vf[0][dg * 2][0] = r0; Vf[0][dg * 2][1] = r1;
                Vf[0][dg * 2 + 1][0] = r2; Vf[0][dg * 2 + 1][1] = r3;
                a = (unsigned)__cvta_generic_to_shared(
                    &Vl_[(kt * 16 + vrow) * KPAD + dg * 16 + vcol]);
                ldmx4t(r0, r1, r2, r3, a);
                Vf[1][dg * 2][0] = r0; Vf[1][dg * 2][1] = r1;
                Vf[1][dg * 2 + 1][0] = r2; Vf[1][dg * 2 + 1][1] = r3;
            }
#pragma unroll
            for (int dnt = 0; dnt < 8; dnt++) {
                mma16816(acc_o[dnt], Ph, Vf[0][dnt]);
                mma16816(acc_o[dnt], Pl, Vf[0][dnt]);
                mma16816(acc_o[dnt], Ph, Vf[1][dnt]);
            }
        }
        __syncthreads();
    }

    // ---- epilogue: quad-reduce row sums, normalize, split, store ----
    lsum0 += __shfl_xor_sync(0xffffffffu, lsum0, 1);
    lsum0 += __shfl_xor_sync(0xffffffffu, lsum0, 2);
    lsum1 += __shfl_xor_sync(0xffffffffu, lsum1, 1);
    lsum1 += __shfl_xor_sync(0xffffffffu, lsum1, 2);
    float inv0 = 1.f / lsum0, inv1 = 1.f / lsum1;
    size_t o0 = ((size_t)b * Sv + row0g) * DM + h * Dv;
    size_t o1 = o0 + (size_t)8 * DM;
#pragma unroll
    for (int dnt = 0; dnt < 8; dnt++) {
        int col = dnt * 8 + 2 * tig;
        float2 v0 = make_float2(acc_o[dnt][0] * inv0, acc_o[dnt][1] * inv0);
        float2 v1 = make_float2(acc_o[dnt][2] * inv1, acc_o[dnt][3] * inv1);
        __nv_bfloat162 h0 = __float22bfloat162_rn(v0);
        __nv_bfloat162 h1 = __float22bfloat162_rn(v1);
        float2 b0 = __bfloat1622float2(h0);
        float2 b1 = __bfloat1622float2(h1);
        __nv_bfloat162 l0 = __float22bfloat162_rn(make_float2(v0.x - b0.x, v0.y - b0.y));
        __nv_bfloat162 l1 = __float22bfloat162_rn(make_float2(v1.x - b1.x, v1.y - b1.y));
        *(__nv_bfloat162*)&yhi[o0 + col] = h0;
        *(__nv_bfloat162*)&ylo[o0 + col] = l0;
        *(__nv_bfloat162*)&yhi[o1 + col] = h1;
        *(__nv_bfloat162*)&ylo[o1 + col] = l1;
    }
}

// ---------------------------------------------------------------------------
// kernel_launch
// ---------------------------------------------------------------------------
extern "C" void kernel_launch(void* const* d_in, const int* in_sizes, int n_in,
                              void* d_out, int out_size)
{
    const float* x  = (const float*)d_in[0];
    const float* Wq = (const float*)d_in[1];
    const float* bq = (const float*)d_in[2];
    const float* Wk = (const float*)d_in[3];
    const float* bk = (const float*)d_in[4];
    const float* Wv = (const float*)d_in[5];
    const float* bv = (const float*)d_in[6];
    const float* Wo = (const float*)d_in[7];
    const float* bo = (const float*)d_in[8];
    float* out = (float*)d_out;

    float *qp, *kp, *vp;
    cudaGetSymbolAddress((void**)&qp, g_q);
    cudaGetSymbolAddress((void**)&kp, g_k);
    cudaGetSymbolAddress((void**)&vp, g_v);
    __nv_bfloat16 *xhi, *xlo, *yhi, *ylo, *whi, *wlo;
    __nv_bfloat16 *qhi, *qlo, *khi, *klo, *vhi, *vlo;
    cudaGetSymbolAddress((void**)&xhi, g_xhi);
    cudaGetSymbolAddress((void**)&xlo, g_xlo);
    cudaGetSymbolAddress((void**)&yhi, g_yhi);
    cudaGetSymbolAddress((void**)&ylo, g_ylo);
    cudaGetSymbolAddress((void**)&whi, g_whi);
    cudaGetSymbolAddress((void**)&wlo, g_wlo);
    cudaGetSymbolAddress((void**)&qhi, g_qhi);
    cudaGetSymbolAddress((void**)&qlo, g_qlo);
    cudaGetSymbolAddress((void**)&khi, g_khi);
    cudaGetSymbolAddress((void**)&klo, g_klo);
    cudaGetSymbolAddress((void**)&vhi, g_vhi);
    cudaGetSymbolAddress((void**)&vlo, g_vlo);

    cudaFuncSetAttribute(flash_mma,
                         cudaFuncAttributeMaxDynamicSharedMemorySize,
                         (int)FLASH_SMEM);

    const int NX = Mv * DM;
    const int NW = DM * DM;

    rope_table_kernel<<<(Sv * 32 + 255) / 256, 256>>>();

    split_kernel<<<(NX + 255) / 256, 256>>>(x, xhi, xlo, NX);
    split_kernel<<<(NW + 255) / 256, 256>>>(Wq, whi + 0 * NW, wlo + 0 * NW, NW);
    split_kernel<<<(NW + 255) / 256, 256>>>(Wk, whi + 1 * NW, wlo + 1 * NW, NW);
    split_kernel<<<(NW + 255) / 256, 256>>>(Wv, whi + 2 * NW, wlo + 2 * NW, NW);
    split_kernel<<<(NW + 255) / 256, 256>>>(Wo, whi + 3 * NW, wlo + 3 * NW, NW);

    dim3 gg(DM / 64, Mv / 128);
    gemm_bf16x3<<<gg, 128>>>(xhi, xlo, whi + 0 * NW, wlo + 0 * NW, bq, qp, Mv, DM, DM);
    gemm_bf16x3<<<gg, 128>>>(xhi, xlo, whi + 1 * NW, wlo + 1 * NW, bk, kp, Mv, DM, DM);
    gemm_bf16x3<<<gg, 128>>>(xhi, xlo, whi + 2 * NW, wlo + 2 * NW, bv, vp, Mv, DM, DM);

    // Q carries 0.125 * log2(e) so softmax is exp2(S); K unscaled
    const float QSCL = 0.125f * 1.4426950408889634f;
    int nrope = Mv * 512;
    rope_split_kernel<<<(nrope + 255) / 256, 256>>>(
        (const float2*)qp, (__nv_bfloat162*)qhi, (__nv_bfloat162*)qlo, QSCL);
    rope_split_kernel<<<(nrope + 255) / 256, 256>>>(
        (const float2*)kp, (__nv_bfloat162*)khi, (__nv_bfloat162*)klo, 1.0f);
    split_kernel<<<(NX + 255) / 256, 256>>>(vp, vhi, vlo, NX);

    dim3 att_grid(Sv / 64, Hv, Bv);
    flash_mma<<<att_grid, 128, FLASH_SMEM>>>(qhi, qlo, khi, klo, vhi, vlo, yhi, ylo);

    gemm_bf16x3<<<gg, 128>>>(yhi, ylo, whi + 3 * NW, wlo + 3 * NW, bo, out, Mv, DM, DM);
}

// round 8
// speedup vs baseline: 3.6633x; 1.0598x over previous
#include <cuda_runtime.h>
#include <cuda_bf16.h>
#include <cuda_fp16.h>
#include <stdint.h>
#include <cstdint>
#include <math.h>

#define Bv 4
#define Sv 2048
#define Hv 16
#define Dv 64
#define DM 1024
#define Mv (Bv*Sv)   // 8192

// ---------------------------------------------------------------------------
// Scratch (allocation-free rule: __device__ globals)
// ---------------------------------------------------------------------------
__device__ float g_q[Mv*DM];
__device__ float g_k[Mv*DM];
__device__ float g_v[Mv*DM];
__device__ float g_cos[Sv*32];
__device__ float g_sin[Sv*32];

__device__ __nv_bfloat16 g_xhi[Mv*DM];
__device__ __nv_bfloat16 g_xlo[Mv*DM];
__device__ __nv_bfloat16 g_yhi[Mv*DM];
__device__ __nv_bfloat16 g_ylo[Mv*DM];
__device__ __nv_bfloat16 g_whi[4*DM*DM];
__device__ __nv_bfloat16 g_wlo[4*DM*DM];
__device__ __half g_qh [Mv*DM];
__device__ __half g_khi[Mv*DM];
__device__ __half g_klo[Mv*DM];
__device__ __half g_vhi[Mv*DM];
__device__ __half g_vlo[Mv*DM];

// ---------------------------------------------------------------------------
// elementwise prep kernels
// ---------------------------------------------------------------------------
__global__ void split_kernel(const float* __restrict__ s,
                             __nv_bfloat16* __restrict__ hi,
                             __nv_bfloat16* __restrict__ lo, int n)
{
    int i = blockIdx.x * blockDim.x + threadIdx.x;
    if (i >= n) return;
    float x = s[i];
    __nv_bfloat16 h = __float2bfloat16(x);
    hi[i] = h;
    lo[i] = __float2bfloat16(x - __bfloat162float(h));
}

// all four weight matrices in one launch (keeps launch #6 = gemm for ncu)
__global__ void split4_kernel(const float* __restrict__ s0, const float* __restrict__ s1,
                              const float* __restrict__ s2, const float* __restrict__ s3,
                              __nv_bfloat16* __restrict__ hi,
                              __nv_bfloat16* __restrict__ lo, int n)
{
    int i = blockIdx.x * blockDim.x + threadIdx.x;
    if (i >= 4 * n) return;
    int w = i / n, r = i - w * n;
    const float* src = (w == 0) ? s0 : (w == 1) ? s1 : (w == 2) ? s2 : s3;
    float x = src[r];
    __nv_bfloat16 h = __float2bfloat16(x);
    hi[i] = h;
    lo[i] = __float2bfloat16(x - __bfloat162float(h));
}

__global__ void rope_table_kernel() {
    int idx = blockIdx.x * blockDim.x + threadIdx.x;
    if (idx >= Sv * 32) return;
    int pos = idx >> 5;
    int i   = idx & 31;
    double inv = pow(10000.0, -(double)i / 32.0);
    double ang = (double)pos * inv;
    g_cos[idx] = (float)cos(ang);
    g_sin[idx] = (float)sin(ang);
}

// rope + scale -> single fp16 (for Q)
__global__ void rope_half_kernel(const float2* __restrict__ src,
                                 __half2* __restrict__ out, float scl)
{
    int idx = blockIdx.x * blockDim.x + threadIdx.x;
    if (idx >= Mv * 512) return;
    int p = idx & 511;
    int i = p & 31;
    int s = (idx >> 9) & (Sv - 1);
    float c  = g_cos[(s << 5) + i];
    float sn = g_sin[(s << 5) + i];
    float2 v = src[idx];
    out[idx] = __floats2half2_rn((v.x * c - v.y * sn) * scl,
                                 (v.y * c + v.x * sn) * scl);
}

// rope -> fp16 hi/lo (for K)
__global__ void rope_split_half_kernel(const float2* __restrict__ src,
                                       __half2* __restrict__ hi,
                                       __half2* __restrict__ lo)
{
    int idx = blockIdx.x * blockDim.x + threadIdx.x;
    if (idx >= Mv * 512) return;
    int p = idx & 511;
    int i = p & 31;
    int s = (idx >> 9) & (Sv - 1);
    float c  = g_cos[(s << 5) + i];
    float sn = g_sin[(s << 5) + i];
    float2 v = src[idx];
    float2 r = make_float2(v.x * c - v.y * sn, v.y * c + v.x * sn);
    __half2 h2 = __floats2half2_rn(r.x, r.y);
    float2 back = __half22float2(h2);
    hi[idx] = h2;
    lo[idx] = __floats2half2_rn(r.x - back.x, r.y - back.y);
}

// fp32 -> fp16 hi/lo (for V)
__global__ void split_half_kernel(const float* __restrict__ s,
                                  __half* __restrict__ hi,
                                  __half* __restrict__ lo, int n)
{
    int i = blockIdx.x * blockDim.x + threadIdx.x;
    if (i >= n) return;
    float x = s[i];
    __half h = __float2half_rn(x);
    hi[i] = h;
    lo[i] = __float2half_rn(x - __half2float(h));
}

// ---------------------------------------------------------------------------
// MMA / async-copy primitives
// ---------------------------------------------------------------------------
__device__ __forceinline__ void ldmx4(unsigned& r0, unsigned& r1,
                                      unsigned& r2, unsigned& r3, unsigned a) {
    asm volatile("ldmatrix.sync.aligned.m8n8.x4.shared.b16 {%0,%1,%2,%3}, [%4];"
        : "=r"(r0), "=r"(r1), "=r"(r2), "=r"(r3) : "r"(a));
}
__device__ __forceinline__ void ldmx4t(unsigned& r0, unsigned& r1,
                                       unsigned& r2, unsigned& r3, unsigned a) {
    asm volatile("ldmatrix.sync.aligned.m8n8.x4.trans.shared.b16 {%0,%1,%2,%3}, [%4];"
        : "=r"(r0), "=r"(r1), "=r"(r2), "=r"(r3) : "r"(a));
}
__device__ __forceinline__ void mma16816(float* c, const unsigned* a, const unsigned* b) {
    asm volatile(
        "mma.sync.aligned.m16n8k16.row.col.f32.bf16.bf16.f32 "
        "{%0,%1,%2,%3}, {%4,%5,%6,%7}, {%8,%9}, {%0,%1,%2,%3};"
        : "+f"(c[0]), "+f"(c[1]), "+f"(c[2]), "+f"(c[3])
        : "r"(a[0]), "r"(a[1]), "r"(a[2]), "r"(a[3]), "r"(b[0]), "r"(b[1]));
}
__device__ __forceinline__ void mma16816h(float* c, const unsigned* a, const unsigned* b) {
    asm volatile(
        "mma.sync.aligned.m16n8k16.row.col.f32.f16.f16.f32 "
        "{%0,%1,%2,%3}, {%4,%5,%6,%7}, {%8,%9}, {%0,%1,%2,%3};"
        : "+f"(c[0]), "+f"(c[1]), "+f"(c[2]), "+f"(c[3])
        : "r"(a[0]), "r"(a[1]), "r"(a[2]), "r"(a[3]), "r"(b[0]), "r"(b[1]));
}
__device__ __forceinline__ void cpa16(void* smem, const void* g) {
    unsigned s = (unsigned)__cvta_generic_to_shared(smem);
    asm volatile("cp.async.cg.shared.global [%0], [%1], 16;" :: "r"(s), "l"(g));
}
__device__ __forceinline__ void cp_commit() { asm volatile("cp.async.commit_group;"); }
template<int N> __device__ __forceinline__ void cp_wait() {
    asm volatile("cp.async.wait_group %0;" :: "n"(N));
}
__device__ __forceinline__ float ex2f(float x) {
    float y;
    asm("ex2.approx.ftz.f32 %0, %1;" : "=f"(y) : "f"(x));
    return y;
}

// ---------------------------------------------------------------------------
// Tensor-core GEMM with bf16x3 split (unchanged — known-good)
// ---------------------------------------------------------------------------
#define APAD 40
#define BPAD 72

__global__ __launch_bounds__(128) void gemm_bf16x3(
    const __nv_bfloat16* __restrict__ Ahi, const __nv_bfloat16* __restrict__ Alo,
    const __nv_bfloat16* __restrict__ Bhi, const __nv_bfloat16* __restrict__ Blo,
    const float* __restrict__ bias, float* __restrict__ C,
    int M, int N, int K)
{
    __shared__ __nv_bfloat16 As[2][128][APAD];
    __shared__ __nv_bfloat16 Bs[2][32][BPAD];

    int tid  = threadIdx.x;
    int lane = tid & 31;
    int warp = tid >> 5;
    int wm = warp >> 1, wn = warp & 1;
    int bm = blockIdx.y << 7;
    int bn = blockIdx.x << 6;

    float acc[4][4][4];
#pragma unroll
    for (int i = 0; i < 4; i++)
#pragma unroll
        for (int j = 0; j < 4; j++)
#pragma unroll
            for (int e = 0; e < 4; e++) acc[i][j][e] = 0.f;

    int u0k = tid >> 3, u0n = (tid & 7) << 3;
    int u1k = (tid + 128) >> 3, u1n = ((tid + 128) & 7) << 3;

    for (int k0 = 0; k0 < K; k0 += 32) {
        uint4 ah[4], al[4], bh[2], bl[2];
        const __nv_bfloat16* Ahp = Ahi + (size_t)(bm + tid) * K + k0;
        const __nv_bfloat16* Alp = Alo + (size_t)(bm + tid) * K + k0;
#pragma unroll
        for (int i = 0; i < 4; i++) {
            ah[i] = *(const uint4*)(Ahp + i * 8);
            al[i] = *(const uint4*)(Alp + i * 8);
        }
        bh[0] = *(const uint4*)(Bhi + (size_t)(k0 + u0k) * N + bn + u0n);
        bh[1] = *(const uint4*)(Bhi + (size_t)(k0 + u1k) * N + bn + u1n);
        bl[0] = *(const uint4*)(Blo + (size_t)(k0 + u0k) * N + bn + u0n);
        bl[1] = *(const uint4*)(Blo + (size_t)(k0 + u1k) * N + bn + u1n);

        __syncthreads();
#pragma unroll
        for (int i = 0; i < 4; i++) {
            *(uint4*)&As[0][tid][i * 8] = ah[i];
            *(uint4*)&As[1][tid][i * 8] = al[i];
        }
        *(uint4*)&Bs[0][u0k][u0n] = bh[0];
        *(uint4*)&Bs[0][u1k][u1n] = bh[1];
        *(uint4*)&Bs[1][u0k][u0n] = bl[0];
        *(uint4*)&Bs[1][u1k][u1n] = bl[1];
        __syncthreads();

#pragma unroll
        for (int ks = 0; ks < 2; ks++) {
            int k16 = ks << 4;
            unsigned Af[2][4][4];
            int ar = (lane & 15);
            int ac = k16 + ((lane >> 4) << 3);
#pragma unroll
            for (int mt = 0; mt < 4; mt++) {
                int m0 = wm * 64 + mt * 16;
                unsigned a0 = (unsigned)__cvta_generic_to_shared(&As[0][m0 + ar][ac]);
                ldmx4(Af[0][mt][0], Af[0][mt][1], Af[0][mt][2], Af[0][mt][3], a0);
                unsigned a1 = (unsigned)__cvta_generic_to_shared(&As[1][m0 + ar][ac]);
                ldmx4(Af[1][mt][0], Af[1][mt][1], Af[1][mt][2], Af[1][mt][3], a1);
            }
            unsigned Bf[2][4][2];
            int bkr = k16 + (lane & 7) + (lane & 8);
#pragma unroll
            for (int p = 0; p < 2; p++) {
                int n0 = wn * 32 + p * 16 + (((lane >> 4) & 1) << 3);
                unsigned r0, r1, r2, r3;
                unsigned ad = (unsigned)__cvta_generic_to_shared(&Bs[0][bkr][n0]);
                ldmx4t(r0, r1, r2, r3, ad);
                Bf[0][p * 2][0] = r0; Bf[0][p * 2][1] = r1;
                Bf[0][p * 2 + 1][0] = r2; Bf[0][p * 2 + 1][1] = r3;
                ad = (unsigned)__cvta_generic_to_shared(&Bs[1][bkr][n0]);
                ldmx4t(r0, r1, r2, r3, ad);
                Bf[1][p * 2][0] = r0; Bf[1][p * 2][1] = r1;
                Bf[1][p * 2 + 1][0] = r2; Bf[1][p * 2 + 1][1] = r3;
            }
#pragma unroll
            for (int mt = 0; mt < 4; mt++)
#pragma unroll
                for (int nt = 0; nt < 4; nt++) {
                    mma16816(acc[mt][nt], Af[0][mt], Bf[0][nt]);
                    mma16816(acc[mt][nt], Af[0][mt], Bf[1][nt]);
                    mma16816(acc[mt][nt], Af[1][mt], Bf[0][nt]);
                }
        }
    }

    int gid = lane >> 2, tq = lane & 3;
#pragma unroll
    for (int mt = 0; mt < 4; mt++) {
        int row = bm + wm * 64 + mt * 16 + gid;
#pragma unroll
        for (int nt = 0; nt < 4; nt++) {
            int col = bn + wn * 32 + nt * 8 + tq * 2;
            float b0 = bias[col], b1 = bias[col + 1];
            *(float2*)&C[(size_t)row * N + col] =
                make_float2(acc[mt][nt][0] + b0, acc[mt][nt][1] + b1);
            *(float2*)&C[(size_t)(row + 8) * N + col] =
                make_float2(acc[mt][nt][2] + b0, acc[mt][nt][3] + b1);
        }
    }
}

// ---------------------------------------------------------------------------
// Flash attention, causal, fp16x2 split (Q,P single fp16; K,V fp16 hi/lo),
// cp.async double-buffered K/V, no-rescale exp2 softmax.
// 128 threads (4 warps). Q tile 64 rows (16/warp), KV tile 64, D=64.
// ---------------------------------------------------------------------------
#define KPAD 72
#define BUF_ELEMS (64*KPAD)      // 4608 halves
#define STG_ELEMS (4*BUF_ELEMS)  // 18432
#define FLASH_SMEM (2*STG_ELEMS*sizeof(__half))  // 73728

__global__ __launch_bounds__(128) void flash_mma(
    const __half* __restrict__ qh,
    const __half* __restrict__ khi, const __half* __restrict__ klo,
    const __half* __restrict__ vhi, const __half* __restrict__ vlo,
    __nv_bfloat16* __restrict__ yhi, __nv_bfloat16* __restrict__ ylo)
{
    extern __shared__ __half smx[];

    int tid = threadIdx.x, lane = tid & 31, warp = tid >> 5;
    int qt = (int)gridDim.x - 1 - (int)blockIdx.x;   // heavy tiles first
    int h = blockIdx.y, b = blockIdx.z;
    int qg0 = qt * 64;
    size_t base = ((size_t)b * Sv) * DM + h * Dv;
    int gid = lane >> 2, tig = lane & 3;

    const __half* srcs[4] = {khi, klo, vhi, vlo};

    // ---- prefetch Q tile (single fp16) into stage 1, buffer 0 ----
#pragma unroll
    for (int p = 0; p < 4; p++) {
        int idx = p * 128 + tid;          // 0..511
        int row = idx >> 3, c = idx & 7;
        cpa16(&smx[STG_ELEMS + row * KPAD + c * 8],
              qh + base + (size_t)(qg0 + row) * DM + c * 8);
    }
    cp_commit();
    // ---- prefetch KV tile 0 into stage 0 ----
#pragma unroll
    for (int p = 0; p < 16; p++) {
        int buf = p >> 2;
        int idx = ((p & 3) << 7) + tid;
        int row = idx >> 3, c = idx & 7;
        cpa16(&smx[buf * BUF_ELEMS + row * KPAD + c * 8],
              srcs[buf] + base + (size_t)row * DM + c * 8);
    }
    cp_commit();

    cp_wait<1>();
    __syncthreads();

    unsigned Qf[4][4];
    {
        int r = warp * 16 + (lane & 15);
        int c = (lane >> 4) << 3;
#pragma unroll
        for (int kt = 0; kt < 4; kt++) {
            unsigned a = (unsigned)__cvta_generic_to_shared(
                &smx[STG_ELEMS + r * KPAD + kt * 16 + c]);
            ldmx4(Qf[kt][0], Qf[kt][1], Qf[kt][2], Qf[kt][3], a);
        }
    }
    __syncthreads();   // Q reads done before tile-1 prefetch overwrites stage 1

    int krow = (lane & 7) + ((lane >> 4) << 3);
    int kcol = ((lane >> 3) & 1) << 3;
    int vrow = (lane & 7) + (((lane >> 3) & 1) << 3);
    int vcol = (lane >> 4) << 3;

    float acc_o[8][4];
#pragma unroll
    for (int i = 0; i < 8; i++)
#pragma unroll
        for (int e = 0; e < 4; e++) acc_o[i][e] = 0.f;
    float lsum0 = 0.f, lsum1 = 0.f;
    int row0g = qg0 + warp * 16 + gid;

    int n = qt + 1;
    for (int j = 0; j < n; j++) {
        int s = j & 1;
        if (j + 1 < n) {
            int sb = (1 - s) * STG_ELEMS;
            size_t grow = base + (size_t)(j + 1) * 64 * DM;
#pragma unroll
            for (int p = 0; p < 16; p++) {
                int buf = p >> 2;
                int idx = ((p & 3) << 7) + tid;
                int row = idx >> 3, c = idx & 7;
                cpa16(&smx[sb + buf * BUF_ELEMS + row * KPAD + c * 8],
                      srcs[buf] + grow + (size_t)row * DM + c * 8);
            }
            cp_commit();
            cp_wait<1>();
        } else {
            cp_wait<0>();
        }
        __syncthreads();

        __half* Kh_ = smx + s * STG_ELEMS;
        __half* Kl_ = Kh_ + BUF_ELEMS;
        __half* Vh_ = Kh_ + 2 * BUF_ELEMS;
        __half* Vl_ = Kh_ + 3 * BUF_ELEMS;

        // ---- S = q̂ (Kh + Kl)ᵀ : 2 terms ----
        float sc[8][4];
#pragma unroll
        for (int i = 0; i < 8; i++)
#pragma unroll
            for (int e = 0; e < 4; e++) sc[i][e] = 0.f;

#pragma unroll
        for (int kt = 0; kt < 4; kt++) {
            unsigned Kf[2][8][2];
#pragma unroll
            for (int ng = 0; ng < 4; ng++) {
                unsigned r0, r1, r2, r3;
                unsigned a = (unsigned)__cvta_generic_to_shared(
                    &Kh_[(ng * 16 + krow) * KPAD + kt * 16 + kcol]);
                ldmx4(r0, r1, r2, r3, a);
                Kf[0][ng * 2][0] = r0; Kf[0][ng * 2][1] = r1;
                Kf[0][ng * 2 + 1][0] = r2; Kf[0][ng * 2 + 1][1] = r3;
                a = (unsigned)__cvta_generic_to_shared(
                    &Kl_[(ng * 16 + krow) * KPAD + kt * 16 + kcol]);
                ldmx4(r0, r1, r2, r3, a);
                Kf[1][ng * 2][0] = r0; Kf[1][ng * 2][1] = r1;
                Kf[1][ng * 2 + 1][0] = r2; Kf[1][ng * 2 + 1][1] = r3;
            }
#pragma unroll
            for (int nt = 0; nt < 8; nt++) {
                mma16816h(sc[nt], Qf[kt], Kf[0][nt]);
                mma16816h(sc[nt], Qf[kt], Kf[1][nt]);
            }
        }

        // ---- P = exp2(S), causal zeroing, row-sum accumulation ----
        if (j == qt) {
#pragma unroll
            for (int nt = 0; nt < 8; nt++) {
#pragma unroll
                for (int e = 0; e < 4; e++) {
                    int col = qg0 + nt * 8 + 2 * tig + (e & 1);
                    int row = row0g + ((e >> 1) << 3);
                    sc[nt][e] = (col > row) ? 0.f : ex2f(sc[nt][e]);
                }
                lsum0 += sc[nt][0] + sc[nt][1];
                lsum1 += sc[nt][2] + sc[nt][3];
            }
        } else {
#pragma unroll
            for (int nt = 0; nt < 8; nt++) {
                sc[nt][0] = ex2f(sc[nt][0]);
                sc[nt][1] = ex2f(sc[nt][1]);
                sc[nt][2] = ex2f(sc[nt][2]);
                sc[nt][3] = ex2f(sc[nt][3]);
                lsum0 += sc[nt][0] + sc[nt][1];
                lsum1 += sc[nt][2] + sc[nt][3];
            }
        }

        // ---- O += P̂ (Vh + Vl) : 2 terms, P single fp16 ----
#pragma unroll
        for (int kt = 0; kt < 4; kt++) {
            unsigned Ph[4];
#pragma unroll
            for (int half = 0; half < 2; half++) {
                int nt = 2 * kt + half;
                __half2 h0 = __floats2half2_rn(sc[nt][0], sc[nt][1]);
                __half2 h1 = __floats2half2_rn(sc[nt][2], sc[nt][3]);
                Ph[half * 2]     = *(unsigned*)&h0;
                Ph[half * 2 + 1] = *(unsigned*)&h1;
            }
            unsigned Vf[2][8][2];
#pragma unroll
            for (int dg = 0; dg < 4; dg++) {
                unsigned r0, r1, r2, r3;
                unsigned a = (unsigned)__cvta_generic_to_shared(
                    &Vh_[(kt * 16 + vrow) * KPAD + dg * 16 + vcol]);
                ldmx4t(r0, r1, r2, r3, a);
                Vf[0][dg * 2][0] = r0; Vf[0][dg * 2][1] = r1;
                Vf[0][dg * 2 + 1][0] = r2; Vf[0][dg * 2 + 1][1] = r3;
                a = (unsigned)__cvta_generic_to_shared(
                    &Vl_[(kt * 16 + vrow) * KPAD + dg * 16 + vcol]);
                ldmx4t(r0, r1, r2, r3, a);
                Vf[1][dg * 2][0] = r0; Vf[1][dg * 2][1] = r1;
                Vf[1][dg * 2 + 1][0] = r2; Vf[1][dg * 2 + 1][1] = r3;
            }
#pragma unroll
            for (int dnt = 0; dnt < 8; dnt++) {
                mma16816h(acc_o[dnt], Ph, Vf[0][dnt]);
                mma16816h(acc_o[dnt], Ph, Vf[1][dnt]);
            }
        }
        __syncthreads();
    }

    // ---- epilogue: quad-reduce row sums, normalize, bf16 split, store ----
    lsum0 += __shfl_xor_sync(0xffffffffu, lsum0, 1);
    lsum0 += __shfl_xor_sync(0xffffffffu, lsum0, 2);
    lsum1 += __shfl_xor_sync(0xffffffffu, lsum1, 1);
    lsum1 += __shfl_xor_sync(0xffffffffu, lsum1, 2);
    float inv0 = 1.f / lsum0, inv1 = 1.f / lsum1;
    size_t o0 = ((size_t)b * Sv + row0g) * DM + h * Dv;
    size_t o1 = o0 + (size_t)8 * DM;
#pragma unroll
    for (int dnt = 0; dnt < 8; dnt++) {
        int col = dnt * 8 + 2 * tig;
        float2 v0 = make_float2(acc_o[dnt][0] * inv0, acc_o[dnt][1] * inv0);
        float2 v1 = make_float2(acc_o[dnt][2] * inv1, acc_o[dnt][3] * inv1);
        __nv_bfloat162 h0 = __float22bfloat162_rn(v0);
        __nv_bfloat162 h1 = __float22bfloat162_rn(v1);
        float2 b0 = __bfloat1622float2(h0);
        float2 b1 = __bfloat1622float2(h1);
        __nv_bfloat162 l0 = __float22bfloat162_rn(make_float2(v0.x - b0.x, v0.y - b0.y));
        __nv_bfloat162 l1 = __float22bfloat162_rn(make_float2(v1.x - b1.x, v1.y - b1.y));
        *(__nv_bfloat162*)&yhi[o0 + col] = h0;
        *(__nv_bfloat162*)&ylo[o0 + col] = l0;
        *(__nv_bfloat162*)&yhi[o1 + col] = h1;
        *(__nv_bfloat162*)&ylo[o1 + col] = l1;
    }
}

// ---------------------------------------------------------------------------
// kernel_launch   (order keeps launch #6 = gemm_bf16x3 for the ncu capture)
// ---------------------------------------------------------------------------
extern "C" void kernel_launch(void* const* d_in, const int* in_sizes, int n_in,
                              void* d_out, int out_size)
{
    const float* x  = (const float*)d_in[0];
    const float* Wq = (const float*)d_in[1];
    const float* bq = (const float*)d_in[2];
    const float* Wk = (const float*)d_in[3];
    const float* bk = (const float*)d_in[4];
    const float* Wv = (const float*)d_in[5];
    const float* bv = (const float*)d_in[6];
    const float* Wo = (const float*)d_in[7];
    const float* bo = (const float*)d_in[8];
    float* out = (float*)d_out;

    float *qp, *kp, *vp;
    cudaGetSymbolAddress((void**)&qp, g_q);
    cudaGetSymbolAddress((void**)&kp, g_k);
    cudaGetSymbolAddress((void**)&vp, g_v);
    __nv_bfloat16 *xhi, *xlo, *yhi, *ylo, *whi, *wlo;
    __half *qh, *khi, *klo, *vhi, *vlo;
    cudaGetSymbolAddress((void**)&xhi, g_xhi);
    cudaGetSymbolAddress((void**)&xlo, g_xlo);
    cudaGetSymbolAddress((void**)&yhi, g_yhi);
    cudaGetSymbolAddress((void**)&ylo, g_ylo);
    cudaGetSymbolAddress((void**)&whi, g_whi);
    cudaGetSymbolAddress((void**)&wlo, g_wlo);
    cudaGetSymbolAddress((void**)&qh,  g_qh);
    cudaGetSymbolAddress((void**)&khi, g_khi);
    cudaGetSymbolAddress((void**)&klo, g_klo);
    cudaGetSymbolAddress((void**)&vhi, g_vhi);
    cudaGetSymbolAddress((void**)&vlo, g_vlo);

    cudaFuncSetAttribute(flash_mma,
                         cudaFuncAttributeMaxDynamicSharedMemorySize,
                         (int)FLASH_SMEM);

    const int NX = Mv * DM;
    const int NW = DM * DM;

    // 1: rope tables
    rope_table_kernel<<<(Sv * 32 + 255) / 256, 256>>>();
    // 2: all weight splits in one launch
    split4_kernel<<<(4 * NW + 255) / 256, 256>>>(Wq, Wk, Wv, Wo, whi, wlo, NW);
    // 3: x split
    split_kernel<<<(NX + 255) / 256, 256>>>(x, xhi, xlo, NX);

    // 4-6: QKV projections  (launch #6 = gemm_v is what ncu captures)
    dim3 gg(DM / 64, Mv / 128);
    gemm_bf16x3<<<gg, 128>>>(xhi, xlo, whi + 0 * NW, wlo + 0 * NW, bq, qp, Mv, DM, DM);
    gemm_bf16x3<<<gg, 128>>>(xhi, xlo, whi + 1 * NW, wlo + 1 * NW, bk, kp, Mv, DM, DM);
    gemm_bf16x3<<<gg, 128>>>(xhi, xlo, whi + 2 * NW, wlo + 2 * NW, bv, vp, Mv, DM, DM);

    // Q carries 0.125*log2(e) so softmax is exp2(S)
    const float QSCL = 0.125f * 1.4426950408889634f;
    int nrope = Mv * 512;
    rope_half_kernel<<<(nrope + 255) / 256, 256>>>(
        (const float2*)qp, (__half2*)qh, QSCL);
    rope_split_half_kernel<<<(nrope + 255) / 256, 256>>>(
        (const float2*)kp, (__half2*)khi, (__half2*)klo);
    split_half_kernel<<<(NX + 255) / 256, 256>>>(vp, vhi, vlo, NX);

    dim3 att_grid(Sv / 64, Hv, Bv);
    flash_mma<<<att_grid, 128, FLASH_SMEM>>>(qh, khi, klo, vhi, vlo, yhi, ylo);

    gemm_bf16x3<<<gg, 128>>>(yhi, ylo, whi + 3 * NW, wlo + 3 * NW, bo, out, Mv, DM, DM);
}

// round 9
// speedup vs baseline: 5.7826x; 1.5785x over previous
#include <cuda_runtime.h>
#include <cuda_bf16.h>
#include <cuda_fp16.h>
#include <stdint.h>
#include <cstdint>
#include <math.h>

#define Bv 4
#define Sv 2048
#define Hv 16
#define Dv 64
#define DM 1024
#define Mv (Bv*Sv)   // 8192

// ---------------------------------------------------------------------------
// Scratch (allocation-free rule: __device__ globals)
// ---------------------------------------------------------------------------
__device__ float g_q[Mv*DM];
__device__ float g_k[Mv*DM];
__device__ float g_v[Mv*DM];
__device__ float g_cos[Sv*32];
__device__ float g_sin[Sv*32];

__device__ __half g_xh [Mv*DM];
__device__ __half g_yh [Mv*DM];
__device__ __half g_whi[4*DM*DM];
__device__ __half g_wlo[4*DM*DM];
__device__ __half g_qh [Mv*DM];
__device__ __half g_khi[Mv*DM];
__device__ __half g_klo[Mv*DM];
__device__ __half g_vhi[Mv*DM];
__device__ __half g_vlo[Mv*DM];

// ---------------------------------------------------------------------------
// elementwise prep kernels
// ---------------------------------------------------------------------------
__global__ void tohalf_kernel(const float* __restrict__ s,
                              __half* __restrict__ o, int n)
{
    int i = blockIdx.x * blockDim.x + threadIdx.x;
    if (i >= n) return;
    o[i] = __float2half_rn(s[i]);
}

// all four weight matrices -> fp16 hi/lo in one launch
__global__ void split4_half_kernel(const float* __restrict__ s0, const float* __restrict__ s1,
                                   const float* __restrict__ s2, const float* __restrict__ s3,
                                   __half* __restrict__ hi,
                                   __half* __restrict__ lo, int n)
{
    int i = blockIdx.x * blockDim.x + threadIdx.x;
    if (i >= 4 * n) return;
    int w = i / n, r = i - w * n;
    const float* src = (w == 0) ? s0 : (w == 1) ? s1 : (w == 2) ? s2 : s3;
    float x = src[r];
    __half h = __float2half_rn(x);
    hi[i] = h;
    lo[i] = __float2half_rn(x - __half2float(h));
}

__global__ void rope_table_kernel() {
    int idx = blockIdx.x * blockDim.x + threadIdx.x;
    if (idx >= Sv * 32) return;
    int pos = idx >> 5;
    int i   = idx & 31;
    double inv = pow(10000.0, -(double)i / 32.0);
    double ang = (double)pos * inv;
    g_cos[idx] = (float)cos(ang);
    g_sin[idx] = (float)sin(ang);
}

// rope + scale -> single fp16 (for Q)
__global__ void rope_half_kernel(const float2* __restrict__ src,
                                 __half2* __restrict__ out, float scl)
{
    int idx = blockIdx.x * blockDim.x + threadIdx.x;
    if (idx >= Mv * 512) return;
    int p = idx & 511;
    int i = p & 31;
    int s = (idx >> 9) & (Sv - 1);
    float c  = g_cos[(s << 5) + i];
    float sn = g_sin[(s << 5) + i];
    float2 v = src[idx];
    out[idx] = __floats2half2_rn((v.x * c - v.y * sn) * scl,
                                 (v.y * c + v.x * sn) * scl);
}

// rope -> fp16 hi/lo (for K)
__global__ void rope_split_half_kernel(const float2* __restrict__ src,
                                       __half2* __restrict__ hi,
                                       __half2* __restrict__ lo)
{
    int idx = blockIdx.x * blockDim.x + threadIdx.x;
    if (idx >= Mv * 512) return;
    int p = idx & 511;
    int i = p & 31;
    int s = (idx >> 9) & (Sv - 1);
    float c  = g_cos[(s << 5) + i];
    float sn = g_sin[(s << 5) + i];
    float2 v = src[idx];
    float2 r = make_float2(v.x * c - v.y * sn, v.y * c + v.x * sn);
    __half2 h2 = __floats2half2_rn(r.x, r.y);
    float2 back = __half22float2(h2);
    hi[idx] = h2;
    lo[idx] = __floats2half2_rn(r.x - back.x, r.y - back.y);
}

// fp32 -> fp16 hi/lo (for V)
__global__ void split_half_kernel(const float* __restrict__ s,
                                  __half* __restrict__ hi,
                                  __half* __restrict__ lo, int n)
{
    int i = blockIdx.x * blockDim.x + threadIdx.x;
    if (i >= n) return;
    float x = s[i];
    __half h = __float2half_rn(x);
    hi[i] = h;
    lo[i] = __float2half_rn(x - __half2float(h));
}

// ---------------------------------------------------------------------------
// MMA / async-copy primitives
// ---------------------------------------------------------------------------
__device__ __forceinline__ void ldmx4(unsigned& r0, unsigned& r1,
                                      unsigned& r2, unsigned& r3, unsigned a) {
    asm volatile("ldmatrix.sync.aligned.m8n8.x4.shared.b16 {%0,%1,%2,%3}, [%4];"
        : "=r"(r0), "=r"(r1), "=r"(r2), "=r"(r3) : "r"(a));
}
__device__ __forceinline__ void ldmx4t(unsigned& r0, unsigned& r1,
                                       unsigned& r2, unsigned& r3, unsigned a) {
    asm volatile("ldmatrix.sync.aligned.m8n8.x4.trans.shared.b16 {%0,%1,%2,%3}, [%4];"
        : "=r"(r0), "=r"(r1), "=r"(r2), "=r"(r3) : "r"(a));
}
__device__ __forceinline__ void mma16816h(float* c, const unsigned* a, const unsigned* b) {
    asm volatile(
        "mma.sync.aligned.m16n8k16.row.col.f32.f16.f16.f32 "
        "{%0,%1,%2,%3}, {%4,%5,%6,%7}, {%8,%9}, {%0,%1,%2,%3};"
        : "+f"(c[0]), "+f"(c[1]), "+f"(c[2]), "+f"(c[3])
        : "r"(a[0]), "r"(a[1]), "r"(a[2]), "r"(a[3]), "r"(b[0]), "r"(b[1]));
}
__device__ __forceinline__ void cpa16(void* smem, const void* g) {
    unsigned s = (unsigned)__cvta_generic_to_shared(smem);
    asm volatile("cp.async.cg.shared.global [%0], [%1], 16;" :: "r"(s), "l"(g));
}
__device__ __forceinline__ void cp_commit() { asm volatile("cp.async.commit_group;"); }
template<int N> __device__ __forceinline__ void cp_wait() {
    asm volatile("cp.async.wait_group %0;" :: "n"(N));
}
__device__ __forceinline__ float ex2f(float x) {
    float y;
    asm("ex2.approx.ftz.f32 %0, %1;" : "=f"(y) : "f"(x));
    return y;
}

// ---------------------------------------------------------------------------
// GEMM, fp16 2-term: C = A(fp16) @ (Bhi + Blo) + bias
// BM=128 BN=64 BK=32, 128 threads (4 warps 2x2), warp tile 64x32.
// ---------------------------------------------------------------------------
#define APAD 40
#define BPAD 72

__global__ __launch_bounds__(128) void gemm_fp16x2(
    const __half* __restrict__ Ah,
    const __half* __restrict__ Bhi, const __half* __restrict__ Blo,
    const float* __restrict__ bias, float* __restrict__ C,
    int M, int N, int K)
{
    __shared__ __half As[128][APAD];
    __shared__ __half Bs[2][32][BPAD];

    int tid  = threadIdx.x;
    int lane = tid & 31;
    int warp = tid >> 5;
    int wm = warp >> 1, wn = warp & 1;
    int bm = blockIdx.y << 7;
    int bn = blockIdx.x << 6;

    float acc[4][4][4];
#pragma unroll
    for (int i = 0; i < 4; i++)
#pragma unroll
        for (int j = 0; j < 4; j++)
#pragma unroll
            for (int e = 0; e < 4; e++) acc[i][j][e] = 0.f;

    int u0k = tid >> 3, u0n = (tid & 7) << 3;
    int u1k = (tid + 128) >> 3, u1n = ((tid + 128) & 7) << 3;

    for (int k0 = 0; k0 < K; k0 += 32) {
        uint4 av[4], bh[2], bl[2];
        const __half* Ap = Ah + (size_t)(bm + tid) * K + k0;
#pragma unroll
        for (int i = 0; i < 4; i++)
            av[i] = *(const uint4*)(Ap + i * 8);
        bh[0] = *(const uint4*)(Bhi + (size_t)(k0 + u0k) * N + bn + u0n);
        bh[1] = *(const uint4*)(Bhi + (size_t)(k0 + u1k) * N + bn + u1n);
        bl[0] = *(const uint4*)(Blo + (size_t)(k0 + u0k) * N + bn + u0n);
        bl[1] = *(const uint4*)(Blo + (size_t)(k0 + u1k) * N + bn + u1n);

        __syncthreads();
#pragma unroll
        for (int i = 0; i < 4; i++)
            *(uint4*)&As[tid][i * 8] = av[i];
        *(uint4*)&Bs[0][u0k][u0n] = bh[0];
        *(uint4*)&Bs[0][u1k][u1n] = bh[1];
        *(uint4*)&Bs[1][u0k][u0n] = bl[0];
        *(uint4*)&Bs[1][u1k][u1n] = bl[1];
        __syncthreads();

#pragma unroll
        for (int ks = 0; ks < 2; ks++) {
            int k16 = ks << 4;
            unsigned Af[4][4];
            int ar = (lane & 15);
            int ac = k16 + ((lane >> 4) << 3);
#pragma unroll
            for (int mt = 0; mt < 4; mt++) {
                int m0 = wm * 64 + mt * 16;
                unsigned a0 = (unsigned)__cvta_generic_to_shared(&As[m0 + ar][ac]);
                ldmx4(Af[mt][0], Af[mt][1], Af[mt][2], Af[mt][3], a0);
            }
            unsigned Bf[2][4][2];
            int bkr = k16 + (lane & 7) + (lane & 8);
#pragma unroll
            for (int p = 0; p < 2; p++) {
                int n0 = wn * 32 + p * 16 + (((lane >> 4) & 1) << 3);
                unsigned r0, r1, r2, r3;
                unsigned ad = (unsigned)__cvta_generic_to_shared(&Bs[0][bkr][n0]);
                ldmx4t(r0, r1, r2, r3, ad);
                Bf[0][p * 2][0] = r0; Bf[0][p * 2][1] = r1;
                Bf[0][p * 2 + 1][0] = r2; Bf[0][p * 2 + 1][1] = r3;
                ad = (unsigned)__cvta_generic_to_shared(&Bs[1][bkr][n0]);
                ldmx4t(r0, r1, r2, r3, ad);
                Bf[1][p * 2][0] = r0; Bf[1][p * 2][1] = r1;
                Bf[1][p * 2 + 1][0] = r2; Bf[1][p * 2 + 1][1] = r3;
            }
#pragma unroll
            for (int mt = 0; mt < 4; mt++)
#pragma unroll
                for (int nt = 0; nt < 4; nt++) {
                    mma16816h(acc[mt][nt], Af[mt], Bf[0][nt]);
                    mma16816h(acc[mt][nt], Af[mt], Bf[1][nt]);
                }
        }
    }

    int gid = lane >> 2, tq = lane & 3;
#pragma unroll
    for (int mt = 0; mt < 4; mt++) {
        int row = bm + wm * 64 + mt * 16 + gid;
#pragma unroll
        for (int nt = 0; nt < 4; nt++) {
            int col = bn + wn * 32 + nt * 8 + tq * 2;
            float b0 = bias[col], b1 = bias[col + 1];
            *(float2*)&C[(size_t)row * N + col] =
                make_float2(acc[mt][nt][0] + b0, acc[mt][nt][1] + b1);
            *(float2*)&C[(size_t)(row + 8) * N + col] =
                make_float2(acc[mt][nt][2] + b0, acc[mt][nt][3] + b1);
        }
    }
}

// ---------------------------------------------------------------------------
// Flash attention, causal, fp16x2 split, cp.async double-buffered K/V,
// no-rescale exp2 softmax. Output y = single fp16.
// ---------------------------------------------------------------------------
#define KPAD 72
#define BUF_ELEMS (64*KPAD)
#define STG_ELEMS (4*BUF_ELEMS)
#define FLASH_SMEM (2*STG_ELEMS*sizeof(__half))  // 73728

__global__ __launch_bounds__(128) void flash_mma(
    const __half* __restrict__ qh,
    const __half* __restrict__ khi, const __half* __restrict__ klo,
    const __half* __restrict__ vhi, const __half* __restrict__ vlo,
    __half* __restrict__ yh)
{
    extern __shared__ __half smx[];

    int tid = threadIdx.x, lane = tid & 31, warp = tid >> 5;
    int qt = (int)gridDim.x - 1 - (int)blockIdx.x;
    int h = blockIdx.y, b = blockIdx.z;
    int qg0 = qt * 64;
    size_t base = ((size_t)b * Sv) * DM + h * Dv;
    int gid = lane >> 2, tig = lane & 3;

    const __half* srcs[4] = {khi, klo, vhi, vlo};

#pragma unroll
    for (int p = 0; p < 4; p++) {
        int idx = p * 128 + tid;
        int row = idx >> 3, c = idx & 7;
        cpa16(&smx[STG_ELEMS + row * KPAD + c * 8],
              qh + base + (size_t)(qg0 + row) * DM + c * 8);
    }
    cp_commit();
#pragma unroll
    for (int p = 0; p < 16; p++) {
        int buf = p >> 2;
        int idx = ((p & 3) << 7) + tid;
        int row = idx >> 3, c = idx & 7;
        cpa16(&smx[buf * BUF_ELEMS + row * KPAD + c * 8],
              srcs[buf] + base + (size_t)row * DM + c * 8);
    }
    cp_commit();

    cp_wait<1>();
    __syncthreads();

    unsigned Qf[4][4];
    {
        int r = warp * 16 + (lane & 15);
        int c = (lane >> 4) << 3;
#pragma unroll
        for (int kt = 0; kt < 4; kt++) {
            unsigned a = (unsigned)__cvta_generic_to_shared(
                &smx[STG_ELEMS + r * KPAD + kt * 16 + c]);
            ldmx4(Qf[kt][0], Qf[kt][1], Qf[kt][2], Qf[kt][3], a);
        }
    }
    __syncthreads();

    int krow = (lane & 7) + ((lane >> 4) << 3);
    int kcol = ((lane >> 3) & 1) << 3;
    int vrow = (lane & 7) + (((lane >> 3) & 1) << 3);
    int vcol = (lane >> 4) << 3;

    float acc_o[8][4];
#pragma unroll
    for (int i = 0; i < 8; i++)
#pragma unroll
        for (int e = 0; e < 4; e++) acc_o[i][e] = 0.f;
    float lsum0 = 0.f, lsum1 = 0.f;
    int row0g = qg0 + warp * 16 + gid;

    int n = qt + 1;
    for (int j = 0; j < n; j++) {
        int s = j & 1;
        if (j + 1 < n) {
            int sb = (1 - s) * STG_ELEMS;
            size_t grow = base + (size_t)(j + 1) * 64 * DM;
#pragma unroll
            for (int p = 0; p < 16; p++) {
                int buf = p >> 2;
                int idx = ((p & 3) << 7) + tid;
                int row = idx >> 3, c = idx & 7;
                cpa16(&smx[sb + buf * BUF_ELEMS + row * KPAD + c * 8],
                      srcs[buf] + grow + (size_t)row * DM + c * 8);
            }
            cp_commit();
            cp_wait<1>();
        } else {
            cp_wait<0>();
        }
        __syncthreads();

        __half* Kh_ = smx + s * STG_ELEMS;
        __half* Kl_ = Kh_ + BUF_ELEMS;
        __half* Vh_ = Kh_ + 2 * BUF_ELEMS;
        __half* Vl_ = Kh_ + 3 * BUF_ELEMS;

        float sc[8][4];
#pragma unroll
        for (int i = 0; i < 8; i++)
#pragma unroll
            for (int e = 0; e < 4; e++) sc[i][e] = 0.f;

#pragma unroll
        for (int kt = 0; kt < 4; kt++) {
            unsigned Kf[2][8][2];
#pragma unroll
            for (int ng = 0; ng < 4; ng++) {
                unsigned r0, r1, r2, r3;
                unsigned a = (unsigned)__cvta_generic_to_shared(
                    &Kh_[(ng * 16 + krow) * KPAD + kt * 16 + kcol]);
                ldmx4(r0, r1, r2, r3, a);
                Kf[0][ng * 2][0] = r0; Kf[0][ng * 2][1] = r1;
                Kf[0][ng * 2 + 1][0] = r2; Kf[0][ng * 2 + 1][1] = r3;
                a = (unsigned)__cvta_generic_to_shared(
                    &Kl_[(ng * 16 + krow) * KPAD + kt * 16 + kcol]);
                ldmx4(r0, r1, r2, r3, a);
                Kf[1][ng * 2][0] = r0; Kf[1][ng * 2][1] = r1;
                Kf[1][ng * 2 + 1][0] = r2; Kf[1][ng * 2 + 1][1] = r3;
            }
#pragma unroll
            for (int nt = 0; nt < 8; nt++) {
                mma16816h(sc[nt], Qf[kt], Kf[0][nt]);
                mma16816h(sc[nt], Qf[kt], Kf[1][nt]);
            }
        }

        if (j == qt) {
#pragma unroll
            for (int nt = 0; nt < 8; nt++) {
#pragma unroll
                for (int e = 0; e < 4; e++) {
                    int col = qg0 + nt * 8 + 2 * tig + (e & 1);
                    int row = row0g + ((e >> 1) << 3);
                    sc[nt][e] = (col > row) ? 0.f : ex2f(sc[nt][e]);
                }
                lsum0 += sc[nt][0] + sc[nt][1];
                lsum1 += sc[nt][2] + sc[nt][3];
            }
        } else {
#pragma unroll
            for (int nt = 0; nt < 8; nt++) {
                sc[nt][0] = ex2f(sc[nt][0]);
                sc[nt][1] = ex2f(sc[nt][1]);
                sc[nt][2] = ex2f(sc[nt][2]);
                sc[nt][3] = ex2f(sc[nt][3]);
                lsum0 += sc[nt][0] + sc[nt][1];
                lsum1 += sc[nt][2] + sc[nt][3];
            }
        }

#pragma unroll
        for (int kt = 0; kt < 4; kt++) {
            unsigned Ph[4];
#pragma unroll
            for (int half = 0; half < 2; half++) {
                int nt = 2 * kt + half;
                __half2 h0 = __floats2half2_rn(sc[nt][0], sc[nt][1]);
                __half2 h1 = __floats2half2_rn(sc[nt][2], sc[nt][3]);
                Ph[half * 2]     = *(unsigned*)&h0;
                Ph[half * 2 + 1] = *(unsigned*)&h1;
            }
            unsigned Vf[2][8][2];
#pragma unroll
            for (int dg = 0; dg < 4; dg++) {
                unsigned r0, r1, r2, r3;
                unsigned a = (unsigned)__cvta_generic_to_shared(
                    &Vh_[(kt * 16 + vrow) * KPAD + dg * 16 + vcol]);
                ldmx4t(r0, r1, r2, r3, a);
                Vf[0][dg * 2][0] = r0; Vf[0][dg * 2][1] = r1;
                Vf[0][dg * 2 + 1][0] = r2; Vf[0][dg * 2 + 1][1] = r3;
                a = (unsigned)__cvta_generic_to_shared(
                    &Vl_[(kt * 16 + vrow) * KPAD + dg * 16 + vcol]);
                ldmx4t(r0, r1, r2, r3, a);
                Vf[1][dg * 2][0] = r0; Vf[1][dg * 2][1] = r1;
                Vf[1][dg * 2 + 1][0] = r2; Vf[1][dg * 2 + 1][1] = r3;
            }
#pragma unroll
            for (int dnt = 0; dnt < 8; dnt++) {
                mma16816h(acc_o[dnt], Ph, Vf[0][dnt]);
                mma16816h(acc_o[dnt], Ph, Vf[1][dnt]);
            }
        }
        __syncthreads();
    }

    // ---- epilogue: quad-reduce sums, normalize, single fp16 store ----
    lsum0 += __shfl_xor_sync(0xffffffffu, lsum0, 1);
    lsum0 += __shfl_xor_sync(0xffffffffu, lsum0, 2);
    lsum1 += __shfl_xor_sync(0xffffffffu, lsum1, 1);
    lsum1 += __shfl_xor_sync(0xffffffffu, lsum1, 2);
    float inv0 = 1.f / lsum0, inv1 = 1.f / lsum1;
    size_t o0 = ((size_t)b * Sv + row0g) * DM + h * Dv;
    size_t o1 = o0 + (size_t)8 * DM;
#pragma unroll
    for (int dnt = 0; dnt < 8; dnt++) {
        int col = dnt * 8 + 2 * tig;
        __half2 h0 = __floats2half2_rn(acc_o[dnt][0] * inv0, acc_o[dnt][1] * inv0);
        __half2 h1 = __floats2half2_rn(acc_o[dnt][2] * inv1, acc_o[dnt][3] * inv1);
        *(__half2*)&yh[o0 + col] = h0;
        *(__half2*)&yh[o1 + col] = h1;
    }
}

// ---------------------------------------------------------------------------
// kernel_launch   (launch #6 = gemm_fp16x2 for the ncu capture)
// ---------------------------------------------------------------------------
extern "C" void kernel_launch(void* const* d_in, const int* in_sizes, int n_in,
                              void* d_out, int out_size)
{
    const float* x  = (const float*)d_in[0];
    const float* Wq = (const float*)d_in[1];
    const float* bq = (const float*)d_in[2];
    const float* Wk = (const float*)d_in[3];
    const float* bk = (const float*)d_in[4];
    const float* Wv = (const float*)d_in[5];
    const float* bv = (const float*)d_in[6];
    const float* Wo = (const float*)d_in[7];
    const float* bo = (const float*)d_in[8];
    float* out = (float*)d_out;

    float *qp, *kp, *vp;
    cudaGetSymbolAddress((void**)&qp, g_q);
    cudaGetSymbolAddress((void**)&kp, g_k);
    cudaGetSymbolAddress((void**)&vp, g_v);
    __half *xh, *yh, *whi, *wlo, *qh, *khi, *klo, *vhi, *vlo;
    cudaGetSymbolAddress((void**)&xh,  g_xh);
    cudaGetSymbolAddress((void**)&yh,  g_yh);
    cudaGetSymbolAddress((void**)&whi, g_whi);
    cudaGetSymbolAddress((void**)&wlo, g_wlo);
    cudaGetSymbolAddress((void**)&qh,  g_qh);
    cudaGetSymbolAddress((void**)&khi, g_khi);
    cudaGetSymbolAddress((void**)&klo, g_klo);
    cudaGetSymbolAddress((void**)&vhi, g_vhi);
    cudaGetSymbolAddress((void**)&vlo, g_vlo);

    cudaFuncSetAttribute(flash_mma,
                         cudaFuncAttributeMaxDynamicSharedMemorySize,
                         (int)FLASH_SMEM);

    const int NX = Mv * DM;
    const int NW = DM * DM;

    // 1: rope tables
    rope_table_kernel<<<(Sv * 32 + 255) / 256, 256>>>();
    // 2: all weight splits (fp16 hi/lo)
    split4_half_kernel<<<(4 * NW + 255) / 256, 256>>>(Wq, Wk, Wv, Wo, whi, wlo, NW);
    // 3: x -> fp16
    tohalf_kernel<<<(NX + 255) / 256, 256>>>(x, xh, NX);

    // 4-6: QKV projections
    dim3 gg(DM / 64, Mv / 128);
    gemm_fp16x2<<<gg, 128>>>(xh, whi + 0 * NW, wlo + 0 * NW, bq, qp, Mv, DM, DM);
    gemm_fp16x2<<<gg, 128>>>(xh, whi + 1 * NW, wlo + 1 * NW, bk, kp, Mv, DM, DM);
    gemm_fp16x2<<<gg, 128>>>(xh, whi + 2 * NW, wlo + 2 * NW, bv, vp, Mv, DM, DM);

    // Q carries 0.125*log2(e) so softmax is exp2(S)
    const float QSCL = 0.125f * 1.4426950408889634f;
    int nrope = Mv * 512;
    rope_half_kernel<<<(nrope + 255) / 256, 256>>>(
        (const float2*)qp, (__half2*)qh, QSCL);
    rope_split_half_kernel<<<(nrope + 255) / 256, 256>>>(
        (const float2*)kp, (__half2*)khi, (__half2*)klo);
    split_half_kernel<<<(NX + 255) / 256, 256>>>(vp, vhi, vlo, NX);

    dim3 att_grid(Sv / 64, Hv, Bv);
    flash_mma<<<att_grid, 128, FLASH_SMEM>>>(qh, khi, klo, vhi, vlo, yh);

    // output projection
    gemm_fp16x2<<<gg, 128>>>(yh, whi + 3 * NW, wlo + 3 * NW, bo, out, Mv, DM, DM);
}

// round 10
// speedup vs baseline: 6.1318x; 1.0604x over previous
#include <cuda_runtime.h>
#include <cuda_bf16.h>
#include <cuda_fp16.h>
#include <stdint.h>
#include <cstdint>
#include <math.h>

#define Bv 4
#define Sv 2048
#define Hv 16
#define Dv 64
#define DM 1024
#define Mv (Bv*Sv)   // 8192

// ---------------------------------------------------------------------------
// Scratch (allocation-free rule: __device__ globals)
// ---------------------------------------------------------------------------
__device__ float g_cos[Sv*32];
__device__ float g_sin[Sv*32];

__device__ __half g_xh [Mv*DM];
__device__ __half g_yh [Mv*DM];
__device__ __half g_whi[4*DM*DM];
__device__ __half g_wlo[4*DM*DM];
__device__ __half g_qh [Mv*DM];
__device__ __half g_khi[Mv*DM];
__device__ __half g_klo[Mv*DM];
__device__ __half g_vh [Mv*DM];

// ---------------------------------------------------------------------------
// prep kernels
// ---------------------------------------------------------------------------
__global__ void tohalf_kernel(const float* __restrict__ s,
                              __half* __restrict__ o, int n)
{
    int i = blockIdx.x * blockDim.x + threadIdx.x;
    if (i >= n) return;
    o[i] = __float2half_rn(s[i]);
}

__global__ void split4_half_kernel(const float* __restrict__ s0, const float* __restrict__ s1,
                                   const float* __restrict__ s2, const float* __restrict__ s3,
                                   __half* __restrict__ hi,
                                   __half* __restrict__ lo, int n)
{
    int i = blockIdx.x * blockDim.x + threadIdx.x;
    if (i >= 4 * n) return;
    int w = i / n, r = i - w * n;
    const float* src = (w == 0) ? s0 : (w == 1) ? s1 : (w == 2) ? s2 : s3;
    float x = src[r];
    __half h = __float2half_rn(x);
    hi[i] = h;
    lo[i] = __float2half_rn(x - __half2float(h));
}

__global__ void rope_table_kernel() {
    int idx = blockIdx.x * blockDim.x + threadIdx.x;
    if (idx >= Sv * 32) return;
    int pos = idx >> 5;
    int i   = idx & 31;
    double inv = pow(10000.0, -(double)i / 32.0);
    double ang = (double)pos * inv;
    g_cos[idx] = (float)cos(ang);
    g_sin[idx] = (float)sin(ang);
}

// ---------------------------------------------------------------------------
// MMA / async-copy primitives
// ---------------------------------------------------------------------------
__device__ __forceinline__ void ldmx4(unsigned& r0, unsigned& r1,
                                      unsigned& r2, unsigned& r3, unsigned a) {
    asm volatile("ldmatrix.sync.aligned.m8n8.x4.shared.b16 {%0,%1,%2,%3}, [%4];"
        : "=r"(r0), "=r"(r1), "=r"(r2), "=r"(r3) : "r"(a));
}
__device__ __forceinline__ void ldmx4t(unsigned& r0, unsigned& r1,
                                       unsigned& r2, unsigned& r3, unsigned a) {
    asm volatile("ldmatrix.sync.aligned.m8n8.x4.trans.shared.b16 {%0,%1,%2,%3}, [%4];"
        : "=r"(r0), "=r"(r1), "=r"(r2), "=r"(r3) : "r"(a));
}
__device__ __forceinline__ void mma16816h(float* c, const unsigned* a, const unsigned* b) {
    asm volatile(
        "mma.sync.aligned.m16n8k16.row.col.f32.f16.f16.f32 "
        "{%0,%1,%2,%3}, {%4,%5,%6,%7}, {%8,%9}, {%0,%1,%2,%3};"
        : "+f"(c[0]), "+f"(c[1]), "+f"(c[2]), "+f"(c[3])
        : "r"(a[0]), "r"(a[1]), "r"(a[2]), "r"(a[3]), "r"(b[0]), "r"(b[1]));
}
__device__ __forceinline__ void cpa16(void* smem, const void* g) {
    unsigned s = (unsigned)__cvta_generic_to_shared(smem);
    asm volatile("cp.async.cg.shared.global [%0], [%1], 16;" :: "r"(s), "l"(g));
}
__device__ __forceinline__ void cp_commit() { asm volatile("cp.async.commit_group;"); }
template<int N> __device__ __forceinline__ void cp_wait() {
    asm volatile("cp.async.wait_group %0;" :: "n"(N));
}
__device__ __forceinline__ float ex2f(float x) {
    float y;
    asm("ex2.approx.ftz.f32 %0, %1;" : "=f"(y) : "f"(x));
    return y;
}

// ---------------------------------------------------------------------------
// Templated GEMM: C = A(fp16) @ (Bhi [+ Blo]) + bias, fused epilogue.
// MODE 0: fp32 out (Cf)        MODE 1: rope+scale -> fp16 (C1)
// MODE 2: rope -> fp16 hi/lo (C1,C2)   MODE 3: fp16 (C1)
// BM=128 BN=64 BK=32, 128 threads (4 warps 2x2), warp tile 64x32.
// ---------------------------------------------------------------------------
#define APAD 40
#define BPAD 72

template<int TERMS, int MODE>
__global__ __launch_bounds__(128) void gemm_t(
    const __half* __restrict__ Ah,
    const __half* __restrict__ Bhi, const __half* __restrict__ Blo,
    const float* __restrict__ bias,
    __half* __restrict__ C1, __half* __restrict__ C2,
    float* __restrict__ Cf,
    int M, int N, int K, float qscl)
{
    __shared__ __half As[128][APAD];
    __shared__ __half Bs[TERMS][32][BPAD];

    int tid  = threadIdx.x;
    int lane = tid & 31;
    int warp = tid >> 5;
    int wm = warp >> 1, wn = warp & 1;
    int bm = blockIdx.y << 7;
    int bn = blockIdx.x << 6;

    float acc[4][4][4];
#pragma unroll
    for (int i = 0; i < 4; i++)
#pragma unroll
        for (int j = 0; j < 4; j++)
#pragma unroll
            for (int e = 0; e < 4; e++) acc[i][j][e] = 0.f;

    int u0k = tid >> 3, u0n = (tid & 7) << 3;
    int u1k = (tid + 128) >> 3, u1n = ((tid + 128) & 7) << 3;

    for (int k0 = 0; k0 < K; k0 += 32) {
        uint4 av[4], bh[2], bl[2];
        const __half* Ap = Ah + (size_t)(bm + tid) * K + k0;
#pragma unroll
        for (int i = 0; i < 4; i++)
            av[i] = *(const uint4*)(Ap + i * 8);
        bh[0] = *(const uint4*)(Bhi + (size_t)(k0 + u0k) * N + bn + u0n);
        bh[1] = *(const uint4*)(Bhi + (size_t)(k0 + u1k) * N + bn + u1n);
        if (TERMS == 2) {
            bl[0] = *(const uint4*)(Blo + (size_t)(k0 + u0k) * N + bn + u0n);
            bl[1] = *(const uint4*)(Blo + (size_t)(k0 + u1k) * N + bn + u1n);
        }

        __syncthreads();
#pragma unroll
        for (int i = 0; i < 4; i++)
            *(uint4*)&As[tid][i * 8] = av[i];
        *(uint4*)&Bs[0][u0k][u0n] = bh[0];
        *(uint4*)&Bs[0][u1k][u1n] = bh[1];
        if (TERMS == 2) {
            *(uint4*)&Bs[1][u0k][u0n] = bl[0];
            *(uint4*)&Bs[1][u1k][u1n] = bl[1];
        }
        __syncthreads();

#pragma unroll
        for (int ks = 0; ks < 2; ks++) {
            int k16 = ks << 4;
            unsigned Af[4][4];
            int ar = (lane & 15);
            int ac = k16 + ((lane >> 4) << 3);
#pragma unroll
            for (int mt = 0; mt < 4; mt++) {
                int m0 = wm * 64 + mt * 16;
                unsigned a0 = (unsigned)__cvta_generic_to_shared(&As[m0 + ar][ac]);
                ldmx4(Af[mt][0], Af[mt][1], Af[mt][2], Af[mt][3], a0);
            }
            unsigned Bf[TERMS][4][2];
            int bkr = k16 + (lane & 7) + (lane & 8);
#pragma unroll
            for (int p = 0; p < 2; p++) {
                int n0 = wn * 32 + p * 16 + (((lane >> 4) & 1) << 3);
                unsigned r0, r1, r2, r3;
                unsigned ad = (unsigned)__cvta_generic_to_shared(&Bs[0][bkr][n0]);
                ldmx4t(r0, r1, r2, r3, ad);
                Bf[0][p * 2][0] = r0; Bf[0][p * 2][1] = r1;
                Bf[0][p * 2 + 1][0] = r2; Bf[0][p * 2 + 1][1] = r3;
                if (TERMS == 2) {
                    ad = (unsigned)__cvta_generic_to_shared(&Bs[1][bkr][n0]);
                    ldmx4t(r0, r1, r2, r3, ad);
                    Bf[1][p * 2][0] = r0; Bf[1][p * 2][1] = r1;
                    Bf[1][p * 2 + 1][0] = r2; Bf[1][p * 2 + 1][1] = r3;
                }
            }
#pragma unroll
            for (int mt = 0; mt < 4; mt++)
#pragma unroll
                for (int nt = 0; nt < 4; nt++) {
                    mma16816h(acc[mt][nt], Af[mt], Bf[0][nt]);
                    if (TERMS == 2)
                        mma16816h(acc[mt][nt], Af[mt], Bf[1][nt]);
                }
        }
    }

    // ---- fused epilogue ----
    int gid = lane >> 2, tq = lane & 3;
#pragma unroll
    for (int mt = 0; mt < 4; mt++) {
        int row = bm + wm * 64 + mt * 16 + gid;
#pragma unroll
        for (int nt = 0; nt < 4; nt++) {
            int col = bn + wn * 32 + nt * 8 + tq * 2;
            float b0 = bias[col], b1 = bias[col + 1];
            float v0 = acc[mt][nt][0] + b0;
            float v1 = acc[mt][nt][1] + b1;
            float v2 = acc[mt][nt][2] + b0;
            float v3 = acc[mt][nt][3] + b1;
            if (MODE == 0) {
                *(float2*)&Cf[(size_t)row * N + col] = make_float2(v0, v1);
                *(float2*)&Cf[(size_t)(row + 8) * N + col] = make_float2(v2, v3);
            } else if (MODE == 3) {
                *(__half2*)&C1[(size_t)row * N + col] = __floats2half2_rn(v0, v1);
                *(__half2*)&C1[(size_t)(row + 8) * N + col] = __floats2half2_rn(v2, v3);
            } else {
                // rope: col pair (2i, 2i+1) within head; i = (col>>1)&31
                int i = (col >> 1) & 31;
                int s1 = row & (Sv - 1);
                float c1 = g_cos[(s1 << 5) + i],       sn1 = g_sin[(s1 << 5) + i];
                float c2 = g_cos[((s1 + 8) << 5) + i], sn2 = g_sin[((s1 + 8) << 5) + i];
                float r0 = (v0 * c1 - v1 * sn1) * qscl;
                float r1 = (v1 * c1 + v0 * sn1) * qscl;
                float r2 = (v2 * c2 - v3 * sn2) * qscl;
                float r3 = (v3 * c2 + v2 * sn2) * qscl;
                __half2 h0 = __floats2half2_rn(r0, r1);
                __half2 h1 = __floats2half2_rn(r2, r3);
                *(__half2*)&C1[(size_t)row * N + col] = h0;
                *(__half2*)&C1[(size_t)(row + 8) * N + col] = h1;
                if (MODE == 2) {
                    float2 k0f = __half22float2(h0);
                    float2 k1f = __half22float2(h1);
                    *(__half2*)&C2[(size_t)row * N + col] =
                        __floats2half2_rn(r0 - k0f.x, r1 - k0f.y);
                    *(__half2*)&C2[(size_t)(row + 8) * N + col] =
                        __floats2half2_rn(r2 - k1f.x, r3 - k1f.y);
                }
            }
        }
    }
}

// ---------------------------------------------------------------------------
// Flash attention, causal: Q,P single fp16; K fp16 hi/lo; V single fp16.
// cp.async double-buffered (3 buffers/stage), no-rescale exp2 softmax.
// ---------------------------------------------------------------------------
#define KPAD 72
#define BUF_ELEMS (64*KPAD)        // 4608 halves
#define STG_ELEMS (3*BUF_ELEMS)    // 13824
#define FLASH_SMEM (2*STG_ELEMS*sizeof(__half))  // 55296

__global__ __launch_bounds__(128) void flash_mma(
    const __half* __restrict__ qh,
    const __half* __restrict__ khi, const __half* __restrict__ klo,
    const __half* __restrict__ vh,
    __half* __restrict__ yh)
{
    extern __shared__ __half smx[];

    int tid = threadIdx.x, lane = tid & 31, warp = tid >> 5;
    int qt = (int)gridDim.x - 1 - (int)blockIdx.x;
    int h = blockIdx.y, b = blockIdx.z;
    int qg0 = qt * 64;
    size_t base = ((size_t)b * Sv) * DM + h * Dv;
    int gid = lane >> 2, tig = lane & 3;

    const __half* srcs[3] = {khi, klo, vh};

    // prefetch Q tile into stage 1, buffer 0
#pragma unroll
    for (int p = 0; p < 4; p++) {
        int idx = p * 128 + tid;
        int row = idx >> 3, c = idx & 7;
        cpa16(&smx[STG_ELEMS + row * KPAD + c * 8],
              qh + base + (size_t)(qg0 + row) * DM + c * 8);
    }
    cp_commit();
    // prefetch KV tile 0 into stage 0
#pragma unroll
    for (int p = 0; p < 12; p++) {
        int buf = p >> 2;
        int idx = ((p & 3) << 7) + tid;
        int row = idx >> 3, c = idx & 7;
        cpa16(&smx[buf * BUF_ELEMS + row * KPAD + c * 8],
              srcs[buf] + base + (size_t)row * DM + c * 8);
    }
    cp_commit();

    cp_wait<1>();
    __syncthreads();

    unsigned Qf[4][4];
    {
        int r = warp * 16 + (lane & 15);
        int c = (lane >> 4) << 3;
#pragma unroll
        for (int kt = 0; kt < 4; kt++) {
            unsigned a = (unsigned)__cvta_generic_to_shared(
                &smx[STG_ELEMS + r * KPAD + kt * 16 + c]);
            ldmx4(Qf[kt][0], Qf[kt][1], Qf[kt][2], Qf[kt][3], a);
        }
    }
    __syncthreads();

    int krow = (lane & 7) + ((lane >> 4) << 3);
    int kcol = ((lane >> 3) & 1) << 3;
    int vrow = (lane & 7) + (((lane >> 3) & 1) << 3);
    int vcol = (lane >> 4) << 3;

    float acc_o[8][4];
#pragma unroll
    for (int i = 0; i < 8; i++)
#pragma unroll
        for (int e = 0; e < 4; e++) acc_o[i][e] = 0.f;
    float lsum0 = 0.f, lsum1 = 0.f;
    int row0g = qg0 + warp * 16 + gid;

    int n = qt + 1;
    for (int j = 0; j < n; j++) {
        int s = j & 1;
        if (j + 1 < n) {
            int sb = (1 - s) * STG_ELEMS;
            size_t grow = base + (size_t)(j + 1) * 64 * DM;
#pragma unroll
            for (int p = 0; p < 12; p++) {
                int buf = p >> 2;
                int idx = ((p & 3) << 7) + tid;
                int row = idx >> 3, c = idx & 7;
                cpa16(&smx[sb + buf * BUF_ELEMS + row * KPAD + c * 8],
                      srcs[buf] + grow + (size_t)row * DM + c * 8);
            }
            cp_commit();
            cp_wait<1>();
        } else {
            cp_wait<0>();
        }
        __syncthreads();

        __half* Kh_ = smx + s * STG_ELEMS;
        __half* Kl_ = Kh_ + BUF_ELEMS;
        __half* Vh_ = Kh_ + 2 * BUF_ELEMS;

        // ---- S = q̂ (Kh + Kl)ᵀ ----
        float sc[8][4];
#pragma unroll
        for (int i = 0; i < 8; i++)
#pragma unroll
            for (int e = 0; e < 4; e++) sc[i][e] = 0.f;

#pragma unroll
        for (int kt = 0; kt < 4; kt++) {
            unsigned Kf[2][8][2];
#pragma unroll
            for (int ng = 0; ng < 4; ng++) {
                unsigned r0, r1, r2, r3;
                unsigned a = (unsigned)__cvta_generic_to_shared(
                    &Kh_[(ng * 16 + krow) * KPAD + kt * 16 + kcol]);
                ldmx4(r0, r1, r2, r3, a);
                Kf[0][ng * 2][0] = r0; Kf[0][ng * 2][1] = r1;
                Kf[0][ng * 2 + 1][0] = r2; Kf[0][ng * 2 + 1][1] = r3;
                a = (unsigned)__cvta_generic_to_shared(
                    &Kl_[(ng * 16 + krow) * KPAD + kt * 16 + kcol]);
                ldmx4(r0, r1, r2, r3, a);
                Kf[1][ng * 2][0] = r0; Kf[1][ng * 2][1] = r1;
                Kf[1][ng * 2 + 1][0] = r2; Kf[1][ng * 2 + 1][1] = r3;
            }
#pragma unroll
            for (int nt = 0; nt < 8; nt++) {
                mma16816h(sc[nt], Qf[kt], Kf[0][nt]);
                mma16816h(sc[nt], Qf[kt], Kf[1][nt]);
            }
        }

        // ---- P = exp2(S), causal zeroing, row sums ----
        if (j == qt) {
#pragma unroll
            for (int nt = 0; nt < 8; nt++) {
#pragma unroll
                for (int e = 0; e < 4; e++) {
                    int col = qg0 + nt * 8 + 2 * tig + (e & 1);
                    int row = row0g + ((e >> 1) << 3);
                    sc[nt][e] = (col > row) ? 0.f : ex2f(sc[nt][e]);
                }
                lsum0 += sc[nt][0] + sc[nt][1];
                lsum1 += sc[nt][2] + sc[nt][3];
            }
        } else {
#pragma unroll
            for (int nt = 0; nt < 8; nt++) {
                sc[nt][0] = ex2f(sc[nt][0]);
                sc[nt][1] = ex2f(sc[nt][1]);
                sc[nt][2] = ex2f(sc[nt][2]);
                sc[nt][3] = ex2f(sc[nt][3]);
                lsum0 += sc[nt][0] + sc[nt][1];
                lsum1 += sc[nt][2] + sc[nt][3];
            }
        }

        // ---- O += P̂ V̂ (single term) ----
#pragma unroll
        for (int kt = 0; kt < 4; kt++) {
            unsigned Ph[4];
#pragma unroll
            for (int half = 0; half < 2; half++) {
                int nt = 2 * kt + half;
                __half2 h0 = __floats2half2_rn(sc[nt][0], sc[nt][1]);
                __half2 h1 = __floats2half2_rn(sc[nt][2], sc[nt][3]);
                Ph[half * 2]     = *(unsigned*)&h0;
                Ph[half * 2 + 1] = *(unsigned*)&h1;
            }
            unsigned Vf[8][2];
#pragma unroll
            for (int dg = 0; dg < 4; dg++) {
                unsigned r0, r1, r2, r3;
                unsigned a = (unsigned)__cvta_generic_to_shared(
                    &Vh_[(kt * 16 + vrow) * KPAD + dg * 16 + vcol]);
                ldmx4t(r0, r1, r2, r3, a);
                Vf[dg * 2][0] = r0; Vf[dg * 2][1] = r1;
                Vf[dg * 2 + 1][0] = r2; Vf[dg * 2 + 1][1] = r3;
            }
#pragma unroll
            for (int dnt = 0; dnt < 8; dnt++)
                mma16816h(acc_o[dnt], Ph, Vf[dnt]);
        }
        __syncthreads();
    }

    // ---- epilogue ----
    lsum0 += __shfl_xor_sync(0xffffffffu, lsum0, 1);
    lsum0 += __shfl_xor_sync(0xffffffffu, lsum0, 2);
    lsum1 += __shfl_xor_sync(0xffffffffu, lsum1, 1);
    lsum1 += __shfl_xor_sync(0xffffffffu, lsum1, 2);
    float inv0 = 1.f / lsum0, inv1 = 1.f / lsum1;
    size_t o0 = ((size_t)b * Sv + row0g) * DM + h * Dv;
    size_t o1 = o0 + (size_t)8 * DM;
#pragma unroll
    for (int dnt = 0; dnt < 8; dnt++) {
        int col = dnt * 8 + 2 * tig;
        *(__half2*)&yh[o0 + col] =
            __floats2half2_rn(acc_o[dnt][0] * inv0, acc_o[dnt][1] * inv0);
        *(__half2*)&yh[o1 + col] =
            __floats2half2_rn(acc_o[dnt][2] * inv1, acc_o[dnt][3] * inv1);
    }
}

// ---------------------------------------------------------------------------
// kernel_launch
// ---------------------------------------------------------------------------
extern "C" void kernel_launch(void* const* d_in, const int* in_sizes, int n_in,
                              void* d_out, int out_size)
{
    const float* x  = (const float*)d_in[0];
    const float* Wq = (const float*)d_in[1];
    const float* bq = (const float*)d_in[2];
    const float* Wk = (const float*)d_in[3];
    const float* bk = (const float*)d_in[4];
    const float* Wv = (const float*)d_in[5];
    const float* bv = (const float*)d_in[6];
    const float* Wo = (const float*)d_in[7];
    const float* bo = (const float*)d_in[8];
    float* out = (float*)d_out;

    __half *xh, *yh, *whi, *wlo, *qh, *khi, *klo, *vh;
    cudaGetSymbolAddress((void**)&xh,  g_xh);
    cudaGetSymbolAddress((void**)&yh,  g_yh);
    cudaGetSymbolAddress((void**)&whi, g_whi);
    cudaGetSymbolAddress((void**)&wlo, g_wlo);
    cudaGetSymbolAddress((void**)&qh,  g_qh);
    cudaGetSymbolAddress((void**)&khi, g_khi);
    cudaGetSymbolAddress((void**)&klo, g_klo);
    cudaGetSymbolAddress((void**)&vh,  g_vh);

    cudaFuncSetAttribute(flash_mma,
                         cudaFuncAttributeMaxDynamicSharedMemorySize,
                         (int)FLASH_SMEM);

    const int NX = Mv * DM;
    const int NW = DM * DM;
    const float QSCL = 0.125f * 1.4426950408889634f;   // exp2 softmax

    // 1: rope tables
    rope_table_kernel<<<(Sv * 32 + 255) / 256, 256>>>();
    // 2: weight splits (fp16 hi/lo; lo used only by Wq, Wk)
    split4_half_kernel<<<(4 * NW + 255) / 256, 256>>>(Wq, Wk, Wv, Wo, whi, wlo, NW);
    // 3: x -> fp16
    tohalf_kernel<<<(NX + 255) / 256, 256>>>(x, xh, NX);

    dim3 gg(DM / 64, Mv / 128);
    // 4: Q = rope(x@Wq + bq) * QSCL  -> fp16       (2-term)
    gemm_t<2, 1><<<gg, 128>>>(xh, whi + 0 * NW, wlo + 0 * NW, bq,
                              qh, nullptr, nullptr, Mv, DM, DM, QSCL);
    // 5: K = rope(x@Wk + bk) -> fp16 hi/lo         (2-term)
    gemm_t<2, 2><<<gg, 128>>>(xh, whi + 1 * NW, wlo + 1 * NW, bk,
                              khi, klo, nullptr, Mv, DM, DM, 1.0f);
    // 6: V = (x@Wv + bv) -> fp16                   (1-term)
    gemm_t<1, 3><<<gg, 128>>>(xh, whi + 2 * NW, nullptr, bv,
                              vh, nullptr, nullptr, Mv, DM, DM, 1.0f);

    // 7: attention
    dim3 att_grid(Sv / 64, Hv, Bv);
    flash_mma<<<att_grid, 128, FLASH_SMEM>>>(qh, khi, klo, vh, yh);

    // 8: out = y@Wo + bo -> fp32                   (1-term)
    gemm_t<1, 0><<<gg, 128>>>(yh, whi + 3 * NW, nullptr, bo,
                              nullptr, nullptr, out, Mv, DM, DM, 1.0f);
}

// round 11
// speedup vs baseline: 7.2741x; 1.1863x over previous
#include <cuda_runtime.h>
#include <cuda_bf16.h>
#include <cuda_fp16.h>
#include <stdint.h>
#include <cstdint>
#include <math.h>

#define Bv 4
#define Sv 2048
#define Hv 16
#define Dv 64
#define DM 1024
#define Mv (Bv*Sv)   // 8192

// ---------------------------------------------------------------------------
// Scratch (allocation-free rule: __device__ globals)
// ---------------------------------------------------------------------------
__device__ float g_cos[Sv*32];
__device__ float g_sin[Sv*32];

__device__ __half g_xh [Mv*DM];
__device__ __half g_yh [Mv*DM];
__device__ __half g_whi[4*DM*DM];
__device__ __half g_wlo[4*DM*DM];
__device__ __half g_qh [Mv*DM];
__device__ __half g_kh [Mv*DM];
__device__ __half g_vh [Mv*DM];

// ---------------------------------------------------------------------------
// prep kernels
// ---------------------------------------------------------------------------
__global__ void tohalf_kernel(const float* __restrict__ s,
                              __half* __restrict__ o, int n)
{
    int i = blockIdx.x * blockDim.x + threadIdx.x;
    if (i >= n) return;
    o[i] = __float2half_rn(s[i]);
}

__global__ void split4_half_kernel(const float* __restrict__ s0, const float* __restrict__ s1,
                                   const float* __restrict__ s2, const float* __restrict__ s3,
                                   __half* __restrict__ hi,
                                   __half* __restrict__ lo, int n)
{
    int i = blockIdx.x * blockDim.x + threadIdx.x;
    if (i >= 4 * n) return;
    int w = i / n, r = i - w * n;
    const float* src = (w == 0) ? s0 : (w == 1) ? s1 : (w == 2) ? s2 : s3;
    float x = src[r];
    __half h = __float2half_rn(x);
    hi[i] = h;
    lo[i] = __float2half_rn(x - __half2float(h));
}

__global__ void rope_table_kernel() {
    int idx = blockIdx.x * blockDim.x + threadIdx.x;
    if (idx >= Sv * 32) return;
    int pos = idx >> 5;
    int i   = idx & 31;
    double inv = pow(10000.0, -(double)i / 32.0);
    double ang = (double)pos * inv;
    g_cos[idx] = (float)cos(ang);
    g_sin[idx] = (float)sin(ang);
}

// ---------------------------------------------------------------------------
// MMA / async-copy primitives
// ---------------------------------------------------------------------------
__device__ __forceinline__ void ldmx4(unsigned& r0, unsigned& r1,
                                      unsigned& r2, unsigned& r3, unsigned a) {
    asm volatile("ldmatrix.sync.aligned.m8n8.x4.shared.b16 {%0,%1,%2,%3}, [%4];"
        : "=r"(r0), "=r"(r1), "=r"(r2), "=r"(r3) : "r"(a));
}
__device__ __forceinline__ void ldmx4t(unsigned& r0, unsigned& r1,
                                       unsigned& r2, unsigned& r3, unsigned a) {
    asm volatile("ldmatrix.sync.aligned.m8n8.x4.trans.shared.b16 {%0,%1,%2,%3}, [%4];"
        : "=r"(r0), "=r"(r1), "=r"(r2), "=r"(r3) : "r"(a));
}
__device__ __forceinline__ void mma16816h(float* c, const unsigned* a, const unsigned* b) {
    asm volatile(
        "mma.sync.aligned.m16n8k16.row.col.f32.f16.f16.f32 "
        "{%0,%1,%2,%3}, {%4,%5,%6,%7}, {%8,%9}, {%0,%1,%2,%3};"
        : "+f"(c[0]), "+f"(c[1]), "+f"(c[2]), "+f"(c[3])
        : "r"(a[0]), "r"(a[1]), "r"(a[2]), "r"(a[3]), "r"(b[0]), "r"(b[1]));
}
__device__ __forceinline__ void cpa16(void* smem, const void* g) {
    unsigned s = (unsigned)__cvta_generic_to_shared(smem);
    asm volatile("cp.async.cg.shared.global [%0], [%1], 16;" :: "r"(s), "l"(g));
}
__device__ __forceinline__ void cp_commit() { asm volatile("cp.async.commit_group;"); }
template<int N> __device__ __forceinline__ void cp_wait() {
    asm volatile("cp.async.wait_group %0;" :: "n"(N));
}
__device__ __forceinline__ float ex2f(float x) {
    float y;
    asm("ex2.approx.ftz.f32 %0, %1;" : "=f"(y) : "f"(x));
    return y;
}

// ---------------------------------------------------------------------------
// GEMM with cp.async 2-stage pipeline: C = A(fp16) @ (Bhi [+ Blo]) + bias.
// MODE 0: fp32 out   MODE 1: rope*qscl -> fp16   MODE 3: fp16
// BM=128 BN=64 BK=32, 128 threads (4 warps 2x2), warp tile 64x32.
// ---------------------------------------------------------------------------
#define APAD 40
#define BPAD 72

template<int TERMS, int MODE>
__global__ __launch_bounds__(128) void gemm_t(
    const __half* __restrict__ Ah,
    const __half* __restrict__ Bhi, const __half* __restrict__ Blo,
    const float* __restrict__ bias,
    __half* __restrict__ C1, float* __restrict__ Cf,
    int M, int N, int K, float qscl)
{
    __shared__ __half As[2][128][APAD];
    __shared__ __half Bs[2][TERMS][32][BPAD];

    int tid  = threadIdx.x;
    int lane = tid & 31;
    int warp = tid >> 5;
    int wm = warp >> 1, wn = warp & 1;
    int bm = blockIdx.y << 7;
    int bn = blockIdx.x << 6;

    float acc[4][4][4];
#pragma unroll
    for (int i = 0; i < 4; i++)
#pragma unroll
        for (int j = 0; j < 4; j++)
#pragma unroll
            for (int e = 0; e < 4; e++) acc[i][j][e] = 0.f;

    int u0k = tid >> 3, u0n = (tid & 7) << 3;
    int u1k = u0k + 16, u1n = u0n;
    const __half* Ap0 = Ah + (size_t)(bm + tid) * K;

    // prologue: prefetch k-tile 0 into stage 0
#pragma unroll
    for (int i = 0; i < 4; i++)
        cpa16(&As[0][tid][i * 8], Ap0 + i * 8);
    cpa16(&Bs[0][0][u0k][u0n], Bhi + (size_t)u0k * N + bn + u0n);
    cpa16(&Bs[0][0][u1k][u1n], Bhi + (size_t)u1k * N + bn + u1n);
    if (TERMS == 2) {
        cpa16(&Bs[0][1][u0k][u0n], Blo + (size_t)u0k * N + bn + u0n);
        cpa16(&Bs[0][1][u1k][u1n], Blo + (size_t)u1k * N + bn + u1n);
    }
    cp_commit();

    int NKT = K >> 5;
    for (int kt = 0; kt < NKT; kt++) {
        int s = kt & 1;
        if (kt + 1 < NKT) {
            int k0 = (kt + 1) << 5;
            int sn = s ^ 1;
#pragma unroll
            for (int i = 0; i < 4; i++)
                cpa16(&As[sn][tid][i * 8], Ap0 + k0 + i * 8);
            cpa16(&Bs[sn][0][u0k][u0n], Bhi + (size_t)(k0 + u0k) * N + bn + u0n);
            cpa16(&Bs[sn][0][u1k][u1n], Bhi + (size_t)(k0 + u1k) * N + bn + u1n);
            if (TERMS == 2) {
                cpa16(&Bs[sn][1][u0k][u0n], Blo + (size_t)(k0 + u0k) * N + bn + u0n);
                cpa16(&Bs[sn][1][u1k][u1n], Blo + (size_t)(k0 + u1k) * N + bn + u1n);
            }
            cp_commit();
            cp_wait<1>();
        } else {
            cp_wait<0>();
        }
        __syncthreads();

#pragma unroll
        for (int ks = 0; ks < 2; ks++) {
            int k16 = ks << 4;
            unsigned Af[4][4];
            int ar = (lane & 15);
            int ac = k16 + ((lane >> 4) << 3);
#pragma unroll
            for (int mt = 0; mt < 4; mt++) {
                int m0 = wm * 64 + mt * 16;
                unsigned a0 = (unsigned)__cvta_generic_to_shared(&As[s][m0 + ar][ac]);
                ldmx4(Af[mt][0], Af[mt][1], Af[mt][2], Af[mt][3], a0);
            }
            unsigned Bf[TERMS][4][2];
            int bkr = k16 + (lane & 7) + (lane & 8);
#pragma unroll
            for (int p = 0; p < 2; p++) {
                int n0 = wn * 32 + p * 16 + (((lane >> 4) & 1) << 3);
                unsigned r0, r1, r2, r3;
                unsigned ad = (unsigned)__cvta_generic_to_shared(&Bs[s][0][bkr][n0]);
                ldmx4t(r0, r1, r2, r3, ad);
                Bf[0][p * 2][0] = r0; Bf[0][p * 2][1] = r1;
                Bf[0][p * 2 + 1][0] = r2; Bf[0][p * 2 + 1][1] = r3;
                if (TERMS == 2) {
                    ad = (unsigned)__cvta_generic_to_shared(&Bs[s][1][bkr][n0]);
                    ldmx4t(r0, r1, r2, r3, ad);
                    Bf[1][p * 2][0] = r0; Bf[1][p * 2][1] = r1;
                    Bf[1][p * 2 + 1][0] = r2; Bf[1][p * 2 + 1][1] = r3;
                }
            }
#pragma unroll
            for (int mt = 0; mt < 4; mt++)
#pragma unroll
                for (int nt = 0; nt < 4; nt++) {
                    mma16816h(acc[mt][nt], Af[mt], Bf[0][nt]);
                    if (TERMS == 2)
                        mma16816h(acc[mt][nt], Af[mt], Bf[1][nt]);
                }
        }
        __syncthreads();   // reads of stage s done before it is re-filled
    }

    // ---- fused epilogue ----
    int gid = lane >> 2, tq = lane & 3;
#pragma unroll
    for (int mt = 0; mt < 4; mt++) {
        int row = bm + wm * 64 + mt * 16 + gid;
#pragma unroll
        for (int nt = 0; nt < 4; nt++) {
            int col = bn + wn * 32 + nt * 8 + tq * 2;
            float b0 = bias[col], b1 = bias[col + 1];
            float v0 = acc[mt][nt][0] + b0;
            float v1 = acc[mt][nt][1] + b1;
            float v2 = acc[mt][nt][2] + b0;
            float v3 = acc[mt][nt][3] + b1;
            if (MODE == 0) {
                *(float2*)&Cf[(size_t)row * N + col] = make_float2(v0, v1);
                *(float2*)&Cf[(size_t)(row + 8) * N + col] = make_float2(v2, v3);
            } else if (MODE == 3) {
                *(__half2*)&C1[(size_t)row * N + col] = __floats2half2_rn(v0, v1);
                *(__half2*)&C1[(size_t)(row + 8) * N + col] = __floats2half2_rn(v2, v3);
            } else {
                int i = (col >> 1) & 31;
                int s1 = row & (Sv - 1);
                float c1 = g_cos[(s1 << 5) + i],       sn1 = g_sin[(s1 << 5) + i];
                float c2 = g_cos[((s1 + 8) << 5) + i], sn2 = g_sin[((s1 + 8) << 5) + i];
                float r0 = (v0 * c1 - v1 * sn1) * qscl;
                float r1 = (v1 * c1 + v0 * sn1) * qscl;
                float r2 = (v2 * c2 - v3 * sn2) * qscl;
                float r3 = (v3 * c2 + v2 * sn2) * qscl;
                *(__half2*)&C1[(size_t)row * N + col] = __floats2half2_rn(r0, r1);
                *(__half2*)&C1[(size_t)(row + 8) * N + col] = __floats2half2_rn(r2, r3);
            }
        }
    }
}

// ---------------------------------------------------------------------------
// Flash attention, causal: Q,K,P,V all single fp16; cp.async double-buffered;
// no-rescale exp2 softmax.
// ---------------------------------------------------------------------------
#define KPAD 72
#define BUF_ELEMS (64*KPAD)        // 4608 halves
#define STG_ELEMS (2*BUF_ELEMS)    // 9216
#define FLASH_SMEM (2*STG_ELEMS*sizeof(__half))  // 36864

__global__ __launch_bounds__(128) void flash_mma(
    const __half* __restrict__ qh, const __half* __restrict__ kh,
    const __half* __restrict__ vh,
    __half* __restrict__ yh)
{
    extern __shared__ __half smx[];

    int tid = threadIdx.x, lane = tid & 31, warp = tid >> 5;
    int qt = (int)gridDim.x - 1 - (int)blockIdx.x;
    int h = blockIdx.y, b = blockIdx.z;
    int qg0 = qt * 64;
    size_t base = ((size_t)b * Sv) * DM + h * Dv;
    int gid = lane >> 2, tig = lane & 3;

    const __half* srcs[2] = {kh, vh};

    // prefetch Q into stage 1, buffer 0
#pragma unroll
    for (int p = 0; p < 4; p++) {
        int idx = p * 128 + tid;
        int row = idx >> 3, c = idx & 7;
        cpa16(&smx[STG_ELEMS + row * KPAD + c * 8],
              qh + base + (size_t)(qg0 + row) * DM + c * 8);
    }
    cp_commit();
    // prefetch KV tile 0 into stage 0
#pragma unroll
    for (int p = 0; p < 8; p++) {
        int buf = p >> 2;
        int idx = ((p & 3) << 7) + tid;
        int row = idx >> 3, c = idx & 7;
        cpa16(&smx[buf * BUF_ELEMS + row * KPAD + c * 8],
              srcs[buf] + base + (size_t)row * DM + c * 8);
    }
    cp_commit();

    cp_wait<1>();
    __syncthreads();

    unsigned Qf[4][4];
    {
        int r = warp * 16 + (lane & 15);
        int c = (lane >> 4) << 3;
#pragma unroll
        for (int kt = 0; kt < 4; kt++) {
            unsigned a = (unsigned)__cvta_generic_to_shared(
                &smx[STG_ELEMS + r * KPAD + kt * 16 + c]);
            ldmx4(Qf[kt][0], Qf[kt][1], Qf[kt][2], Qf[kt][3], a);
        }
    }
    __syncthreads();

    int krow = (lane & 7) + ((lane >> 4) << 3);
    int kcol = ((lane >> 3) & 1) << 3;
    int vrow = (lane & 7) + (((lane >> 3) & 1) << 3);
    int vcol = (lane >> 4) << 3;

    float acc_o[8][4];
#pragma unroll
    for (int i = 0; i < 8; i++)
#pragma unroll
        for (int e = 0; e < 4; e++) acc_o[i][e] = 0.f;
    float lsum0 = 0.f, lsum1 = 0.f;
    int row0g = qg0 + warp * 16 + gid;

    int n = qt + 1;
    for (int j = 0; j < n; j++) {
        int s = j & 1;
        if (j + 1 < n) {
            int sb = (1 - s) * STG_ELEMS;
            size_t grow = base + (size_t)(j + 1) * 64 * DM;
#pragma unroll
            for (int p = 0; p < 8; p++) {
                int buf = p >> 2;
                int idx = ((p & 3) << 7) + tid;
                int row = idx >> 3, c = idx & 7;
                cpa16(&smx[sb + buf * BUF_ELEMS + row * KPAD + c * 8],
                      srcs[buf] + grow + (size_t)row * DM + c * 8);
            }
            cp_commit();
            cp_wait<1>();
        } else {
            cp_wait<0>();
        }
        __syncthreads();

        __half* Kh_ = smx + s * STG_ELEMS;
        __half* Vh_ = Kh_ + BUF_ELEMS;

        // ---- S = q̂ k̂ᵀ (single term) ----
        float sc[8][4];
#pragma unroll
        for (int i = 0; i < 8; i++)
#pragma unroll
            for (int e = 0; e < 4; e++) sc[i][e] = 0.f;

#pragma unroll
        for (int kt = 0; kt < 4; kt++) {
            unsigned Kf[8][2];
#pragma unroll
            for (int ng = 0; ng < 4; ng++) {
                unsigned r0, r1, r2, r3;
                unsigned a = (unsigned)__cvta_generic_to_shared(
                    &Kh_[(ng * 16 + krow) * KPAD + kt * 16 + kcol]);
                ldmx4(r0, r1, r2, r3, a);
                Kf[ng * 2][0] = r0; Kf[ng * 2][1] = r1;
                Kf[ng * 2 + 1][0] = r2; Kf[ng * 2 + 1][1] = r3;
            }
#pragma unroll
            for (int nt = 0; nt < 8; nt++)
                mma16816h(sc[nt], Qf[kt], Kf[nt]);
        }

        // ---- P = exp2(S), causal zeroing, row sums ----
        if (j == qt) {
#pragma unroll
            for (int nt = 0; nt < 8; nt++) {
#pragma unroll
                for (int e = 0; e < 4; e++) {
                    int col = qg0 + nt * 8 + 2 * tig + (e & 1);
                    int row = row0g + ((e >> 1) << 3);
                    sc[nt][e] = (col > row) ? 0.f : ex2f(sc[nt][e]);
                }
                lsum0 += sc[nt][0] + sc[nt][1];
                lsum1 += sc[nt][2] + sc[nt][3];
            }
        } else {
#pragma unroll
            for (int nt = 0; nt < 8; nt++) {
                sc[nt][0] = ex2f(sc[nt][0]);
                sc[nt][1] = ex2f(sc[nt][1]);
                sc[nt][2] = ex2f(sc[nt][2]);
                sc[nt][3] = ex2f(sc[nt][3]);
                lsum0 += sc[nt][0] + sc[nt][1];
                lsum1 += sc[nt][2] + sc[nt][3];
            }
        }

        // ---- O += P̂ V̂ ----
#pragma unroll
        for (int kt = 0; kt < 4; kt++) {
            unsigned Ph[4];
#pragma unroll
            for (int half = 0; half < 2; half++) {
                int nt = 2 * kt + half;
                __half2 h0 = __floats2half2_rn(sc[nt][0], sc[nt][1]);
                __half2 h1 = __floats2half2_rn(sc[nt][2], sc[nt][3]);
                Ph[half * 2]     = *(unsigned*)&h0;
                Ph[half * 2 + 1] = *(unsigned*)&h1;
            }
            unsigned Vf[8][2];
#pragma unroll
            for (int dg = 0; dg < 4; dg++) {
                unsigned r0, r1, r2, r3;
                unsigned a = (unsigned)__cvta_generic_to_shared(
                    &Vh_[(kt * 16 + vrow) * KPAD + dg * 16 + vcol]);
                ldmx4t(r0, r1, r2, r3, a);
                Vf[dg * 2][0] = r0; Vf[dg * 2][1] = r1;
                Vf[dg * 2 + 1][0] = r2; Vf[dg * 2 + 1][1] = r3;
            }
#pragma unroll
            for (int dnt = 0; dnt < 8; dnt++)
                mma16816h(acc_o[dnt], Ph, Vf[dnt]);
        }
        __syncthreads();
    }

    // ---- epilogue ----
    lsum0 += __shfl_xor_sync(0xffffffffu, lsum0, 1);
    lsum0 += __shfl_xor_sync(0xffffffffu, lsum0, 2);
    lsum1 += __shfl_xor_sync(0xffffffffu, lsum1, 1);
    lsum1 += __shfl_xor_sync(0xffffffffu, lsum1, 2);
    float inv0 = 1.f / lsum0, inv1 = 1.f / lsum1;
    size_t o0 = ((size_t)b * Sv + row0g) * DM + h * Dv;
    size_t o1 = o0 + (size_t)8 * DM;
#pragma unroll
    for (int dnt = 0; dnt < 8; dnt++) {
        int col = dnt * 8 + 2 * tig;
        *(__half2*)&yh[o0 + col] =
            __floats2half2_rn(acc_o[dnt][0] * inv0, acc_o[dnt][1] * inv0);
        *(__half2*)&yh[o1 + col] =
            __floats2half2_rn(acc_o[dnt][2] * inv1, acc_o[dnt][3] * inv1);
    }
}

// ---------------------------------------------------------------------------
// kernel_launch
// ---------------------------------------------------------------------------
extern "C" void kernel_launch(void* const* d_in, const int* in_sizes, int n_in,
                              void* d_out, int out_size)
{
    const float* x  = (const float*)d_in[0];
    const float* Wq = (const float*)d_in[1];
    const float* bq = (const float*)d_in[2];
    const float* Wk = (const float*)d_in[3];
    const float* bk = (const float*)d_in[4];
    const float* Wv = (const float*)d_in[5];
    const float* bv = (const float*)d_in[6];
    const float* Wo = (const float*)d_in[7];
    const float* bo = (const float*)d_in[8];
    float* out = (float*)d_out;

    __half *xh, *yh, *whi, *wlo, *qh, *kh, *vh;
    cudaGetSymbolAddress((void**)&xh,  g_xh);
    cudaGetSymbolAddress((void**)&yh,  g_yh);
    cudaGetSymbolAddress((void**)&whi, g_whi);
    cudaGetSymbolAddress((void**)&wlo, g_wlo);
    cudaGetSymbolAddress((void**)&qh,  g_qh);
    cudaGetSymbolAddress((void**)&kh,  g_kh);
    cudaGetSymbolAddress((void**)&vh,  g_vh);

    cudaFuncSetAttribute(flash_mma,
                         cudaFuncAttributeMaxDynamicSharedMemorySize,
                         (int)FLASH_SMEM);

    const int NX = Mv * DM;
    const int NW = DM * DM;
    const float QSCL = 0.125f * 1.4426950408889634f;   // exp2 softmax

    // 1: rope tables
    rope_table_kernel<<<(Sv * 32 + 255) / 256, 256>>>();
    // 2: weight splits (lo used only by Wq, Wk)
    split4_half_kernel<<<(4 * NW + 255) / 256, 256>>>(Wq, Wk, Wv, Wo, whi, wlo, NW);
    // 3: x -> fp16
    tohalf_kernel<<<(NX + 255) / 256, 256>>>(x, xh, NX);

    dim3 gg(DM / 64, Mv / 128);
    // 4: Q = rope(x@Wq + bq) * QSCL -> fp16   (2-term)
    gemm_t<2, 1><<<gg, 128>>>(xh, whi + 0 * NW, wlo + 0 * NW, bq,
                              qh, nullptr, Mv, DM, DM, QSCL);
    // 5: K = rope(x@Wk + bk) -> fp16          (2-term)
    gemm_t<2, 1><<<gg, 128>>>(xh, whi + 1 * NW, wlo + 1 * NW, bk,
                              kh, nullptr, Mv, DM, DM, 1.0f);
    // 6: V = (x@Wv + bv) -> fp16              (1-term)
    gemm_t<1, 3><<<gg, 128>>>(xh, whi + 2 * NW, nullptr, bv,
                              vh, nullptr, Mv, DM, DM, 1.0f);

    // 7: attention
    dim3 att_grid(Sv / 64, Hv, Bv);
    flash_mma<<<att_grid, 128, FLASH_SMEM>>>(qh, kh, vh, yh);

    // 8: out = y@Wo + bo -> fp32              (1-term)
    gemm_t<1, 0><<<gg, 128>>>(yh, whi + 3 * NW, nullptr, bo,
                              nullptr, out, Mv, DM, DM, 1.0f);
}

// round 12
// speedup vs baseline: 7.8596x; 1.0805x over previous
#include <cuda_runtime.h>
#include <cuda_bf16.h>
#include <cuda_fp16.h>
#include <stdint.h>
#include <cstdint>
#include <math.h>

#define Bv 4
#define Sv 2048
#define Hv 16
#define Dv 64
#define DM 1024
#define Mv (Bv*Sv)   // 8192

// ---------------------------------------------------------------------------
// Scratch
// ---------------------------------------------------------------------------
__device__ float g_cos[Sv*32];
__device__ float g_sin[Sv*32];

__device__ __half g_xh [Mv*DM];
__device__ __half g_yh [Mv*DM];
__device__ __half g_whi[4*DM*DM];
__device__ __half g_wlo[4*DM*DM];
__device__ __half g_qh [Mv*DM];
__device__ __half g_kh [Mv*DM];
__device__ __half g_vh [Mv*DM];

// ---------------------------------------------------------------------------
// prep kernels
// ---------------------------------------------------------------------------
__global__ void tohalf_kernel(const float* __restrict__ s,
                              __half* __restrict__ o, int n)
{
    int i = blockIdx.x * blockDim.x + threadIdx.x;
    if (i >= n) return;
    o[i] = __float2half_rn(s[i]);
}

__global__ void split4_half_kernel(const float* __restrict__ s0, const float* __restrict__ s1,
                                   const float* __restrict__ s2, const float* __restrict__ s3,
                                   __half* __restrict__ hi,
                                   __half* __restrict__ lo, int n)
{
    int i = blockIdx.x * blockDim.x + threadIdx.x;
    if (i >= 4 * n) return;
    int w = i / n, r = i - w * n;
    const float* src = (w == 0) ? s0 : (w == 1) ? s1 : (w == 2) ? s2 : s3;
    float x = src[r];
    __half h = __float2half_rn(x);
    hi[i] = h;
    lo[i] = __float2half_rn(x - __half2float(h));
}

__global__ void rope_table_kernel() {
    int idx = blockIdx.x * blockDim.x + threadIdx.x;
    if (idx >= Sv * 32) return;
    int pos = idx >> 5;
    int i   = idx & 31;
    double inv = pow(10000.0, -(double)i / 32.0);
    double ang = (double)pos * inv;
    g_cos[idx] = (float)cos(ang);
    g_sin[idx] = (float)sin(ang);
}

// ---------------------------------------------------------------------------
// primitives
// ---------------------------------------------------------------------------
__device__ __forceinline__ void ldmx4(unsigned& r0, unsigned& r1,
                                      unsigned& r2, unsigned& r3, unsigned a) {
    asm volatile("ldmatrix.sync.aligned.m8n8.x4.shared.b16 {%0,%1,%2,%3}, [%4];"
        : "=r"(r0), "=r"(r1), "=r"(r2), "=r"(r3) : "r"(a));
}
__device__ __forceinline__ void ldmx4t(unsigned& r0, unsigned& r1,
                                       unsigned& r2, unsigned& r3, unsigned a) {
    asm volatile("ldmatrix.sync.aligned.m8n8.x4.trans.shared.b16 {%0,%1,%2,%3}, [%4];"
        : "=r"(r0), "=r"(r1), "=r"(r2), "=r"(r3) : "r"(a));
}
__device__ __forceinline__ void mma16816h(float* c, const unsigned* a, const unsigned* b) {
    asm volatile(
        "mma.sync.aligned.m16n8k16.row.col.f32.f16.f16.f32 "
        "{%0,%1,%2,%3}, {%4,%5,%6,%7}, {%8,%9}, {%0,%1,%2,%3};"
        : "+f"(c[0]), "+f"(c[1]), "+f"(c[2]), "+f"(c[3])
        : "r"(a[0]), "r"(a[1]), "r"(a[2]), "r"(a[3]), "r"(b[0]), "r"(b[1]));
}
__device__ __forceinline__ void cpa16(void* smem, const void* g) {
    unsigned s = (unsigned)__cvta_generic_to_shared(smem);
    asm volatile("cp.async.cg.shared.global [%0], [%1], 16;" :: "r"(s), "l"(g));
}
__device__ __forceinline__ void cp_commit() { asm volatile("cp.async.commit_group;"); }
template<int N> __device__ __forceinline__ void cp_wait() {
    asm volatile("cp.async.wait_group %0;" :: "n"(N));
}
__device__ __forceinline__ float ex2f(float x) {
    float y;
    asm("ex2.approx.ftz.f32 %0, %1;" : "=f"(y) : "f"(x));
    return y;
}

#define APAD 40

// ---------------------------------------------------------------------------
// Fused QKV GEMM: 256 threads, BM=128 BN=128 BK=32, 2-stage cp.async.
// grid.x = 24: [0,8)=Q [8,16)=K [16,24)=V. V skips the W-lo term.
// Q/K epilogue: rope (+qscl for Q) -> fp16.  V epilogue: fp16.
// dynamic smem: As 2x128x40 halves, Bs 2stage x 2term x 32 x 136 halves.
// ---------------------------------------------------------------------------
#define BPAD2 136
#define AS_OFF(s, r, c)      ((s) * 5120 + (r) * APAD + (c))
#define BS_OFF(s, t, r, c)   (10240 + (((s) * 2 + (t)) * 4352) + (r) * BPAD2 + (c))
#define QKV_SMEM ((10240 + 4 * 4352) * sizeof(__half))   // 55296 B

__global__ __launch_bounds__(256) void gemm_qkv(
    const __half* __restrict__ xh,
    const __half* __restrict__ whi, const __half* __restrict__ wlo,
    const float* __restrict__ bq, const float* __restrict__ bk,
    const float* __restrict__ bv,
    __half* __restrict__ qout, __half* __restrict__ kout,
    __half* __restrict__ vout, float qscl)
{
    extern __shared__ __half sm[];

    int tid = threadIdx.x, lane = tid & 31, warp = tid >> 5;
    int wm = warp >> 2, wn = warp & 3;
    int bx = blockIdx.x;
    int w = bx >> 3;
    int bn = (bx & 7) << 7;
    int bm = blockIdx.y << 7;
    bool two = (w < 2);
    const __half* Bhi = whi + (size_t)w * DM * DM;
    const __half* Blo = wlo + (size_t)w * DM * DM;
    const float* bias = (w == 0) ? bq : (w == 1) ? bk : bv;
    __half* Cout = (w == 0) ? qout : (w == 1) ? kout : vout;

    float acc[4][4][4];
#pragma unroll
    for (int i = 0; i < 4; i++)
#pragma unroll
        for (int j = 0; j < 4; j++)
#pragma unroll
            for (int e = 0; e < 4; e++) acc[i][j][e] = 0.f;

    // B loaders: 512 uint4 per term per k-tile; 2 per thread per term
    int u0k = tid >> 4, u0n = (tid & 15) << 3;
    int u1k = u0k + 16;
    // A loaders: 512 uint4 per k-tile; 2 per thread
    int arow = tid >> 1;
    int ac0 = (tid & 1) << 4;
    const __half* Ap0 = xh + (size_t)(bm + arow) * DM;

    // prologue: k-tile 0 into stage 0
    cpa16(&sm[AS_OFF(0, arow, ac0)],     Ap0 + ac0);
    cpa16(&sm[AS_OFF(0, arow, ac0 + 8)], Ap0 + ac0 + 8);
    cpa16(&sm[BS_OFF(0, 0, u0k, u0n)], Bhi + (size_t)u0k * DM + bn + u0n);
    cpa16(&sm[BS_OFF(0, 0, u1k, u0n)], Bhi + (size_t)u1k * DM + bn + u0n);
    if (two) {
        cpa16(&sm[BS_OFF(0, 1, u0k, u0n)], Blo + (size_t)u0k * DM + bn + u0n);
        cpa16(&sm[BS_OFF(0, 1, u1k, u0n)], Blo + (size_t)u1k * DM + bn + u0n);
    }
    cp_commit();

    const int NKT = DM >> 5;   // 32
    for (int kt = 0; kt < NKT; kt++) {
        int s = kt & 1;
        if (kt + 1 < NKT) {
            int k0 = (kt + 1) << 5;
            int sn = s ^ 1;
            cpa16(&sm[AS_OFF(sn, arow, ac0)],     Ap0 + k0 + ac0);
            cpa16(&sm[AS_OFF(sn, arow, ac0 + 8)], Ap0 + k0 + ac0 + 8);
            cpa16(&sm[BS_OFF(sn, 0, u0k, u0n)], Bhi + (size_t)(k0 + u0k) * DM + bn + u0n);
            cpa16(&sm[BS_OFF(sn, 0, u1k, u0n)], Bhi + (size_t)(k0 + u1k) * DM + bn + u0n);
            if (two) {
                cpa16(&sm[BS_OFF(sn, 1, u0k, u0n)], Blo + (size_t)(k0 + u0k) * DM + bn + u0n);
                cpa16(&sm[BS_OFF(sn, 1, u1k, u0n)], Blo + (size_t)(k0 + u1k) * DM + bn + u0n);
            }
            cp_commit();
            cp_wait<1>();
        } else {
            cp_wait<0>();
        }
        __syncthreads();

#pragma unroll
        for (int ks = 0; ks < 2; ks++) {
            int k16 = ks << 4;
            unsigned Af[4][4];
            int ar = (lane & 15);
            int ac = k16 + ((lane >> 4) << 3);
#pragma unroll
            for (int mt = 0; mt < 4; mt++) {
                int m0 = wm * 64 + mt * 16;
                unsigned a0 = (unsigned)__cvta_generic_to_shared(
                    &sm[AS_OFF(s, m0 + ar, ac)]);
                ldmx4(Af[mt][0], Af[mt][1], Af[mt][2], Af[mt][3], a0);
            }
            unsigned Bf[2][4][2];
            int bkr = k16 + (lane & 7) + (lane & 8);
#pragma unroll
            for (int p = 0; p < 2; p++) {
                int n0 = wn * 32 + p * 16 + (((lane >> 4) & 1) << 3);
                unsigned r0, r1, r2, r3;
                unsigned ad = (unsigned)__cvta_generic_to_shared(
                    &sm[BS_OFF(s, 0, bkr, n0)]);
                ldmx4t(r0, r1, r2, r3, ad);
                Bf[0][p * 2][0] = r0; Bf[0][p * 2][1] = r1;
                Bf[0][p * 2 + 1][0] = r2; Bf[0][p * 2 + 1][1] = r3;
                if (two) {
                    ad = (unsigned)__cvta_generic_to_shared(
                        &sm[BS_OFF(s, 1, bkr, n0)]);
                    ldmx4t(r0, r1, r2, r3, ad);
                    Bf[1][p * 2][0] = r0; Bf[1][p * 2][1] = r1;
                    Bf[1][p * 2 + 1][0] = r2; Bf[1][p * 2 + 1][1] = r3;
                }
            }
#pragma unroll
            for (int mt = 0; mt < 4; mt++)
#pragma unroll
                for (int nt = 0; nt < 4; nt++) {
                    mma16816h(acc[mt][nt], Af[mt], Bf[0][nt]);
                    if (two)
                        mma16816h(acc[mt][nt], Af[mt], Bf[1][nt]);
                }
        }
        __syncthreads();
    }

    // ---- epilogue ----
    int gid = lane >> 2, tq = lane & 3;
    float scl = (w == 0) ? qscl : 1.0f;
#pragma unroll
    for (int mt = 0; mt < 4; mt++) {
        int row = bm + wm * 64 + mt * 16 + gid;
#pragma unroll
        for (int nt = 0; nt < 4; nt++) {
            int col = bn + wn * 32 + nt * 8 + tq * 2;
            float b0 = bias[col], b1 = bias[col + 1];
            float v0 = acc[mt][nt][0] + b0;
            float v1 = acc[mt][nt][1] + b1;
            float v2 = acc[mt][nt][2] + b0;
            float v3 = acc[mt][nt][3] + b1;
            if (w == 2) {
                *(__half2*)&Cout[(size_t)row * DM + col] = __floats2half2_rn(v0, v1);
                *(__half2*)&Cout[(size_t)(row + 8) * DM + col] = __floats2half2_rn(v2, v3);
            } else {
                int i = (col >> 1) & 31;
                int s1 = row & (Sv - 1);
                float c1 = g_cos[(s1 << 5) + i],       sn1 = g_sin[(s1 << 5) + i];
                float c2 = g_cos[((s1 + 8) << 5) + i], sn2 = g_sin[((s1 + 8) << 5) + i];
                float r0 = (v0 * c1 - v1 * sn1) * scl;
                float r1 = (v1 * c1 + v0 * sn1) * scl;
                float r2 = (v2 * c2 - v3 * sn2) * scl;
                float r3 = (v3 * c2 + v2 * sn2) * scl;
                *(__half2*)&Cout[(size_t)row * DM + col] = __floats2half2_rn(r0, r1);
                *(__half2*)&Cout[(size_t)(row + 8) * DM + col] = __floats2half2_rn(r2, r3);
            }
        }
    }
}

// ---------------------------------------------------------------------------
// O-projection GEMM (128 threads, BM=128 BN=64, 1-term, fp32 out) — unchanged
// ---------------------------------------------------------------------------
#define BPAD 72

__global__ __launch_bounds__(128) void gemm_o(
    const __half* __restrict__ Ah, const __half* __restrict__ Bhi,
    const float* __restrict__ bias, float* __restrict__ Cf,
    int M, int N, int K)
{
    __shared__ __half As[2][128][APAD];
    __shared__ __half Bs[2][32][BPAD];

    int tid  = threadIdx.x;
    int lane = tid & 31;
    int warp = tid >> 5;
    int wm = warp >> 1, wn = warp & 1;
    int bm = blockIdx.y << 7;
    int bn = blockIdx.x << 6;

    float acc[4][4][4];
#pragma unroll
    for (int i = 0; i < 4; i++)
#pragma unroll
        for (int j = 0; j < 4; j++)
#pragma unroll
            for (int e = 0; e < 4; e++) acc[i][j][e] = 0.f;

    int u0k = tid >> 3, u0n = (tid & 7) << 3;
    int u1k = u0k + 16;
    const __half* Ap0 = Ah + (size_t)(bm + tid) * K;

#pragma unroll
    for (int i = 0; i < 4; i++)
        cpa16(&As[0][tid][i * 8], Ap0 + i * 8);
    cpa16(&Bs[0][u0k][u0n], Bhi + (size_t)u0k * N + bn + u0n);
    cpa16(&Bs[0][u1k][u0n], Bhi + (size_t)u1k * N + bn + u0n);
    cp_commit();

    int NKT = K >> 5;
    for (int kt = 0; kt < NKT; kt++) {
        int s = kt & 1;
        if (kt + 1 < NKT) {
            int k0 = (kt + 1) << 5;
            int sn = s ^ 1;
#pragma unroll
            for (int i = 0; i < 4; i++)
                cpa16(&As[sn][tid][i * 8], Ap0 + k0 + i * 8);
            cpa16(&Bs[sn][u0k][u0n], Bhi + (size_t)(k0 + u0k) * N + bn + u0n);
            cpa16(&Bs[sn][u1k][u0n], Bhi + (size_t)(k0 + u1k) * N + bn + u0n);
            cp_commit();
            cp_wait<1>();
        } else {
            cp_wait<0>();
        }
        __syncthreads();

#pragma unroll
        for (int ks = 0; ks < 2; ks++) {
            int k16 = ks << 4;
            unsigned Af[4][4];
            int ar = (lane & 15);
            int ac = k16 + ((lane >> 4) << 3);
#pragma unroll
            for (int mt = 0; mt < 4; mt++) {
                int m0 = wm * 64 + mt * 16;
                unsigned a0 = (unsigned)__cvta_generic_to_shared(&As[s][m0 + ar][ac]);
                ldmx4(Af[mt][0], Af[mt][1], Af[mt][2], Af[mt][3], a0);
            }
            unsigned Bf[4][2];
            int bkr = k16 + (lane & 7) + (lane & 8);
#pragma unroll
            for (int p = 0; p < 2; p++) {
                int n0 = wn * 32 + p * 16 + (((lane >> 4) & 1) << 3);
                unsigned r0, r1, r2, r3;
                unsigned ad = (unsigned)__cvta_generic_to_shared(&Bs[s][bkr][n0]);
                ldmx4t(r0, r1, r2, r3, ad);
                Bf[p * 2][0] = r0; Bf[p * 2][1] = r1;
                Bf[p * 2 + 1][0] = r2; Bf[p * 2 + 1][1] = r3;
            }
#pragma unroll
            for (int mt = 0; mt < 4; mt++)
#pragma unroll
                for (int nt = 0; nt < 4; nt++)
                    mma16816h(acc[mt][nt], Af[mt], Bf[nt]);
        }
        __syncthreads();
    }

    int gid = lane >> 2, tq = lane & 3;
#pragma unroll
    for (int mt = 0; mt < 4; mt++) {
        int row = bm + wm * 64 + mt * 16 + gid;
#pragma unroll
        for (int nt = 0; nt < 4; nt++) {
            int col = bn + wn * 32 + nt * 8 + tq * 2;
            float b0 = bias[col], b1 = bias[col + 1];
            *(float2*)&Cf[(size_t)row * N + col] =
                make_float2(acc[mt][nt][0] + b0, acc[mt][nt][1] + b1);
            *(float2*)&Cf[(size_t)(row + 8) * N + col] =
                make_float2(acc[mt][nt][2] + b0, acc[mt][nt][3] + b1);
        }
    }
}

// ---------------------------------------------------------------------------
// Flash attention: 256 threads (8 warps), Q tile 128 rows, KV tile 64,
// all fp16 single-term, cp.async double-buffered, no-rescale exp2 softmax.
// ---------------------------------------------------------------------------
#define KPAD 72
#define BUF_ELEMS (64*KPAD)        // 4608 halves
#define STG_ELEMS (2*BUF_ELEMS)    // 9216
#define FLASH_SMEM (2*STG_ELEMS*sizeof(__half))  // 36864

__global__ __launch_bounds__(256) void flash_mma(
    const __half* __restrict__ qh, const __half* __restrict__ kh,
    const __half* __restrict__ vh,
    __half* __restrict__ yh)
{
    extern __shared__ __half smx[];

    int tid = threadIdx.x, lane = tid & 31, warp = tid >> 5;
    int qt = (int)gridDim.x - 1 - (int)blockIdx.x;   // heavy first
    int h = blockIdx.y, b = blockIdx.z;
    int qg0 = qt * 128;
    size_t base = ((size_t)b * Sv) * DM + h * Dv;
    int gid = lane >> 2, tig = lane & 3;

    const __half* srcs[2] = {kh, vh};

    // prefetch Q (128x64) into stage 1 (exactly STG_ELEMS halves)
#pragma unroll
    for (int p = 0; p < 4; p++) {
        int idx = p * 256 + tid;        // 0..1023
        int row = idx >> 3, c = idx & 7;
        cpa16(&smx[STG_ELEMS + row * KPAD + c * 8],
              qh + base + (size_t)(qg0 + row) * DM + c * 8);
    }
    cp_commit();
    // prefetch KV tile 0 into stage 0
#pragma unroll
    for (int p = 0; p < 4; p++) {
        int buf = p >> 1;
        int idx = ((p & 1) << 8) + tid;  // 0..511
        int row = idx >> 3, c = idx & 7;
        cpa16(&smx[buf * BUF_ELEMS + row * KPAD + c * 8],
              srcs[buf] + base + (size_t)row * DM + c * 8);
    }
    cp_commit();

    cp_wait<1>();
    __syncthreads();

    unsigned Qf[4][4];
    {
        int r = warp * 16 + (lane & 15);
        int c = (lane >> 4) << 3;
#pragma unroll
        for (int kt = 0; kt < 4; kt++) {
            unsigned a = (unsigned)__cvta_generic_to_shared(
                &smx[STG_ELEMS + r * KPAD + kt * 16 + c]);
            ldmx4(Qf[kt][0], Qf[kt][1], Qf[kt][2], Qf[kt][3], a);
        }
    }
    __syncthreads();

    int krow = (lane & 7) + ((lane >> 4) << 3);
    int kcol = ((lane >> 3) & 1) << 3;
    int vrow = (lane & 7) + (((lane >> 3) & 1) << 3);
    int vcol = (lane >> 4) << 3;

    float acc_o[8][4];
#pragma unroll
    for (int i = 0; i < 8; i++)
#pragma unroll
        for (int e = 0; e < 4; e++) acc_o[i][e] = 0.f;
    float lsum0 = 0.f, lsum1 = 0.f;
    int row0g = qg0 + warp * 16 + gid;

    int n = 2 * qt + 2;
    for (int j = 0; j < n; j++) {
        int s = j & 1;
        if (j + 1 < n) {
            int sb = (1 - s) * STG_ELEMS;
            size_t grow = base + (size_t)(j + 1) * 64 * DM;
#pragma unroll
            for (int p = 0; p < 4; p++) {
                int buf = p >> 1;
                int idx = ((p & 1) << 8) + tid;
                int row = idx >> 3, c = idx & 7;
                cpa16(&smx[sb + buf * BUF_ELEMS + row * KPAD + c * 8],
                      srcs[buf] + grow + (size_t)row * DM + c * 8);
            }
            cp_commit();
            cp_wait<1>();
        } else {
            cp_wait<0>();
        }
        __syncthreads();

        __half* Kh_ = smx + s * STG_ELEMS;
        __half* Vh_ = Kh_ + BUF_ELEMS;

        // ---- S = q̂ k̂ᵀ ----
        float sc[8][4];
#pragma unroll
        for (int i = 0; i < 8; i++)
#pragma unroll
            for (int e = 0; e < 4; e++) sc[i][e] = 0.f;

#pragma unroll
        for (int kt = 0; kt < 4; kt++) {
            unsigned Kf[8][2];
#pragma unroll
            for (int ng = 0; ng < 4; ng++) {
                unsigned r0, r1, r2, r3;
                unsigned a = (unsigned)__cvta_generic_to_shared(
                    &Kh_[(ng * 16 + krow) * KPAD + kt * 16 + kcol]);
                ldmx4(r0, r1, r2, r3, a);
                Kf[ng * 2][0] = r0; Kf[ng * 2][1] = r1;
                Kf[ng * 2 + 1][0] = r2; Kf[ng * 2 + 1][1] = r3;
            }
#pragma unroll
            for (int nt = 0; nt < 8; nt++)
                mma16816h(sc[nt], Qf[kt], Kf[nt]);
        }

        // ---- P = exp2(S), causal zeroing on last two tiles, row sums ----
        if (j >= 2 * qt) {
#pragma unroll
            for (int nt = 0; nt < 8; nt++) {
#pragma unroll
                for (int e = 0; e < 4; e++) {
                    int col = j * 64 + nt * 8 + 2 * tig + (e & 1);
                    int row = row0g + ((e >> 1) << 3);
                    sc[nt][e] = (col > row) ? 0.f : ex2f(sc[nt][e]);
                }
                lsum0 += sc[nt][0] + sc[nt][1];
                lsum1 += sc[nt][2] + sc[nt][3];
            }
        } else {
#pragma unroll
            for (int nt = 0; nt < 8; nt++) {
                sc[nt][0] = ex2f(sc[nt][0]);
                sc[nt][1] = ex2f(sc[nt][1]);
                sc[nt][2] = ex2f(sc[nt][2]);
                sc[nt][3] = ex2f(sc[nt][3]);
                lsum0 += sc[nt][0] + sc[nt][1];
                lsum1 += sc[nt][2] + sc[nt][3];
            }
        }

        // ---- O += P̂ V̂ ----
#pragma unroll
        for (int kt = 0; kt < 4; kt++) {
            unsigned Ph[4];
#pragma unroll
            for (int half = 0; half < 2; half++) {
                int nt = 2 * kt + half;
                __half2 h0 = __floats2half2_rn(sc[nt][0], sc[nt][1]);
                __half2 h1 = __floats2half2_rn(sc[nt][2], sc[nt][3]);
                Ph[half * 2]     = *(unsigned*)&h0;
                Ph[half * 2 + 1] = *(unsigned*)&h1;
            }
            unsigned Vf[8][2];
#pragma unroll
            for (int dg = 0; dg < 4; dg++) {
                unsigned r0, r1, r2, r3;
                unsigned a = (unsigned)__cvta_generic_to_shared(
                    &Vh_[(kt * 16 + vrow) * KPAD + dg * 16 + vcol]);
                ldmx4t(r0, r1, r2, r3, a);
                Vf[dg * 2][0] = r0; Vf[dg * 2][1] = r1;
                Vf[dg * 2 + 1][0] = r2; Vf[dg * 2 + 1][1] = r3;
            }
#pragma unroll
            for (int dnt = 0; dnt < 8; dnt++)
                mma16816h(acc_o[dnt], Ph, Vf[dnt]);
        }
        __syncthreads();
    }

    // ---- epilogue ----
    lsum0 += __shfl_xor_sync(0xffffffffu, lsum0, 1);
    lsum0 += __shfl_xor_sync(0xffffffffu, lsum0, 2);
    lsum1 += __shfl_xor_sync(0xffffffffu, lsum1, 1);
    lsum1 += __shfl_xor_sync(0xffffffffu, lsum1, 2);
    float inv0 = 1.f / lsum0, inv1 = 1.f / lsum1;
    size_t o0 = ((size_t)b * Sv + row0g) * DM + h * Dv;
    size_t o1 = o0 + (size_t)8 * DM;
#pragma unroll
    for (int dnt = 0; dnt < 8; dnt++) {
        int col = dnt * 8 + 2 * tig;
        *(__half2*)&yh[o0 + col] =
            __floats2half2_rn(acc_o[dnt][0] * inv0, acc_o[dnt][1] * inv0);
        *(__half2*)&yh[o1 + col] =
            __floats2half2_rn(acc_o[dnt][2] * inv1, acc_o[dnt][3] * inv1);
    }
}

// ---------------------------------------------------------------------------
// kernel_launch
// ---------------------------------------------------------------------------
extern "C" void kernel_launch(void* const* d_in, const int* in_sizes, int n_in,
                              void* d_out, int out_size)
{
    const float* x  = (const float*)d_in[0];
    const float* Wq = (const float*)d_in[1];
    const float* bq = (const float*)d_in[2];
    const float* Wk = (const float*)d_in[3];
    const float* bk = (const float*)d_in[4];
    const float* Wv = (const float*)d_in[5];
    const float* bv = (const float*)d_in[6];
    const float* Wo = (const float*)d_in[7];
    const float* bo = (const float*)d_in[8];
    float* out = (float*)d_out;

    __half *xh, *yh, *whi, *wlo, *qh, *kh, *vh;
    cudaGetSymbolAddress((void**)&xh,  g_xh);
    cudaGetSymbolAddress((void**)&yh,  g_yh);
    cudaGetSymbolAddress((void**)&whi, g_whi);
    cudaGetSymbolAddress((void**)&wlo, g_wlo);
    cudaGetSymbolAddress((void**)&qh,  g_qh);
    cudaGetSymbolAddress((void**)&kh,  g_kh);
    cudaGetSymbolAddress((void**)&vh,  g_vh);

    cudaFuncSetAttribute(gemm_qkv,
                         cudaFuncAttributeMaxDynamicSharedMemorySize,
                         (int)QKV_SMEM);
    cudaFuncSetAttribute(flash_mma,
                         cudaFuncAttributeMaxDynamicSharedMemorySize,
                         (int)FLASH_SMEM);

    const int NX = Mv * DM;
    const int NW = DM * DM;
    const float QSCL = 0.125f * 1.4426950408889634f;   // exp2 softmax

    // 1: rope tables
    rope_table_kernel<<<(Sv * 32 + 255) / 256, 256>>>();
    // 2: weight splits (lo used only by Wq, Wk)
    split4_half_kernel<<<(4 * NW + 255) / 256, 256>>>(Wq, Wk, Wv, Wo, whi, wlo, NW);
    // 3: x -> fp16
    tohalf_kernel<<<(NX + 255) / 256, 256>>>(x, xh, NX);

    // 4: fused QKV projection + rope + fp16 quantization
    dim3 qkv_grid(24, Mv / 128);
    gemm_qkv<<<qkv_grid, 256, QKV_SMEM>>>(xh, whi, wlo, bq, bk, bv,
                                          qh, kh, vh, QSCL);

    // 5: attention (Q tile 128)
    dim3 att_grid(Sv / 128, Hv, Bv);
    flash_mma<<<att_grid, 256, FLASH_SMEM>>>(qh, kh, vh, yh);

    // 6: out = y@Wo + bo -> fp32
    dim3 og(DM / 64, Mv / 128);
    gemm_o<<<og, 128>>>(yh, whi + 3 * NW, bo, out, Mv, DM, DM);
}

// round 13
// speedup vs baseline: 9.3847x; 1.1940x over previous
#include <cuda_runtime.h>
#include <cuda_bf16.h>
#include <cuda_fp16.h>
#include <stdint.h>
#include <cstdint>
#include <math.h>

#define Bv 4
#define Sv 2048
#define Hv 16
#define Dv 64
#define DM 1024
#define Mv (Bv*Sv)   // 8192

// ---------------------------------------------------------------------------
// Scratch
// ---------------------------------------------------------------------------
__device__ float g_cos[Sv*32];
__device__ float g_sin[Sv*32];

__device__ __half g_xh [Mv*DM];
__device__ __half g_yh [Mv*DM];
__device__ __half g_wh [4*DM*DM];
__device__ __half g_qh [Mv*DM];
__device__ __half g_kh [Mv*DM];
__device__ __half g_vh [Mv*DM];

// ---------------------------------------------------------------------------
// prep kernels
// ---------------------------------------------------------------------------
__global__ void tohalf_kernel(const float* __restrict__ s,
                              __half* __restrict__ o, int n)
{
    int i = blockIdx.x * blockDim.x + threadIdx.x;
    if (i >= n) return;
    o[i] = __float2half_rn(s[i]);
}

// all four weight matrices -> fp16 in one launch
__global__ void conv4_half_kernel(const float* __restrict__ s0, const float* __restrict__ s1,
                                  const float* __restrict__ s2, const float* __restrict__ s3,
                                  __half* __restrict__ o, int n)
{
    int i = blockIdx.x * blockDim.x + threadIdx.x;
    if (i >= 4 * n) return;
    int w = i / n, r = i - w * n;
    const float* src = (w == 0) ? s0 : (w == 1) ? s1 : (w == 2) ? s2 : s3;
    o[i] = __float2half_rn(src[r]);
}

__global__ void rope_table_kernel() {
    int idx = blockIdx.x * blockDim.x + threadIdx.x;
    if (idx >= Sv * 32) return;
    int pos = idx >> 5;
    int i   = idx & 31;
    double inv = pow(10000.0, -(double)i / 32.0);
    double ang = (double)pos * inv;
    g_cos[idx] = (float)cos(ang);
    g_sin[idx] = (float)sin(ang);
}

// ---------------------------------------------------------------------------
// primitives
// ---------------------------------------------------------------------------
__device__ __forceinline__ void ldmx4(unsigned& r0, unsigned& r1,
                                      unsigned& r2, unsigned& r3, unsigned a) {
    asm volatile("ldmatrix.sync.aligned.m8n8.x4.shared.b16 {%0,%1,%2,%3}, [%4];"
        : "=r"(r0), "=r"(r1), "=r"(r2), "=r"(r3) : "r"(a));
}
__device__ __forceinline__ void ldmx4t(unsigned& r0, unsigned& r1,
                                       unsigned& r2, unsigned& r3, unsigned a) {
    asm volatile("ldmatrix.sync.aligned.m8n8.x4.trans.shared.b16 {%0,%1,%2,%3}, [%4];"
        : "=r"(r0), "=r"(r1), "=r"(r2), "=r"(r3) : "r"(a));
}
__device__ __forceinline__ void mma16816h(float* c, const unsigned* a, const unsigned* b) {
    asm volatile(
        "mma.sync.aligned.m16n8k16.row.col.f32.f16.f16.f32 "
        "{%0,%1,%2,%3}, {%4,%5,%6,%7}, {%8,%9}, {%0,%1,%2,%3};"
        : "+f"(c[0]), "+f"(c[1]), "+f"(c[2]), "+f"(c[3])
        : "r"(a[0]), "r"(a[1]), "r"(a[2]), "r"(a[3]), "r"(b[0]), "r"(b[1]));
}
__device__ __forceinline__ void cpa16(void* smem, const void* g) {
    unsigned s = (unsigned)__cvta_generic_to_shared(smem);
    asm volatile("cp.async.cg.shared.global [%0], [%1], 16;" :: "r"(s), "l"(g));
}
__device__ __forceinline__ void cp_commit() { asm volatile("cp.async.commit_group;"); }
template<int N> __device__ __forceinline__ void cp_wait() {
    asm volatile("cp.async.wait_group %0;" :: "n"(N));
}
__device__ __forceinline__ float ex2f(float x) {
    float y;
    asm("ex2.approx.ftz.f32 %0, %1;" : "=f"(y) : "f"(x));
    return y;
}

#define APAD 40

// ---------------------------------------------------------------------------
// Fused QKV GEMM: 256 threads, BM=128 BN=128 BK=32, 1-term fp16 weights,
// 3-stage cp.async, ONE sync per k-tile.
// grid.x = 24: [0,8)=Q [8,16)=K [16,24)=V.
// Q/K epilogue: rope (+qscl for Q) -> fp16. V epilogue: fp16.
// smem halves: As 3x128x40 = 15360, Bs 3x32x136 = 13056 -> 56832 B dynamic.
// ---------------------------------------------------------------------------
#define BPAD2 136
#define AS_OFF(s, r, c)  ((s) * 5120 + (r) * APAD + (c))
#define BS_OFF(s, r, c)  (15360 + (s) * 4352 + (r) * BPAD2 + (c))
#define QKV_SMEM ((15360 + 3 * 4352) * sizeof(__half))   // 56832 B

__global__ __launch_bounds__(256) void gemm_qkv(
    const __half* __restrict__ xh, const __half* __restrict__ wh,
    const float* __restrict__ bq, const float* __restrict__ bk,
    const float* __restrict__ bv,
    __half* __restrict__ qout, __half* __restrict__ kout,
    __half* __restrict__ vout, float qscl)
{
    extern __shared__ __half sm[];

    int tid = threadIdx.x, lane = tid & 31, warp = tid >> 5;
    int wm = warp >> 2, wn = warp & 3;
    int bx = blockIdx.x;
    int w = bx >> 3;
    int bn = (bx & 7) << 7;
    int bm = blockIdx.y << 7;
    const __half* Bw = wh + (size_t)w * DM * DM;
    const float* bias = (w == 0) ? bq : (w == 1) ? bk : bv;
    __half* Cout = (w == 0) ? qout : (w == 1) ? kout : vout;

    float acc[4][4][4];
#pragma unroll
    for (int i = 0; i < 4; i++)
#pragma unroll
        for (int j = 0; j < 4; j++)
#pragma unroll
            for (int e = 0; e < 4; e++) acc[i][j][e] = 0.f;

    int u0k = tid >> 4, u0n = (tid & 15) << 3;
    int u1k = u0k + 16;
    int arow = tid >> 1;
    int ac0 = (tid & 1) << 4;
    const __half* Ap0 = xh + (size_t)(bm + arow) * DM;

    // prologue: k-tiles 0,1 into stages 0,1
#pragma unroll
    for (int pk = 0; pk < 2; pk++) {
        int k0 = pk << 5;
        cpa16(&sm[AS_OFF(pk, arow, ac0)],     Ap0 + k0 + ac0);
        cpa16(&sm[AS_OFF(pk, arow, ac0 + 8)], Ap0 + k0 + ac0 + 8);
        cpa16(&sm[BS_OFF(pk, u0k, u0n)], Bw + (size_t)(k0 + u0k) * DM + bn + u0n);
        cpa16(&sm[BS_OFF(pk, u1k, u0n)], Bw + (size_t)(k0 + u1k) * DM + bn + u0n);
        cp_commit();
    }

    const int NKT = DM >> 5;   // 32
    for (int kt = 0; kt < NKT; kt++) {
        int s = kt % 3;
        // stage s ready (its group is the oldest of ≤2 outstanding)
        if (kt + 1 < NKT) { cp_wait<1>(); } else { cp_wait<0>(); }
        __syncthreads();
        // fill stage (kt+2)%3 — its consumers ran at iter kt-1, before this barrier
        if (kt + 2 < NKT) {
            int k0 = (kt + 2) << 5;
            int sn = (kt + 2) % 3;
            cpa16(&sm[AS_OFF(sn, arow, ac0)],     Ap0 + k0 + ac0);
            cpa16(&sm[AS_OFF(sn, arow, ac0 + 8)], Ap0 + k0 + ac0 + 8);
            cpa16(&sm[BS_OFF(sn, u0k, u0n)], Bw + (size_t)(k0 + u0k) * DM + bn + u0n);
            cpa16(&sm[BS_OFF(sn, u1k, u0n)], Bw + (size_t)(k0 + u1k) * DM + bn + u0n);
            cp_commit();
        }

#pragma unroll
        for (int ks = 0; ks < 2; ks++) {
            int k16 = ks << 4;
            unsigned Af[4][4];
            int ar = (lane & 15);
            int ac = k16 + ((lane >> 4) << 3);
#pragma unroll
            for (int mt = 0; mt < 4; mt++) {
                int m0 = wm * 64 + mt * 16;
                unsigned a0 = (unsigned)__cvta_generic_to_shared(
                    &sm[AS_OFF(s, m0 + ar, ac)]);
                ldmx4(Af[mt][0], Af[mt][1], Af[mt][2], Af[mt][3], a0);
            }
            unsigned Bf[4][2];
            int bkr = k16 + (lane & 7) + (lane & 8);
#pragma unroll
            for (int p = 0; p < 2; p++) {
                int n0 = wn * 32 + p * 16 + (((lane >> 4) & 1) << 3);
                unsigned r0, r1, r2, r3;
                unsigned ad = (unsigned)__cvta_generic_to_shared(
                    &sm[BS_OFF(s, bkr, n0)]);
                ldmx4t(r0, r1, r2, r3, ad);
                Bf[p * 2][0] = r0; Bf[p * 2][1] = r1;
                Bf[p * 2 + 1][0] = r2; Bf[p * 2 + 1][1] = r3;
            }
#pragma unroll
            for (int mt = 0; mt < 4; mt++)
#pragma unroll
                for (int nt = 0; nt < 4; nt++)
                    mma16816h(acc[mt][nt], Af[mt], Bf[nt]);
        }
    }

    // ---- epilogue ----
    int gid = lane >> 2, tq = lane & 3;
    float scl = (w == 0) ? qscl : 1.0f;
#pragma unroll
    for (int mt = 0; mt < 4; mt++) {
        int row = bm + wm * 64 + mt * 16 + gid;
#pragma unroll
        for (int nt = 0; nt < 4; nt++) {
            int col = bn + wn * 32 + nt * 8 + tq * 2;
            float b0 = bias[col], b1 = bias[col + 1];
            float v0 = acc[mt][nt][0] + b0;
            float v1 = acc[mt][nt][1] + b1;
            float v2 = acc[mt][nt][2] + b0;
            float v3 = acc[mt][nt][3] + b1;
            if (w == 2) {
                *(__half2*)&Cout[(size_t)row * DM + col] = __floats2half2_rn(v0, v1);
                *(__half2*)&Cout[(size_t)(row + 8) * DM + col] = __floats2half2_rn(v2, v3);
            } else {
                int i = (col >> 1) & 31;
                int s1 = row & (Sv - 1);
                float c1 = g_cos[(s1 << 5) + i],       sn1 = g_sin[(s1 << 5) + i];
                float c2 = g_cos[((s1 + 8) << 5) + i], sn2 = g_sin[((s1 + 8) << 5) + i];
                float r0 = (v0 * c1 - v1 * sn1) * scl;
                float r1 = (v1 * c1 + v0 * sn1) * scl;
                float r2 = (v2 * c2 - v3 * sn2) * scl;
                float r3 = (v3 * c2 + v2 * sn2) * scl;
                *(__half2*)&Cout[(size_t)row * DM + col] = __floats2half2_rn(r0, r1);
                *(__half2*)&Cout[(size_t)(row + 8) * DM + col] = __floats2half2_rn(r2, r3);
            }
        }
    }
}

// ---------------------------------------------------------------------------
// O-projection GEMM: 128 threads, BM=128 BN=64, 1-term, 3-stage, 1 sync/kt.
// ---------------------------------------------------------------------------
#define BPAD 72

__global__ __launch_bounds__(128) void gemm_o(
    const __half* __restrict__ Ah, const __half* __restrict__ Bw,
    const float* __restrict__ bias, float* __restrict__ Cf,
    int M, int N, int K)
{
    __shared__ __half As[3][128][APAD];
    __shared__ __half Bs[3][32][BPAD];

    int tid  = threadIdx.x;
    int lane = tid & 31;
    int warp = tid >> 5;
    int wm = warp >> 1, wn = warp & 1;
    int bm = blockIdx.y << 7;
    int bn = blockIdx.x << 6;

    float acc[4][4][4];
#pragma unroll
    for (int i = 0; i < 4; i++)
#pragma unroll
        for (int j = 0; j < 4; j++)
#pragma unroll
            for (int e = 0; e < 4; e++) acc[i][j][e] = 0.f;

    int u0k = tid >> 3, u0n = (tid & 7) << 3;
    int u1k = u0k + 16;
    const __half* Ap0 = Ah + (size_t)(bm + tid) * K;

#pragma unroll
    for (int pk = 0; pk < 2; pk++) {
        int k0 = pk << 5;
#pragma unroll
        for (int i = 0; i < 4; i++)
            cpa16(&As[pk][tid][i * 8], Ap0 + k0 + i * 8);
        cpa16(&Bs[pk][u0k][u0n], Bw + (size_t)(k0 + u0k) * N + bn + u0n);
        cpa16(&Bs[pk][u1k][u0n], Bw + (size_t)(k0 + u1k) * N + bn + u0n);
        cp_commit();
    }

    int NKT = K >> 5;
    for (int kt = 0; kt < NKT; kt++) {
        int s = kt % 3;
        if (kt + 1 < NKT) { cp_wait<1>(); } else { cp_wait<0>(); }
        __syncthreads();
        if (kt + 2 < NKT) {
            int k0 = (kt + 2) << 5;
            int sn = (kt + 2) % 3;
#pragma unroll
            for (int i = 0; i < 4; i++)
                cpa16(&As[sn][tid][i * 8], Ap0 + k0 + i * 8);
            cpa16(&Bs[sn][u0k][u0n], Bw + (size_t)(k0 + u0k) * N + bn + u0n);
            cpa16(&Bs[sn][u1k][u0n], Bw + (size_t)(k0 + u1k) * N + bn + u0n);
            cp_commit();
        }

#pragma unroll
        for (int ks = 0; ks < 2; ks++) {
            int k16 = ks << 4;
            unsigned Af[4][4];
            int ar = (lane & 15);
            int ac = k16 + ((lane >> 4) << 3);
#pragma unroll
            for (int mt = 0; mt < 4; mt++) {
                int m0 = wm * 64 + mt * 16;
                unsigned a0 = (unsigned)__cvta_generic_to_shared(&As[s][m0 + ar][ac]);
                ldmx4(Af[mt][0], Af[mt][1], Af[mt][2], Af[mt][3], a0);
            }
            unsigned Bf[4][2];
            int bkr = k16 + (lane & 7) + (lane & 8);
#pragma unroll
            for (int p = 0; p < 2; p++) {
                int n0 = wn * 32 + p * 16 + (((lane >> 4) & 1) << 3);
                unsigned r0, r1, r2, r3;
                unsigned ad = (unsigned)__cvta_generic_to_shared(&Bs[s][bkr][n0]);
                ldmx4t(r0, r1, r2, r3, ad);
                Bf[p * 2][0] = r0; Bf[p * 2][1] = r1;
                Bf[p * 2 + 1][0] = r2; Bf[p * 2 + 1][1] = r3;
            }
#pragma unroll
            for (int mt = 0; mt < 4; mt++)
#pragma unroll
                for (int nt = 0; nt < 4; nt++)
                    mma16816h(acc[mt][nt], Af[mt], Bf[nt]);
        }
    }

    int gid = lane >> 2, tq = lane & 3;
#pragma unroll
    for (int mt = 0; mt < 4; mt++) {
        int row = bm + wm * 64 + mt * 16 + gid;
#pragma unroll
        for (int nt = 0; nt < 4; nt++) {
            int col = bn + wn * 32 + nt * 8 + tq * 2;
            float b0 = bias[col], b1 = bias[col + 1];
            *(float2*)&Cf[(size_t)row * N + col] =
                make_float2(acc[mt][nt][0] + b0, acc[mt][nt][1] + b1);
            *(float2*)&Cf[(size_t)(row + 8) * N + col] =
                make_float2(acc[mt][nt][2] + b0, acc[mt][nt][3] + b1);
        }
    }
}

// ---------------------------------------------------------------------------
// Flash attention: 256 threads, Q tile 128, KV tile 64, all fp16 single-term,
// cp.async double-buffered, no-rescale exp2 softmax. (unchanged from R12)
// ---------------------------------------------------------------------------
#define KPAD 72
#define BUF_ELEMS (64*KPAD)
#define STG_ELEMS (2*BUF_ELEMS)
#define FLASH_SMEM (2*STG_ELEMS*sizeof(__half))  // 36864

__global__ __launch_bounds__(256) void flash_mma(
    const __half* __restrict__ qh, const __half* __restrict__ kh,
    const __half* __restrict__ vh,
    __half* __restrict__ yh)
{
    extern __shared__ __half smx[];

    int tid = threadIdx.x, lane = tid & 31, warp = tid >> 5;
    int qt = (int)gridDim.x - 1 - (int)blockIdx.x;
    int h = blockIdx.y, b = blockIdx.z;
    int qg0 = qt * 128;
    size_t base = ((size_t)b * Sv) * DM + h * Dv;
    int gid = lane >> 2, tig = lane & 3;

    const __half* srcs[2] = {kh, vh};

#pragma unroll
    for (int p = 0; p < 4; p++) {
        int idx = p * 256 + tid;
        int row = idx >> 3, c = idx & 7;
        cpa16(&smx[STG_ELEMS + row * KPAD + c * 8],
              qh + base + (size_t)(qg0 + row) * DM + c * 8);
    }
    cp_commit();
#pragma unroll
    for (int p = 0; p < 4; p++) {
        int buf = p >> 1;
        int idx = ((p & 1) << 8) + tid;
        int row = idx >> 3, c = idx & 7;
        cpa16(&smx[buf * BUF_ELEMS + row * KPAD + c * 8],
              srcs[buf] + base + (size_t)row * DM + c * 8);
    }
    cp_commit();

    cp_wait<1>();
    __syncthreads();

    unsigned Qf[4][4];
    {
        int r = warp * 16 + (lane & 15);
        int c = (lane >> 4) << 3;
#pragma unroll
        for (int kt = 0; kt < 4; kt++) {
            unsigned a = (unsigned)__cvta_generic_to_shared(
                &smx[STG_ELEMS + r * KPAD + kt * 16 + c]);
            ldmx4(Qf[kt][0], Qf[kt][1], Qf[kt][2], Qf[kt][3], a);
        }
    }
    __syncthreads();

    int krow = (lane & 7) + ((lane >> 4) << 3);
    int kcol = ((lane >> 3) & 1) << 3;
    int vrow = (lane & 7) + (((lane >> 3) & 1) << 3);
    int vcol = (lane >> 4) << 3;

    float acc_o[8][4];
#pragma unroll
    for (int i = 0; i < 8; i++)
#pragma unroll
        for (int e = 0; e < 4; e++) acc_o[i][e] = 0.f;
    float lsum0 = 0.f, lsum1 = 0.f;
    int row0g = qg0 + warp * 16 + gid;

    int n = 2 * qt + 2;
    for (int j = 0; j < n; j++) {
        int s = j & 1;
        if (j + 1 < n) {
            int sb = (1 - s) * STG_ELEMS;
            size_t grow = base + (size_t)(j + 1) * 64 * DM;
#pragma unroll
            for (int p = 0; p < 4; p++) {
                int buf = p >> 1;
                int idx = ((p & 1) << 8) + tid;
                int row = idx >> 3, c = idx & 7;
                cpa16(&smx[sb + buf * BUF_ELEMS + row * KPAD + c * 8],
                      srcs[buf] + grow + (size_t)row * DM + c * 8);
            }
            cp_commit();
            cp_wait<1>();
        } else {
            cp_wait<0>();
        }
        __syncthreads();

        __half* Kh_ = smx + s * STG_ELEMS;
        __half* Vh_ = Kh_ + BUF_ELEMS;

        float sc[8][4];
#pragma unroll
        for (int i = 0; i < 8; i++)
#pragma unroll
            for (int e = 0; e < 4; e++) sc[i][e] = 0.f;

#pragma unroll
        for (int kt = 0; kt < 4; kt++) {
            unsigned Kf[8][2];
#pragma unroll
            for (int ng = 0; ng < 4; ng++) {
                unsigned r0, r1, r2, r3;
                unsigned a = (unsigned)__cvta_generic_to_shared(
                    &Kh_[(ng * 16 + krow) * KPAD + kt * 16 + kcol]);
                ldmx4(r0, r1, r2, r3, a);
                Kf[ng * 2][0] = r0; Kf[ng * 2][1] = r1;
                Kf[ng * 2 + 1][0] = r2; Kf[ng * 2 + 1][1] = r3;
            }
#pragma unroll
            for (int nt = 0; nt < 8; nt++)
                mma16816h(sc[nt], Qf[kt], Kf[nt]);
        }

        if (j >= 2 * qt) {
#pragma unroll
            for (int nt = 0; nt < 8; nt++) {
#pragma unroll
                for (int e = 0; e < 4; e++) {
                    int col = j * 64 + nt * 8 + 2 * tig + (e & 1);
                    int row = row0g + ((e >> 1) << 3);
                    sc[nt][e] = (col > row) ? 0.f : ex2f(sc[nt][e]);
                }
                lsum0 += sc[nt][0] + sc[nt][1];
                lsum1 += sc[nt][2] + sc[nt][3];
            }
        } else {
#pragma unroll
            for (int nt = 0; nt < 8; nt++) {
                sc[nt][0] = ex2f(sc[nt][0]);
                sc[nt][1] = ex2f(sc[nt][1]);
                sc[nt][2] = ex2f(sc[nt][2]);
                sc[nt][3] = ex2f(sc[nt][3]);
                lsum0 += sc[nt][0] + sc[nt][1];
                lsum1 += sc[nt][2] + sc[nt][3];
            }
        }

#pragma unroll
        for (int kt = 0; kt < 4; kt++) {
            unsigned Ph[4];
#pragma unroll
            for (int half = 0; half < 2; half++) {
                int nt = 2 * kt + half;
                __half2 h0 = __floats2half2_rn(sc[nt][0], sc[nt][1]);
                __half2 h1 = __floats2half2_rn(sc[nt][2], sc[nt][3]);
                Ph[half * 2]     = *(unsigned*)&h0;
                Ph[half * 2 + 1] = *(unsigned*)&h1;
            }
            unsigned Vf[8][2];
#pragma unroll
            for (int dg = 0; dg < 4; dg++) {
                unsigned r0, r1, r2, r3;
                unsigned a = (unsigned)__cvta_generic_to_shared(
                    &Vh_[(kt * 16 + vrow) * KPAD + dg * 16 + vcol]);
                ldmx4t(r0, r1, r2, r3, a);
                Vf[dg * 2][0] = r0; Vf[dg * 2][1] = r1;
                Vf[dg * 2 + 1][0] = r2; Vf[dg * 2 + 1][1] = r3;
            }
#pragma unroll
            for (int dnt = 0; dnt < 8; dnt++)
                mma16816h(acc_o[dnt], Ph, Vf[dnt]);
        }
        __syncthreads();
    }

    lsum0 += __shfl_xor_sync(0xffffffffu, lsum0, 1);
    lsum0 += __shfl_xor_sync(0xffffffffu, lsum0, 2);
    lsum1 += __shfl_xor_sync(0xffffffffu, lsum1, 1);
    lsum1 += __shfl_xor_sync(0xffffffffu, lsum1, 2);
    float inv0 = 1.f / lsum0, inv1 = 1.f / lsum1;
    size_t o0 = ((size_t)b * Sv + row0g) * DM + h * Dv;
    size_t o1 = o0 + (size_t)8 * DM;
#pragma unroll
    for (int dnt = 0; dnt < 8; dnt++) {
        int col = dnt * 8 + 2 * tig;
        *(__half2*)&yh[o0 + col] =
            __floats2half2_rn(acc_o[dnt][0] * inv0, acc_o[dnt][1] * inv0);
        *(__half2*)&yh[o1 + col] =
            __floats2half2_rn(acc_o[dnt][2] * inv1, acc_o[dnt][3] * inv1);
    }
}

// ---------------------------------------------------------------------------
// kernel_launch
// ---------------------------------------------------------------------------
extern "C" void kernel_launch(void* const* d_in, const int* in_sizes, int n_in,
                              void* d_out, int out_size)
{
    const float* x  = (const float*)d_in[0];
    const float* Wq = (const float*)d_in[1];
    const float* bq = (const float*)d_in[2];
    const float* Wk = (const float*)d_in[3];
    const float* bk = (const float*)d_in[4];
    const float* Wv = (const float*)d_in[5];
    const float* bv = (const float*)d_in[6];
    const float* Wo = (const float*)d_in[7];
    const float* bo = (const float*)d_in[8];
    float* out = (float*)d_out;

    __half *xh, *yh, *wh, *qh, *kh, *vh;
    cudaGetSymbolAddress((void**)&xh, g_xh);
    cudaGetSymbolAddress((void**)&yh, g_yh);
    cudaGetSymbolAddress((void**)&wh, g_wh);
    cudaGetSymbolAddress((void**)&qh, g_qh);
    cudaGetSymbolAddress((void**)&kh, g_kh);
    cudaGetSymbolAddress((void**)&vh, g_vh);

    cudaFuncSetAttribute(gemm_qkv,
                         cudaFuncAttributeMaxDynamicSharedMemorySize,
                         (int)QKV_SMEM);
    cudaFuncSetAttribute(flash_mma,
                         cudaFuncAttributeMaxDynamicSharedMemorySize,
                         (int)FLASH_SMEM);

    const int NX = Mv * DM;
    const int NW = DM * DM;
    const float QSCL = 0.125f * 1.4426950408889634f;   // exp2 softmax

    rope_table_kernel<<<(Sv * 32 + 255) / 256, 256>>>();
    conv4_half_kernel<<<(4 * NW + 255) / 256, 256>>>(Wq, Wk, Wv, Wo, wh, NW);
    tohalf_kernel<<<(NX + 255) / 256, 256>>>(x, xh, NX);

    // fused QKV projection + rope + fp16 quantization (all 1-term)
    dim3 qkv_grid(24, Mv / 128);
    gemm_qkv<<<qkv_grid, 256, QKV_SMEM>>>(xh, wh, bq, bk, bv, qh, kh, vh, QSCL);

    // attention
    dim3 att_grid(Sv / 128, Hv, Bv);
    flash_mma<<<att_grid, 256, FLASH_SMEM>>>(qh, kh, vh, yh);

    // out = y@Wo + bo -> fp32
    dim3 og(DM / 64, Mv / 128);
    gemm_o<<<og, 128>>>(yh, wh + 3 * (size_t)NW, bo, out, Mv, DM, DM);
}